// round 11
// baseline (speedup 1.0000x reference)
#include <cuda_runtime.h>
#include <cuda_fp16.h>
#include <cstdint>

// ---------------------------------------------------------------------------
// Problem constants
// ---------------------------------------------------------------------------
#define B_    64
#define NQ_   1024
#define DM_   1024
#define H_    16
#define D_    64
#define LT_   77
#define LI_   256
#define NR_   33
#define CTXR  (LT_ + LI_)     // 333

__device__ __forceinline__ uint32_t smem_to_u32(const void* p) {
    uint32_t a;
    asm("{ .reg .u64 t; cvta.to.shared.u64 t, %1; cvt.u32.u64 %0, t; }"
        : "=r"(a) : "l"(p));
    return a;
}

#define CPA16(dst, src) \
    asm volatile("cp.async.cg.shared.global [%0], [%1], 16;" \
                 :: "r"(dst), "l"(src))
#define CPA_COMMIT() asm volatile("cp.async.commit_group;" ::: "memory")
#define CPA_WAIT(n)  asm volatile("cp.async.wait_group %0;" :: "n"(n) : "memory")

#define LDMX4(r0, r1, r2, r3, addr) \
    asm volatile("ldmatrix.sync.aligned.m8n8.x4.shared.b16 {%0,%1,%2,%3}, [%4];" \
                 : "=r"(r0), "=r"(r1), "=r"(r2), "=r"(r3) : "r"(addr))
#define LDMX4T(r0, r1, r2, r3, addr) \
    asm volatile("ldmatrix.sync.aligned.m8n8.x4.trans.shared.b16 {%0,%1,%2,%3}, [%4];" \
                 : "=r"(r0), "=r"(r1), "=r"(r2), "=r"(r3) : "r"(addr))

#define MMA16816(c, a, b0, b1) \
    asm volatile("mma.sync.aligned.m16n8k16.row.col.f32.f16.f16.f32 " \
                 "{%0,%1,%2,%3}, {%4,%5,%6,%7}, {%8,%9}, {%0,%1,%2,%3};" \
                 : "+f"((c)[0]), "+f"((c)[1]), "+f"((c)[2]), "+f"((c)[3]) \
                 : "r"((a)[0]), "r"((a)[1]), "r"((a)[2]), "r"((a)[3]), \
                   "r"(b0), "r"(b1))

__device__ __forceinline__ uint32_t packh(float lo, float hi) {
    uint32_t d;
    asm("cvt.rn.f16x2.f32 %0, %1, %2;" : "=r"(d) : "f"(hi), "f"(lo));
    return d;
}

// ---------------------------------------------------------------------------
// Scratch (static device globals)
// ---------------------------------------------------------------------------
__device__ __half g_ahi[(size_t)B_ * NQ_ * DM_];  // x hi, later att hi
__device__ __half g_alo[(size_t)B_ * NQ_ * DM_];
__device__ __half g_qhi[(size_t)B_ * NQ_ * DM_];
__device__ __half g_qlo[(size_t)B_ * NQ_ * DM_];
__device__ __half g_chi[(size_t)B_ * CTXR * DM_];
__device__ __half g_clo[(size_t)B_ * CTXR * DM_];
__device__ __half g_whi[6 * (size_t)DM_ * DM_];
__device__ __half g_wlo[6 * (size_t)DM_ * DM_];
__device__ __half g_kt[(size_t)B_ * H_ * LT_ * D_];   // hi only
__device__ __half g_vt[(size_t)B_ * H_ * LT_ * D_];
__device__ __half g_ki[(size_t)B_ * H_ * LI_ * D_];
__device__ __half g_vi[(size_t)B_ * H_ * LI_ * D_];

// ---------------------------------------------------------------------------
// fp32 -> fp16 hi/lo split
// ---------------------------------------------------------------------------
__global__ void conv_rows(const float* __restrict__ src,
                          __half* __restrict__ hi,
                          __half* __restrict__ lo, size_t n)
{
    size_t i = ((size_t)blockIdx.x * blockDim.x + threadIdx.x) * 4;
    if (i >= n) return;
    float4 v = *(const float4*)(src + i);
    float h0 = __half2float(__float2half(v.x));
    float h1 = __half2float(__float2half(v.y));
    float h2 = __half2float(__float2half(v.z));
    float h3 = __half2float(__float2half(v.w));
    *(uint2*)(hi + i) = make_uint2(packh(h0, h1), packh(h2, h3));
    *(uint2*)(lo + i) = make_uint2(packh(v.x - h0, v.y - h1),
                                   packh(v.z - h2, v.w - h3));
}

// W [K=1024, N=1024] -> Wt hi/lo [N, K]
__global__ void conv_wt(const float* __restrict__ W,
                        __half* __restrict__ hi,
                        __half* __restrict__ lo)
{
    __shared__ float tile[32][33];
    const int k0 = blockIdx.y * 32, n0 = blockIdx.x * 32;
    const int tx = threadIdx.x;
    for (int r = threadIdx.y; r < 32; r += 8)
        tile[r][tx] = W[(size_t)(k0 + r) * DM_ + n0 + tx];
    __syncthreads();
    for (int r = threadIdx.y; r < 32; r += 8) {
        float v = tile[tx][r];
        float h = __half2float(__float2half(v));
        size_t oi = (size_t)(n0 + r) * DM_ + k0 + tx;
        hi[oi] = __float2half(h);
        lo[oi] = __float2half(v - h);
    }
}

// ---------------------------------------------------------------------------
// fp16 2-term GEMM via mma.sync: C = remap(A) @ B^T, AhiBhi + AloBhi.
// MODE 0: fp32 C + bias.  MODE 1: KV scatter fp16 hi only.  MODE 2: Q *0.125
// hi/lo.  CTA 128x128, BK=32, 3-stage cp.async pipeline, 2 CTAs/SM.
// ---------------------------------------------------------------------------
#define BUF_BYTES   30720
#define GM_SMEM     (3 * BUF_BYTES)   // 92160

template <int MODE>
__global__ void __launch_bounds__(256, 2)
gemm_mma(const __half* __restrict__ Ahi, const __half* __restrict__ Alo,
         const __half* __restrict__ Bhi,
         float* __restrict__ C, const float* __restrict__ bias,
         __half* __restrict__ Chi, __half* __restrict__ Clo,
         int M, int rows_per_seg, int seg_stride, int seg_base)
{
    extern __shared__ __align__(128) char smem[];
    const uint32_t sb = smem_to_u32(smem);
    const int tid = threadIdx.x;
    const int bn = blockIdx.x * 128;
    const int bm = blockIdx.y * 128;
    const int wid = tid >> 5, lane = tid & 31;
    const int Wm = (wid & 3) * 32;
    const int Wn = (wid >> 2) * 64;

    const int lrow = tid >> 1;
    const int lc = tid & 1;
    int m = bm + lrow; if (m > M - 1) m = M - 1;
    const int seg = m / rows_per_seg;
    const int t = m - seg * rows_per_seg;
    const size_t aoff = (size_t)(seg * seg_stride + seg_base + t) * 1024 + lc * 16;
    const size_t boff = (size_t)(bn + lrow) * 1024 + lc * 16;
    const uint32_t soff = (uint32_t)lrow * 80u + (uint32_t)lc * 32u;

    float acc[2][8][4];
#pragma unroll
    for (int i = 0; i < 2; i++)
#pragma unroll
        for (int j = 0; j < 8; j++)
#pragma unroll
            for (int c = 0; c < 4; c++) acc[i][j][c] = 0.f;

    const uint32_t a_frag_row = (uint32_t)(Wm + (lane & 15)) * 80u + ((lane >> 4) * 16u);
    const uint32_t b_frag_row =
        (uint32_t)(Wn + (lane & 7) + ((lane >> 4) << 3)) * 80u + (((lane >> 3) & 1) * 16u);

#define ISSUE(p, k0)                                                       \
    {                                                                      \
        uint32_t d = sb + (p) * BUF_BYTES + soff;                          \
        const __half* s;                                                   \
        s = Ahi + aoff + (k0); CPA16(d,           s); CPA16(d + 16,         s + 8); \
        s = Alo + aoff + (k0); CPA16(d + 10240,   s); CPA16(d + 10240 + 16, s + 8); \
        s = Bhi + boff + (k0); CPA16(d + 20480,   s); CPA16(d + 20480 + 16, s + 8); \
    }

    ISSUE(0, 0);
    CPA_COMMIT();
    ISSUE(1, 32);
    CPA_COMMIT();

    int stage = 0;
    for (int i = 0; i < 32; i++) {
        if (i < 31) { CPA_WAIT(1); } else { CPA_WAIT(0); }
        __syncthreads();
        if (i + 2 < 32) {
            int ns = stage + 2; if (ns >= 3) ns -= 3;
            ISSUE(ns, (i + 2) * 32);
            CPA_COMMIT();
        }

        const uint32_t base = sb + stage * BUF_BYTES;
#pragma unroll
        for (int kk = 0; kk < 2; kk++) {
            uint32_t ah[2][4], al[2][4], bh[4][4];
            const uint32_t ar = base + a_frag_row + kk * 32;
            LDMX4(ah[0][0], ah[0][1], ah[0][2], ah[0][3], ar);
            LDMX4(ah[1][0], ah[1][1], ah[1][2], ah[1][3], ar + 16 * 80);
            LDMX4(al[0][0], al[0][1], al[0][2], al[0][3], ar + 10240);
            LDMX4(al[1][0], al[1][1], al[1][2], al[1][3], ar + 10240 + 16 * 80);
#pragma unroll
            for (int j = 0; j < 4; j++) {
                const uint32_t br = base + 20480 + b_frag_row + kk * 32
                                    + (uint32_t)j * (16 * 80);
                LDMX4(bh[j][0], bh[j][1], bh[j][2], bh[j][3], br);
            }
#pragma unroll
            for (int j = 0; j < 4; j++)
#pragma unroll
                for (int mt = 0; mt < 2; mt++) {
                    MMA16816(acc[mt][2 * j],     ah[mt], bh[j][0], bh[j][1]);
                    MMA16816(acc[mt][2 * j + 1], ah[mt], bh[j][2], bh[j][3]);
                }
#pragma unroll
            for (int j = 0; j < 4; j++)
#pragma unroll
                for (int mt = 0; mt < 2; mt++) {
                    MMA16816(acc[mt][2 * j],     al[mt], bh[j][0], bh[j][1]);
                    MMA16816(acc[mt][2 * j + 1], al[mt], bh[j][2], bh[j][3]);
                }
        }
        stage++; if (stage >= 3) stage = 0;
    }
#undef ISSUE

    const int er = lane >> 2, ec = (lane & 3) * 2;
#pragma unroll
    for (int mt = 0; mt < 2; mt++) {
#pragma unroll
        for (int hrow = 0; hrow < 2; hrow++) {
            const int cm = bm + Wm + mt * 16 + er + hrow * 8;
            if (cm >= M) continue;
            if (MODE == 1) {
                const int segc = cm / rows_per_seg;
                const int tc = cm - segc * rows_per_seg;
#pragma unroll
                for (int nt = 0; nt < 8; nt++) {
                    const int cn = bn + Wn + nt * 8 + ec;
                    const int hh = cn >> 6, dd = cn & 63;
                    size_t oi = (((size_t)segc * H_ + hh) * rows_per_seg + tc) * 64 + dd;
                    *(uint32_t*)(Chi + oi) =
                        packh(acc[mt][nt][hrow * 2], acc[mt][nt][hrow * 2 + 1]);
                }
            } else if (MODE == 2) {
#pragma unroll
                for (int nt = 0; nt < 8; nt++) {
                    const int cn = bn + Wn + nt * 8 + ec;
                    size_t oi = (size_t)cm * DM_ + cn;
                    float v0 = acc[mt][nt][hrow * 2] * 0.125f;
                    float v1 = acc[mt][nt][hrow * 2 + 1] * 0.125f;
                    float h0 = __half2float(__float2half(v0));
                    float h1 = __half2float(__float2half(v1));
                    *(uint32_t*)(Chi + oi) = packh(h0, h1);
                    *(uint32_t*)(Clo + oi) = packh(v0 - h0, v1 - h1);
                }
            } else {
                float* Cp = C + (size_t)cm * DM_ + bn + Wn + ec;
                const float* bp = bias + bn + Wn + ec;
#pragma unroll
                for (int nt = 0; nt < 8; nt++) {
                    float2 v = make_float2(acc[mt][nt][hrow * 2] + bp[nt * 8],
                                           acc[mt][nt][hrow * 2 + 1] + bp[nt * 8 + 1]);
                    *(float2*)(Cp + nt * 8) = v;
                }
            }
        }
    }
}

// ---------------------------------------------------------------------------
// Tensor-core flash attention, 2-term (K/V hi-only in smem).
// One CTA = (b, h, 128-query tile). smem ~131 KB.
// ---------------------------------------------------------------------------
#define AT_KHI 0                 // [336][144B] K hi (text 0..76, img 80..335)
#define AT_VHI 48384             // [336][144B] V hi
#define AT_QHI 96768             // [128][144B]
#define AT_QLO 115200            // [128][144B]
#define AT_PS  96768             // fp32 [128][34] (reuses QHI after frag load)
#define AT_RKH 115200            // relk hi (reuses QLO)
#define AT_RKL 120960
#define AT_SMEM 133632

__device__ __forceinline__ int bidx(int j, int i)
{
    int d = j - i;
    d = max(-16, min(16, d));
    return d + 16;
}

__device__ __forceinline__ void wsplit(const float* s0, const float* s1,
                                       uint32_t* ahi, uint32_t* alo)
{
    float v[8] = {s0[0], s0[1], s0[2], s0[3], s1[0], s1[1], s1[2], s1[3]};
    float hv[8];
#pragma unroll
    for (int i = 0; i < 8; i++)
        hv[i] = __half2float(__float2half(v[i]));
    ahi[0] = packh(hv[0], hv[1]); ahi[1] = packh(hv[2], hv[3]);
    ahi[2] = packh(hv[4], hv[5]); ahi[3] = packh(hv[6], hv[7]);
    alo[0] = packh(v[0] - hv[0], v[1] - hv[1]);
    alo[1] = packh(v[2] - hv[2], v[3] - hv[3]);
    alo[2] = packh(v[4] - hv[4], v[5] - hv[5]);
    alo[3] = packh(v[6] - hv[6], v[7] - hv[7]);
}

__global__ void __launch_bounds__(256, 1)
attn_mma(const __half* __restrict__ qhi, const __half* __restrict__ qlo,
         const __half* __restrict__ kt, const __half* __restrict__ vt,
         const __half* __restrict__ ki, const __half* __restrict__ vi,
         const float* __restrict__ relk, const float* __restrict__ relv,
         __half* __restrict__ atthi, __half* __restrict__ attlo)
{
    extern __shared__ __align__(128) char sm[];
    const uint32_t sb = smem_to_u32(sm);
    const int tid = threadIdx.x, w = tid >> 5, lane = tid & 31;
    const int bh = blockIdx.x >> 3, qt = blockIdx.x & 7;
    const int b = bh >> 4, h = bh & 15;
    const int i0 = qt * 128;
    const unsigned FULL = 0xffffffffu;

    // ---- stage K/V (hi only) + Q (hi/lo) ----
    {
        size_t tb = (size_t)bh * (LT_ * 64);
        for (int idx = tid; idx < LT_ * 8; idx += 256) {
            int r = idx >> 3, c = idx & 7;
            uint32_t d = (uint32_t)r * 144 + c * 16;
            size_t s = tb + (size_t)r * 64 + c * 8;
            CPA16(sb + AT_KHI + d, kt + s);
            CPA16(sb + AT_VHI + d, vt + s);
        }
        size_t ib = (size_t)bh * (LI_ * 64);
        for (int idx = tid; idx < LI_ * 8; idx += 256) {
            int r = idx >> 3, c = idx & 7;
            uint32_t d = (uint32_t)(80 + r) * 144 + c * 16;
            size_t s = ib + (size_t)r * 64 + c * 8;
            CPA16(sb + AT_KHI + d, ki + s);
            CPA16(sb + AT_VHI + d, vi + s);
        }
        size_t qb = ((size_t)(b * NQ_ + i0)) * 1024 + h * 64;
        for (int idx = tid; idx < 128 * 8; idx += 256) {
            int r = idx >> 3, c = idx & 7;
            uint32_t d = (uint32_t)r * 144 + c * 16;
            size_t s = qb + (size_t)r * 1024 + c * 8;
            CPA16(sb + AT_QHI + d, qhi + s);
            CPA16(sb + AT_QLO + d, qlo + s);
        }
        for (int idx = tid; idx < 3 * 36; idx += 256) {
            uint32_t d = (uint32_t)(77 + idx / 36) * 144 + (idx % 36) * 4;
            *(uint32_t*)(sm + AT_KHI + d) = 0;
            *(uint32_t*)(sm + AT_VHI + d) = 0;
        }
        CPA_COMMIT();
        CPA_WAIT(0);
        __syncthreads();
    }

    const int wr = w * 16;
    const int r0l = wr + (lane >> 2);

    // ---- Q fragments ----
    uint32_t qh[4][4], ql[4][4];
    {
        int row = wr + (lane & 15);
        int kb = (lane >> 4) * 16;
#pragma unroll
        for (int kk = 0; kk < 4; kk++) {
            uint32_t a = sb + AT_QHI + (uint32_t)row * 144 + kk * 32 + kb;
            LDMX4(qh[kk][0], qh[kk][1], qh[kk][2], qh[kk][3], a);
            LDMX4(ql[kk][0], ql[kk][1], ql[kk][2], ql[kk][3], a + (AT_QLO - AT_QHI));
        }
    }
    __syncthreads();

    if (qt == 0) {
        for (int idx = tid; idx < NR_ * 64; idx += 256) {
            int r = idx >> 6, dc = idx & 63;
            float v = relk[idx];
            float hh = __half2float(__float2half(v));
            *(__half*)(sm + AT_RKH + r * 144 + dc * 2) = __float2half(hh);
            *(__half*)(sm + AT_RKL + r * 144 + dc * 2) = __float2half(v - hh);
        }
    }
    __syncthreads();

    float* pS = (float*)(sm + AT_PS);

    const int brow = ((lane >> 4) << 3) + (lane & 7);
    const int bdb = (lane & 8) * 2;

    // ---- rel-K projections (tile 0; 3-term kept) ----
    if (qt == 0) {
        float pr[5][4];
#pragma unroll
        for (int i = 0; i < 5; i++)
#pragma unroll
            for (int c = 0; c < 4; c++) pr[i][c] = 0.f;
#pragma unroll
        for (int kk = 0; kk < 4; kk++) {
#pragma unroll
            for (int p2 = 0; p2 < 3; p2++) {
                uint32_t bh4[4], bl4[4];
                uint32_t ad = sb + AT_RKH + (uint32_t)(p2 * 16 + brow) * 144
                              + kk * 32 + bdb;
                LDMX4(bh4[0], bh4[1], bh4[2], bh4[3], ad);
                LDMX4(bl4[0], bl4[1], bl4[2], bl4[3], ad + (AT_RKL - AT_RKH));
                MMA16816(pr[2 * p2], qh[kk], bh4[0], bh4[1]);
                MMA16816(pr[2 * p2], ql[kk], bh4[0], bh4[1]);
                MMA16816(pr[2 * p2], qh[kk], bl4[0], bl4[1]);
                if (p2 < 2) {
                    MMA16816(pr[2 * p2 + 1], qh[kk], bh4[2], bh4[3]);
                    MMA16816(pr[2 * p2 + 1], ql[kk], bh4[2], bh4[3]);
                    MMA16816(pr[2 * p2 + 1], qh[kk], bl4[2], bl4[3]);
                }
            }
        }
#pragma unroll
        for (int nt = 0; nt < 5; nt++) {
            int c0 = nt * 8 + 2 * (lane & 3);
            if (c0 < NR_) {
                pS[r0l * 34 + c0] = pr[nt][0];
                pS[(r0l + 8) * 34 + c0] = pr[nt][2];
            }
            if (c0 + 1 < NR_) {
                pS[r0l * 34 + c0 + 1] = pr[nt][1];
                pS[(r0l + 8) * 34 + c0 + 1] = pr[nt][3];
            }
        }
        __syncwarp();
    }

    // ---- text scores (2-term: Qhi@Khi + Qlo@Khi) ----
    float s[10][4];
#pragma unroll
    for (int i = 0; i < 10; i++)
#pragma unroll
        for (int c = 0; c < 4; c++) s[i][c] = 0.f;
#pragma unroll
    for (int kk = 0; kk < 4; kk++) {
#pragma unroll
        for (int p2 = 0; p2 < 5; p2++) {
            uint32_t kh4[4];
            uint32_t ad = sb + AT_KHI + (uint32_t)(p2 * 16 + brow) * 144
                          + kk * 32 + bdb;
            LDMX4(kh4[0], kh4[1], kh4[2], kh4[3], ad);
            MMA16816(s[2 * p2], qh[kk], kh4[0], kh4[1]);
            MMA16816(s[2 * p2], ql[kk], kh4[0], kh4[1]);
            MMA16816(s[2 * p2 + 1], qh[kk], kh4[2], kh4[3]);
            MMA16816(s[2 * p2 + 1], ql[kk], kh4[2], kh4[3]);
        }
    }

#pragma unroll
    for (int nt = 0; nt < 10; nt++) {
        int c0 = nt * 8 + 2 * (lane & 3);
        if (qt == 0) {
            s[nt][0] += pS[r0l * 34 + bidx(c0, r0l)];
            s[nt][1] += pS[r0l * 34 + bidx(c0 + 1, r0l)];
            s[nt][2] += pS[(r0l + 8) * 34 + bidx(c0, r0l + 8)];
            s[nt][3] += pS[(r0l + 8) * 34 + bidx(c0 + 1, r0l + 8)];
        }
        if (c0 >= LT_) { s[nt][0] = -1e30f; s[nt][2] = -1e30f; }
        if (c0 + 1 >= LT_) { s[nt][1] = -1e30f; s[nt][3] = -1e30f; }
    }

    float m0 = -1e30f, m1 = -1e30f;
#pragma unroll
    for (int nt = 0; nt < 10; nt++) {
        m0 = fmaxf(m0, fmaxf(s[nt][0], s[nt][1]));
        m1 = fmaxf(m1, fmaxf(s[nt][2], s[nt][3]));
    }
    m0 = fmaxf(m0, __shfl_xor_sync(FULL, m0, 1));
    m0 = fmaxf(m0, __shfl_xor_sync(FULL, m0, 2));
    m1 = fmaxf(m1, __shfl_xor_sync(FULL, m1, 1));
    m1 = fmaxf(m1, __shfl_xor_sync(FULL, m1, 2));
    float l0 = 0.f, l1 = 0.f;
#pragma unroll
    for (int nt = 0; nt < 10; nt++) {
        s[nt][0] = __expf(s[nt][0] - m0); l0 += s[nt][0];
        s[nt][1] = __expf(s[nt][1] - m0); l0 += s[nt][1];
        s[nt][2] = __expf(s[nt][2] - m1); l1 += s[nt][2];
        s[nt][3] = __expf(s[nt][3] - m1); l1 += s[nt][3];
    }
    l0 += __shfl_xor_sync(FULL, l0, 1); l0 += __shfl_xor_sync(FULL, l0, 2);
    l1 += __shfl_xor_sync(FULL, l1, 1); l1 += __shfl_xor_sync(FULL, l1, 2);
    float inv0 = 1.f / l0, inv1 = 1.f / l1;
#pragma unroll
    for (int nt = 0; nt < 10; nt++) {
        s[nt][0] *= inv0; s[nt][1] *= inv0;
        s[nt][2] *= inv1; s[nt][3] *= inv1;
    }

    if (qt == 0) {
        for (int idx = lane; idx < 16 * 34; idx += 32)
            pS[(wr + idx / 34) * 34 + idx % 34] = 0.f;
        __syncwarp();
#pragma unroll
        for (int nt = 0; nt < 10; nt++) {
            int c0 = nt * 8 + 2 * (lane & 3);
            if (c0 < LT_) {
                atomicAdd(&pS[r0l * 34 + bidx(c0, r0l)], s[nt][0]);
                atomicAdd(&pS[(r0l + 8) * 34 + bidx(c0, r0l + 8)], s[nt][2]);
            }
            if (c0 + 1 < LT_) {
                atomicAdd(&pS[r0l * 34 + bidx(c0 + 1, r0l)], s[nt][1]);
                atomicAdd(&pS[(r0l + 8) * 34 + bidx(c0 + 1, r0l + 8)], s[nt][3]);
            }
        }
        __syncwarp();
    }

    const int vrow = (lane & 8) + (lane & 7);
    const int vdb = (lane >> 4) * 16;

    // ---- O_text = W @ V_text (2-term: Whi@Vhi + Wlo@Vhi) ----
    float ot[8][4];
#pragma unroll
    for (int i = 0; i < 8; i++)
#pragma unroll
        for (int c = 0; c < 4; c++) ot[i][c] = 0.f;
#pragma unroll
    for (int wk = 0; wk < 5; wk++) {
        uint32_t ahi[4], alo[4];
        wsplit(s[2 * wk], s[2 * wk + 1], ahi, alo);
#pragma unroll
        for (int dp = 0; dp < 4; dp++) {
            uint32_t vh4[4];
            uint32_t ad = sb + AT_VHI + (uint32_t)(wk * 16 + vrow) * 144
                          + dp * 32 + vdb;
            LDMX4T(vh4[0], vh4[1], vh4[2], vh4[3], ad);
            MMA16816(ot[2 * dp], ahi, vh4[0], vh4[1]);
            MMA16816(ot[2 * dp], alo, vh4[0], vh4[1]);
            MMA16816(ot[2 * dp + 1], ahi, vh4[2], vh4[3]);
            MMA16816(ot[2 * dp + 1], alo, vh4[2], vh4[3]);
        }
    }

    if (qt == 0) {
#pragma unroll 1
        for (int r = 0; r < NR_; r++) {
            float w0 = pS[r0l * 34 + r];
            float w1 = pS[(r0l + 8) * 34 + r];
            const float* rv = relv + r * 64 + 2 * (lane & 3);
#pragma unroll
            for (int dt = 0; dt < 8; dt++) {
                float rv0 = rv[dt * 8], rv1 = rv[dt * 8 + 1];
                ot[dt][0] += w0 * rv0; ot[dt][1] += w0 * rv1;
                ot[dt][2] += w1 * rv0; ot[dt][3] += w1 * rv1;
            }
        }
    } else {
        const float* rv = relv + 2 * (lane & 3);
#pragma unroll
        for (int dt = 0; dt < 8; dt++) {
            float rv0 = rv[dt * 8], rv1 = rv[dt * 8 + 1];
            ot[dt][0] += rv0; ot[dt][1] += rv1;
            ot[dt][2] += rv0; ot[dt][3] += rv1;
        }
    }

    // ---- image branch (2-term QK and WV) ----
    float oi[8][4];
#pragma unroll
    for (int i = 0; i < 8; i++)
#pragma unroll
        for (int c = 0; c < 4; c++) oi[i][c] = 0.f;
    float mi0 = -1e30f, mi1 = -1e30f, li0 = 0.f, li1 = 0.f;
#pragma unroll 1
    for (int ch = 0; ch < 8; ch++) {
        const int j0 = 80 + ch * 32;
        float sc[4][4];
#pragma unroll
        for (int i = 0; i < 4; i++)
#pragma unroll
            for (int c = 0; c < 4; c++) sc[i][c] = 0.f;
#pragma unroll
        for (int kk = 0; kk < 4; kk++) {
#pragma unroll
            for (int p2 = 0; p2 < 2; p2++) {
                uint32_t kh4[4];
                uint32_t ad = sb + AT_KHI + (uint32_t)(j0 + p2 * 16 + brow) * 144
                              + kk * 32 + bdb;
                LDMX4(kh4[0], kh4[1], kh4[2], kh4[3], ad);
                MMA16816(sc[2 * p2], qh[kk], kh4[0], kh4[1]);
                MMA16816(sc[2 * p2], ql[kk], kh4[0], kh4[1]);
                MMA16816(sc[2 * p2 + 1], qh[kk], kh4[2], kh4[3]);
                MMA16816(sc[2 * p2 + 1], ql[kk], kh4[2], kh4[3]);
            }
        }
        float cm0 = -1e30f, cm1 = -1e30f;
#pragma unroll
        for (int t = 0; t < 4; t++) {
            cm0 = fmaxf(cm0, fmaxf(sc[t][0], sc[t][1]));
            cm1 = fmaxf(cm1, fmaxf(sc[t][2], sc[t][3]));
        }
        cm0 = fmaxf(cm0, __shfl_xor_sync(FULL, cm0, 1));
        cm0 = fmaxf(cm0, __shfl_xor_sync(FULL, cm0, 2));
        cm1 = fmaxf(cm1, __shfl_xor_sync(FULL, cm1, 1));
        cm1 = fmaxf(cm1, __shfl_xor_sync(FULL, cm1, 2));
        float mn0 = fmaxf(mi0, cm0), mn1 = fmaxf(mi1, cm1);
        float al0 = __expf(mi0 - mn0), al1 = __expf(mi1 - mn1);
        float cs0 = 0.f, cs1 = 0.f;
#pragma unroll
        for (int t = 0; t < 4; t++) {
            sc[t][0] = __expf(sc[t][0] - mn0); cs0 += sc[t][0];
            sc[t][1] = __expf(sc[t][1] - mn0); cs0 += sc[t][1];
            sc[t][2] = __expf(sc[t][2] - mn1); cs1 += sc[t][2];
            sc[t][3] = __expf(sc[t][3] - mn1); cs1 += sc[t][3];
        }
        cs0 += __shfl_xor_sync(FULL, cs0, 1); cs0 += __shfl_xor_sync(FULL, cs0, 2);
        cs1 += __shfl_xor_sync(FULL, cs1, 1); cs1 += __shfl_xor_sync(FULL, cs1, 2);
        li0 = li0 * al0 + cs0; li1 = li1 * al1 + cs1;
        mi0 = mn0; mi1 = mn1;
#pragma unroll
        for (int dt = 0; dt < 8; dt++) {
            oi[dt][0] *= al0; oi[dt][1] *= al0;
            oi[dt][2] *= al1; oi[dt][3] *= al1;
        }
#pragma unroll
        for (int wk = 0; wk < 2; wk++) {
            uint32_t ahi[4], alo[4];
            wsplit(sc[2 * wk], sc[2 * wk + 1], ahi, alo);
#pragma unroll
            for (int dp = 0; dp < 4; dp++) {
                uint32_t vh4[4];
                uint32_t ad = sb + AT_VHI + (uint32_t)(j0 + wk * 16 + vrow) * 144
                              + dp * 32 + vdb;
                LDMX4T(vh4[0], vh4[1], vh4[2], vh4[3], ad);
                MMA16816(oi[2 * dp], ahi, vh4[0], vh4[1]);
                MMA16816(oi[2 * dp], alo, vh4[0], vh4[1]);
                MMA16816(oi[2 * dp + 1], ahi, vh4[2], vh4[3]);
                MMA16816(oi[2 * dp + 1], alo, vh4[2], vh4[3]);
            }
        }
    }
    float ii0 = 1.f / li0, ii1 = 1.f / li1;

    {
        size_t ob = ((size_t)(b * NQ_ + i0 + r0l)) * 1024 + h * 64 + 2 * (lane & 3);
#pragma unroll
        for (int dt = 0; dt < 8; dt++) {
            float v0 = ot[dt][0] + oi[dt][0] * ii0;
            float v1 = ot[dt][1] + oi[dt][1] * ii0;
            float v2 = ot[dt][2] + oi[dt][2] * ii1;
            float v3 = ot[dt][3] + oi[dt][3] * ii1;
            float h0 = __half2float(__float2half(v0));
            float h1 = __half2float(__float2half(v1));
            float h2 = __half2float(__float2half(v2));
            float h3 = __half2float(__float2half(v3));
            size_t o0 = ob + dt * 8;
            size_t o1 = o0 + 8 * 1024;
            *(uint32_t*)(atthi + o0) = packh(h0, h1);
            *(uint32_t*)(attlo + o0) = packh(v0 - h0, v1 - h1);
            *(uint32_t*)(atthi + o1) = packh(h2, h3);
            *(uint32_t*)(attlo + o1) = packh(v2 - h2, v3 - h3);
        }
    }
}

// ---------------------------------------------------------------------------
// Host launcher
// ---------------------------------------------------------------------------
extern "C" void kernel_launch(void* const* d_in, const int* in_sizes, int n_in,
                              void* d_out, int out_size)
{
    const float* x     = (const float*)d_in[0];
    const float* ctx   = (const float*)d_in[1];
    const float* Wq    = (const float*)d_in[2];
    const float* Wk    = (const float*)d_in[3];
    const float* Wv    = (const float*)d_in[4];
    const float* Wk_ip = (const float*)d_in[5];
    const float* Wv_ip = (const float*)d_in[6];
    const float* Wout  = (const float*)d_in[7];
    const float* bout  = (const float*)d_in[8];
    const float* relk  = (const float*)d_in[9];
    const float* relv  = (const float*)d_in[10];
    float* out = (float*)d_out;

    __half *pahi, *palo, *pqhi, *pqlo, *pchi, *pclo, *pwhi, *pwlo;
    __half *pkt, *pvt, *pki, *pvi;
    cudaGetSymbolAddress((void**)&pahi, g_ahi);
    cudaGetSymbolAddress((void**)&palo, g_alo);
    cudaGetSymbolAddress((void**)&pqhi, g_qhi);
    cudaGetSymbolAddress((void**)&pqlo, g_qlo);
    cudaGetSymbolAddress((void**)&pchi, g_chi);
    cudaGetSymbolAddress((void**)&pclo, g_clo);
    cudaGetSymbolAddress((void**)&pwhi, g_whi);
    cudaGetSymbolAddress((void**)&pwlo, g_wlo);
    cudaGetSymbolAddress((void**)&pkt, g_kt);
    cudaGetSymbolAddress((void**)&pvt, g_vt);
    cudaGetSymbolAddress((void**)&pki, g_ki);
    cudaGetSymbolAddress((void**)&pvi, g_vi);

    cudaFuncSetAttribute(gemm_mma<0>,
                         cudaFuncAttributeMaxDynamicSharedMemorySize, GM_SMEM);
    cudaFuncSetAttribute(gemm_mma<1>,
                         cudaFuncAttributeMaxDynamicSharedMemorySize, GM_SMEM);
    cudaFuncSetAttribute(gemm_mma<2>,
                         cudaFuncAttributeMaxDynamicSharedMemorySize, GM_SMEM);
    cudaFuncSetAttribute(attn_mma,
                         cudaFuncAttributeMaxDynamicSharedMemorySize, AT_SMEM);

    const size_t WSZ = (size_t)DM_ * DM_;
    size_t nx = (size_t)B_ * NQ_ * DM_;
    size_t nc = (size_t)B_ * CTXR * DM_;

    conv_wt<<<dim3(32, 32), dim3(32, 8)>>>(Wq, pwhi + 0 * WSZ, pwlo + 0 * WSZ);
    conv_rows<<<(unsigned)(nx / 4 / 256), 256>>>(x, pahi, palo, nx);
    conv_rows<<<(unsigned)((nc / 4 + 255) / 256), 256>>>(ctx, pchi, pclo, nc);
    conv_wt<<<dim3(32, 32), dim3(32, 8)>>>(Wk, pwhi + 1 * WSZ, pwlo + 1 * WSZ);
    conv_wt<<<dim3(32, 32), dim3(32, 8)>>>(Wv, pwhi + 2 * WSZ, pwlo + 2 * WSZ);

    // Q = (x @ Wq) * 0.125 -> fp16 hi/lo
    gemm_mma<2><<<dim3(8, 512), 256, GM_SMEM>>>(
        pahi, palo, pwhi + 0 * WSZ, nullptr, nullptr,
        pqhi, pqlo, B_ * NQ_, B_ * NQ_, B_ * NQ_, 0);

    conv_wt<<<dim3(32, 32), dim3(32, 8)>>>(Wk_ip, pwhi + 3 * WSZ, pwlo + 3 * WSZ);
    conv_wt<<<dim3(32, 32), dim3(32, 8)>>>(Wv_ip, pwhi + 4 * WSZ, pwlo + 4 * WSZ);
    conv_wt<<<dim3(32, 32), dim3(32, 8)>>>(Wout,  pwhi + 5 * WSZ, pwlo + 5 * WSZ);

    // K/V text -> [b][h][t][d] fp16 hi only
    gemm_mma<1><<<dim3(8, 39), 256, GM_SMEM>>>(
        pchi, pclo, pwhi + 1 * WSZ, nullptr, nullptr,
        pkt, nullptr, B_ * LT_, LT_, CTXR, 0);
    gemm_mma<1><<<dim3(8, 39), 256, GM_SMEM>>>(
        pchi, pclo, pwhi + 2 * WSZ, nullptr, nullptr,
        pvt, nullptr, B_ * LT_, LT_, CTXR, 0);

    // K/V image
    gemm_mma<1><<<dim3(8, 128), 256, GM_SMEM>>>(
        pchi, pclo, pwhi + 3 * WSZ, nullptr, nullptr,
        pki, nullptr, B_ * LI_, LI_, CTXR, LT_);
    gemm_mma<1><<<dim3(8, 128), 256, GM_SMEM>>>(
        pchi, pclo, pwhi + 4 * WSZ, nullptr, nullptr,
        pvi, nullptr, B_ * LI_, LI_, CTXR, LT_);

    // tensor-core attention (2-term) -> fp16 hi/lo into final-GEMM inputs
    attn_mma<<<B_ * H_ * 8, 256, AT_SMEM>>>(
        pqhi, pqlo, pkt, pvt, pki, pvi, relk, relv, pahi, palo);

    // final projection + bias
    gemm_mma<0><<<dim3(8, 512), 256, GM_SMEM>>>(
        pahi, palo, pwhi + 5 * WSZ, out, bout,
        nullptr, nullptr, B_ * NQ_, B_ * NQ_, B_ * NQ_, 0);
}

// round 12
// speedup vs baseline: 1.5236x; 1.5236x over previous
#include <cuda_runtime.h>
#include <cuda_fp16.h>
#include <cstdint>

// ---------------------------------------------------------------------------
// Problem constants
// ---------------------------------------------------------------------------
#define B_    64
#define NQ_   1024
#define DM_   1024
#define H_    16
#define D_    64
#define LT_   77
#define LI_   256
#define NR_   33
#define CTXR  (LT_ + LI_)     // 333

__device__ __forceinline__ uint32_t smem_to_u32(const void* p) {
    uint32_t a;
    asm("{ .reg .u64 t; cvta.to.shared.u64 t, %1; cvt.u32.u64 %0, t; }"
        : "=r"(a) : "l"(p));
    return a;
}

#define CPA16(dst, src) \
    asm volatile("cp.async.cg.shared.global [%0], [%1], 16;" \
                 :: "r"(dst), "l"(src))
#define CPA_COMMIT() asm volatile("cp.async.commit_group;" ::: "memory")
#define CPA_WAIT(n)  asm volatile("cp.async.wait_group %0;" :: "n"(n) : "memory")

#define LDMX4(r0, r1, r2, r3, addr) \
    asm volatile("ldmatrix.sync.aligned.m8n8.x4.shared.b16 {%0,%1,%2,%3}, [%4];" \
                 : "=r"(r0), "=r"(r1), "=r"(r2), "=r"(r3) : "r"(addr))
#define LDMX4T(r0, r1, r2, r3, addr) \
    asm volatile("ldmatrix.sync.aligned.m8n8.x4.trans.shared.b16 {%0,%1,%2,%3}, [%4];" \
                 : "=r"(r0), "=r"(r1), "=r"(r2), "=r"(r3) : "r"(addr))

#define MMA16816(c, a, b0, b1) \
    asm volatile("mma.sync.aligned.m16n8k16.row.col.f32.f16.f16.f32 " \
                 "{%0,%1,%2,%3}, {%4,%5,%6,%7}, {%8,%9}, {%0,%1,%2,%3};" \
                 : "+f"((c)[0]), "+f"((c)[1]), "+f"((c)[2]), "+f"((c)[3]) \
                 : "r"((a)[0]), "r"((a)[1]), "r"((a)[2]), "r"((a)[3]), \
                   "r"(b0), "r"(b1))

__device__ __forceinline__ uint32_t packh(float lo, float hi) {
    uint32_t d;
    asm("cvt.rn.f16x2.f32 %0, %1, %2;" : "=r"(d) : "f"(hi), "f"(lo));
    return d;
}

// ---------------------------------------------------------------------------
// Scratch (static device globals)
// ---------------------------------------------------------------------------
__device__ __half g_ahi[(size_t)B_ * NQ_ * DM_];  // x hi, later att hi
__device__ __half g_alo[(size_t)B_ * NQ_ * DM_];
__device__ __half g_qhi[(size_t)B_ * NQ_ * DM_];
__device__ __half g_qlo[(size_t)B_ * NQ_ * DM_];
__device__ __half g_chi[(size_t)B_ * CTXR * DM_];
__device__ __half g_clo[(size_t)B_ * CTXR * DM_];
__device__ __half g_whi[6 * (size_t)DM_ * DM_];
__device__ __half g_wlo[6 * (size_t)DM_ * DM_];
__device__ __half g_kt[(size_t)B_ * H_ * LT_ * D_];   // hi only
__device__ __half g_vt[(size_t)B_ * H_ * LT_ * D_];
__device__ __half g_ki[(size_t)B_ * H_ * LI_ * D_];
__device__ __half g_vi[(size_t)B_ * H_ * LI_ * D_];

// ---------------------------------------------------------------------------
// fp32 -> fp16 hi/lo split
// ---------------------------------------------------------------------------
__global__ void conv_rows(const float* __restrict__ src,
                          __half* __restrict__ hi,
                          __half* __restrict__ lo, size_t n)
{
    size_t i = ((size_t)blockIdx.x * blockDim.x + threadIdx.x) * 4;
    if (i >= n) return;
    float4 v = *(const float4*)(src + i);
    float h0 = __half2float(__float2half(v.x));
    float h1 = __half2float(__float2half(v.y));
    float h2 = __half2float(__float2half(v.z));
    float h3 = __half2float(__float2half(v.w));
    *(uint2*)(hi + i) = make_uint2(packh(h0, h1), packh(h2, h3));
    *(uint2*)(lo + i) = make_uint2(packh(v.x - h0, v.y - h1),
                                   packh(v.z - h2, v.w - h3));
}

// W [K=1024, N=1024] -> Wt hi/lo [N, K]
__global__ void conv_wt(const float* __restrict__ W,
                        __half* __restrict__ hi,
                        __half* __restrict__ lo)
{
    __shared__ float tile[32][33];
    const int k0 = blockIdx.y * 32, n0 = blockIdx.x * 32;
    const int tx = threadIdx.x;
    for (int r = threadIdx.y; r < 32; r += 8)
        tile[r][tx] = W[(size_t)(k0 + r) * DM_ + n0 + tx];
    __syncthreads();
    for (int r = threadIdx.y; r < 32; r += 8) {
        float v = tile[tx][r];
        float h = __half2float(__float2half(v));
        size_t oi = (size_t)(n0 + r) * DM_ + k0 + tx;
        hi[oi] = __float2half(h);
        lo[oi] = __float2half(v - h);
    }
}

// ---------------------------------------------------------------------------
// fp16 2-term GEMM via mma.sync: C = remap(A) @ B^T, AhiBhi + AloBhi.
// MODE 0: fp32 C + bias.  MODE 1: KV scatter fp16 hi only.  MODE 2: Q *0.125
// hi/lo.  CTA 128x128, BK=32, 3-stage cp.async pipeline, 2 CTAs/SM.
// ---------------------------------------------------------------------------
#define BUF_BYTES   30720
#define GM_SMEM     (3 * BUF_BYTES)   // 92160

template <int MODE>
__global__ void __launch_bounds__(256, 2)
gemm_mma(const __half* __restrict__ Ahi, const __half* __restrict__ Alo,
         const __half* __restrict__ Bhi,
         float* __restrict__ C, const float* __restrict__ bias,
         __half* __restrict__ Chi, __half* __restrict__ Clo,
         int M, int rows_per_seg, int seg_stride, int seg_base)
{
    extern __shared__ __align__(128) char smem[];
    const uint32_t sb = smem_to_u32(smem);
    const int tid = threadIdx.x;
    const int bn = blockIdx.x * 128;
    const int bm = blockIdx.y * 128;
    const int wid = tid >> 5, lane = tid & 31;
    const int Wm = (wid & 3) * 32;
    const int Wn = (wid >> 2) * 64;

    const int lrow = tid >> 1;
    const int lc = tid & 1;
    int m = bm + lrow; if (m > M - 1) m = M - 1;
    const int seg = m / rows_per_seg;
    const int t = m - seg * rows_per_seg;
    const size_t aoff = (size_t)(seg * seg_stride + seg_base + t) * 1024 + lc * 16;
    const size_t boff = (size_t)(bn + lrow) * 1024 + lc * 16;
    const uint32_t soff = (uint32_t)lrow * 80u + (uint32_t)lc * 32u;

    float acc[2][8][4];
#pragma unroll
    for (int i = 0; i < 2; i++)
#pragma unroll
        for (int j = 0; j < 8; j++)
#pragma unroll
            for (int c = 0; c < 4; c++) acc[i][j][c] = 0.f;

    const uint32_t a_frag_row = (uint32_t)(Wm + (lane & 15)) * 80u + ((lane >> 4) * 16u);
    const uint32_t b_frag_row =
        (uint32_t)(Wn + (lane & 7) + ((lane >> 4) << 3)) * 80u + (((lane >> 3) & 1) * 16u);

#define ISSUE(p, k0)                                                       \
    {                                                                      \
        uint32_t d = sb + (p) * BUF_BYTES + soff;                          \
        const __half* s;                                                   \
        s = Ahi + aoff + (k0); CPA16(d,           s); CPA16(d + 16,         s + 8); \
        s = Alo + aoff + (k0); CPA16(d + 10240,   s); CPA16(d + 10240 + 16, s + 8); \
        s = Bhi + boff + (k0); CPA16(d + 20480,   s); CPA16(d + 20480 + 16, s + 8); \
    }

    ISSUE(0, 0);
    CPA_COMMIT();
    ISSUE(1, 32);
    CPA_COMMIT();

    int stage = 0;
    for (int i = 0; i < 32; i++) {
        if (i < 31) { CPA_WAIT(1); } else { CPA_WAIT(0); }
        __syncthreads();
        if (i + 2 < 32) {
            int ns = stage + 2; if (ns >= 3) ns -= 3;
            ISSUE(ns, (i + 2) * 32);
            CPA_COMMIT();
        }

        const uint32_t base = sb + stage * BUF_BYTES;
#pragma unroll
        for (int kk = 0; kk < 2; kk++) {
            uint32_t ah[2][4], al[2][4], bh[4][4];
            const uint32_t ar = base + a_frag_row + kk * 32;
            LDMX4(ah[0][0], ah[0][1], ah[0][2], ah[0][3], ar);
            LDMX4(ah[1][0], ah[1][1], ah[1][2], ah[1][3], ar + 16 * 80);
            LDMX4(al[0][0], al[0][1], al[0][2], al[0][3], ar + 10240);
            LDMX4(al[1][0], al[1][1], al[1][2], al[1][3], ar + 10240 + 16 * 80);
#pragma unroll
            for (int j = 0; j < 4; j++) {
                const uint32_t br = base + 20480 + b_frag_row + kk * 32
                                    + (uint32_t)j * (16 * 80);
                LDMX4(bh[j][0], bh[j][1], bh[j][2], bh[j][3], br);
            }
#pragma unroll
            for (int j = 0; j < 4; j++)
#pragma unroll
                for (int mt = 0; mt < 2; mt++) {
                    MMA16816(acc[mt][2 * j],     ah[mt], bh[j][0], bh[j][1]);
                    MMA16816(acc[mt][2 * j + 1], ah[mt], bh[j][2], bh[j][3]);
                }
#pragma unroll
            for (int j = 0; j < 4; j++)
#pragma unroll
                for (int mt = 0; mt < 2; mt++) {
                    MMA16816(acc[mt][2 * j],     al[mt], bh[j][0], bh[j][1]);
                    MMA16816(acc[mt][2 * j + 1], al[mt], bh[j][2], bh[j][3]);
                }
        }
        stage++; if (stage >= 3) stage = 0;
    }
#undef ISSUE

    const int er = lane >> 2, ec = (lane & 3) * 2;
#pragma unroll
    for (int mt = 0; mt < 2; mt++) {
#pragma unroll
        for (int hrow = 0; hrow < 2; hrow++) {
            const int cm = bm + Wm + mt * 16 + er + hrow * 8;
            if (cm >= M) continue;
            if (MODE == 1) {
                const int segc = cm / rows_per_seg;
                const int tc = cm - segc * rows_per_seg;
#pragma unroll
                for (int nt = 0; nt < 8; nt++) {
                    const int cn = bn + Wn + nt * 8 + ec;
                    const int hh = cn >> 6, dd = cn & 63;
                    size_t oi = (((size_t)segc * H_ + hh) * rows_per_seg + tc) * 64 + dd;
                    *(uint32_t*)(Chi + oi) =
                        packh(acc[mt][nt][hrow * 2], acc[mt][nt][hrow * 2 + 1]);
                }
            } else if (MODE == 2) {
#pragma unroll
                for (int nt = 0; nt < 8; nt++) {
                    const int cn = bn + Wn + nt * 8 + ec;
                    size_t oi = (size_t)cm * DM_ + cn;
                    float v0 = acc[mt][nt][hrow * 2] * 0.125f;
                    float v1 = acc[mt][nt][hrow * 2 + 1] * 0.125f;
                    float h0 = __half2float(__float2half(v0));
                    float h1 = __half2float(__float2half(v1));
                    *(uint32_t*)(Chi + oi) = packh(h0, h1);
                    *(uint32_t*)(Clo + oi) = packh(v0 - h0, v1 - h1);
                }
            } else {
                float* Cp = C + (size_t)cm * DM_ + bn + Wn + ec;
                const float* bp = bias + bn + Wn + ec;
#pragma unroll
                for (int nt = 0; nt < 8; nt++) {
                    float2 v = make_float2(acc[mt][nt][hrow * 2] + bp[nt * 8],
                                           acc[mt][nt][hrow * 2 + 1] + bp[nt * 8 + 1]);
                    *(float2*)(Cp + nt * 8) = v;
                }
            }
        }
    }
}

// ---------------------------------------------------------------------------
// Tensor-core flash attention, 2-term (K/V hi-only in smem), image-first
// merged accumulator. One CTA = (b, h, 128-query tile). smem ~131 KB.
// ---------------------------------------------------------------------------
#define AT_KHI 0                 // [336][144B] K hi (text 0..76, img 80..335)
#define AT_VHI 48384             // [336][144B] V hi
#define AT_QHI 96768             // [128][144B]
#define AT_QLO 115200            // [128][144B]
#define AT_PS  96768             // fp32 [128][34] (reuses QHI after frag load)
#define AT_RKH 115200            // relk hi (reuses QLO)
#define AT_RKL 120960
#define AT_SMEM 133632

__device__ __forceinline__ int bidx(int j, int i)
{
    int d = j - i;
    d = max(-16, min(16, d));
    return d + 16;
}

__device__ __forceinline__ void wsplit(const float* s0, const float* s1,
                                       uint32_t* ahi, uint32_t* alo)
{
    float v[8] = {s0[0], s0[1], s0[2], s0[3], s1[0], s1[1], s1[2], s1[3]};
    float hv[8];
#pragma unroll
    for (int i = 0; i < 8; i++)
        hv[i] = __half2float(__float2half(v[i]));
    ahi[0] = packh(hv[0], hv[1]); ahi[1] = packh(hv[2], hv[3]);
    ahi[2] = packh(hv[4], hv[5]); ahi[3] = packh(hv[6], hv[7]);
    alo[0] = packh(v[0] - hv[0], v[1] - hv[1]);
    alo[1] = packh(v[2] - hv[2], v[3] - hv[3]);
    alo[2] = packh(v[4] - hv[4], v[5] - hv[5]);
    alo[3] = packh(v[6] - hv[6], v[7] - hv[7]);
}

__global__ void __launch_bounds__(256, 1)
attn_mma(const __half* __restrict__ qhi, const __half* __restrict__ qlo,
         const __half* __restrict__ kt, const __half* __restrict__ vt,
         const __half* __restrict__ ki, const __half* __restrict__ vi,
         const float* __restrict__ relk, const float* __restrict__ relv,
         __half* __restrict__ atthi, __half* __restrict__ attlo)
{
    extern __shared__ __align__(128) char sm[];
    const uint32_t sb = smem_to_u32(sm);
    const int tid = threadIdx.x, w = tid >> 5, lane = tid & 31;
    const int bh = blockIdx.x >> 3, qt = blockIdx.x & 7;
    const int b = bh >> 4, h = bh & 15;
    const int i0 = qt * 128;
    const unsigned FULL = 0xffffffffu;

    // ---- stage K/V (hi only) + Q (hi/lo) ----
    {
        size_t tb = (size_t)bh * (LT_ * 64);
        for (int idx = tid; idx < LT_ * 8; idx += 256) {
            int r = idx >> 3, c = idx & 7;
            uint32_t d = (uint32_t)r * 144 + c * 16;
            size_t s = tb + (size_t)r * 64 + c * 8;
            CPA16(sb + AT_KHI + d, kt + s);
            CPA16(sb + AT_VHI + d, vt + s);
        }
        size_t ib = (size_t)bh * (LI_ * 64);
        for (int idx = tid; idx < LI_ * 8; idx += 256) {
            int r = idx >> 3, c = idx & 7;
            uint32_t d = (uint32_t)(80 + r) * 144 + c * 16;
            size_t s = ib + (size_t)r * 64 + c * 8;
            CPA16(sb + AT_KHI + d, ki + s);
            CPA16(sb + AT_VHI + d, vi + s);
        }
        size_t qb = ((size_t)(b * NQ_ + i0)) * 1024 + h * 64;
        for (int idx = tid; idx < 128 * 8; idx += 256) {
            int r = idx >> 3, c = idx & 7;
            uint32_t d = (uint32_t)r * 144 + c * 16;
            size_t s = qb + (size_t)r * 1024 + c * 8;
            CPA16(sb + AT_QHI + d, qhi + s);
            CPA16(sb + AT_QLO + d, qlo + s);
        }
        for (int idx = tid; idx < 3 * 36; idx += 256) {
            uint32_t d = (uint32_t)(77 + idx / 36) * 144 + (idx % 36) * 4;
            *(uint32_t*)(sm + AT_KHI + d) = 0;
            *(uint32_t*)(sm + AT_VHI + d) = 0;
        }
        CPA_COMMIT();
        CPA_WAIT(0);
        __syncthreads();
    }

    const int wr = w * 16;
    const int r0l = wr + (lane >> 2);

    // ---- Q fragments ----
    uint32_t qh[4][4], ql[4][4];
    {
        int row = wr + (lane & 15);
        int kb = (lane >> 4) * 16;
#pragma unroll
        for (int kk = 0; kk < 4; kk++) {
            uint32_t a = sb + AT_QHI + (uint32_t)row * 144 + kk * 32 + kb;
            LDMX4(qh[kk][0], qh[kk][1], qh[kk][2], qh[kk][3], a);
            LDMX4(ql[kk][0], ql[kk][1], ql[kk][2], ql[kk][3], a + (AT_QLO - AT_QHI));
        }
    }
    __syncthreads();

    // ---- stage relk hi/lo (tile 0; published by the post-image sync) ----
    if (qt == 0) {
        for (int idx = tid; idx < NR_ * 64; idx += 256) {
            int r = idx >> 6, dc = idx & 63;
            float v = relk[idx];
            float hh = __half2float(__float2half(v));
            *(__half*)(sm + AT_RKH + r * 144 + dc * 2) = __float2half(hh);
            *(__half*)(sm + AT_RKL + r * 144 + dc * 2) = __float2half(v - hh);
        }
    }

    const int brow = ((lane >> 4) << 3) + (lane & 7);
    const int bdb = (lane & 8) * 2;
    const int vrow = (lane & 8) + (lane & 7);
    const int vdb = (lane >> 4) * 16;

    // ================= image branch first (merged accumulator) =============
    float o[8][4];
#pragma unroll
    for (int i = 0; i < 8; i++)
#pragma unroll
        for (int c = 0; c < 4; c++) o[i][c] = 0.f;
    float mi0 = -1e30f, mi1 = -1e30f, li0 = 0.f, li1 = 0.f;
#pragma unroll 1
    for (int ch = 0; ch < 8; ch++) {
        const int j0 = 80 + ch * 32;
        float sc[4][4];
#pragma unroll
        for (int i = 0; i < 4; i++)
#pragma unroll
            for (int c = 0; c < 4; c++) sc[i][c] = 0.f;
#pragma unroll
        for (int kk = 0; kk < 4; kk++) {
#pragma unroll
            for (int p2 = 0; p2 < 2; p2++) {
                uint32_t kh4[4];
                uint32_t ad = sb + AT_KHI + (uint32_t)(j0 + p2 * 16 + brow) * 144
                              + kk * 32 + bdb;
                LDMX4(kh4[0], kh4[1], kh4[2], kh4[3], ad);
                MMA16816(sc[2 * p2], qh[kk], kh4[0], kh4[1]);
                MMA16816(sc[2 * p2], ql[kk], kh4[0], kh4[1]);
                MMA16816(sc[2 * p2 + 1], qh[kk], kh4[2], kh4[3]);
                MMA16816(sc[2 * p2 + 1], ql[kk], kh4[2], kh4[3]);
            }
        }
        float cm0 = -1e30f, cm1 = -1e30f;
#pragma unroll
        for (int t = 0; t < 4; t++) {
            cm0 = fmaxf(cm0, fmaxf(sc[t][0], sc[t][1]));
            cm1 = fmaxf(cm1, fmaxf(sc[t][2], sc[t][3]));
        }
        cm0 = fmaxf(cm0, __shfl_xor_sync(FULL, cm0, 1));
        cm0 = fmaxf(cm0, __shfl_xor_sync(FULL, cm0, 2));
        cm1 = fmaxf(cm1, __shfl_xor_sync(FULL, cm1, 1));
        cm1 = fmaxf(cm1, __shfl_xor_sync(FULL, cm1, 2));
        float mn0 = fmaxf(mi0, cm0), mn1 = fmaxf(mi1, cm1);
        float al0 = __expf(mi0 - mn0), al1 = __expf(mi1 - mn1);
        float cs0 = 0.f, cs1 = 0.f;
#pragma unroll
        for (int t = 0; t < 4; t++) {
            sc[t][0] = __expf(sc[t][0] - mn0); cs0 += sc[t][0];
            sc[t][1] = __expf(sc[t][1] - mn0); cs0 += sc[t][1];
            sc[t][2] = __expf(sc[t][2] - mn1); cs1 += sc[t][2];
            sc[t][3] = __expf(sc[t][3] - mn1); cs1 += sc[t][3];
        }
        cs0 += __shfl_xor_sync(FULL, cs0, 1); cs0 += __shfl_xor_sync(FULL, cs0, 2);
        cs1 += __shfl_xor_sync(FULL, cs1, 1); cs1 += __shfl_xor_sync(FULL, cs1, 2);
        li0 = li0 * al0 + cs0; li1 = li1 * al1 + cs1;
        mi0 = mn0; mi1 = mn1;
#pragma unroll
        for (int dt = 0; dt < 8; dt++) {
            o[dt][0] *= al0; o[dt][1] *= al0;
            o[dt][2] *= al1; o[dt][3] *= al1;
        }
#pragma unroll
        for (int wk = 0; wk < 2; wk++) {
            uint32_t ahi[4], alo[4];
            wsplit(sc[2 * wk], sc[2 * wk + 1], ahi, alo);
#pragma unroll
            for (int dp = 0; dp < 4; dp++) {
                uint32_t vh4[4];
                uint32_t ad = sb + AT_VHI + (uint32_t)(j0 + wk * 16 + vrow) * 144
                              + dp * 32 + vdb;
                LDMX4T(vh4[0], vh4[1], vh4[2], vh4[3], ad);
                MMA16816(o[2 * dp], ahi, vh4[0], vh4[1]);
                MMA16816(o[2 * dp], alo, vh4[0], vh4[1]);
                MMA16816(o[2 * dp + 1], ahi, vh4[2], vh4[3]);
                MMA16816(o[2 * dp + 1], alo, vh4[2], vh4[3]);
            }
        }
    }
    {
        float ii0 = 1.f / li0, ii1 = 1.f / li1;
#pragma unroll
        for (int dt = 0; dt < 8; dt++) {
            o[dt][0] *= ii0; o[dt][1] *= ii0;
            o[dt][2] *= ii1; o[dt][3] *= ii1;
        }
    }

    // publish relk staging (tile 0) to all warps
    __syncthreads();

    float* pS = (float*)(sm + AT_PS);

    // ---- rel-K projections (tile 0; 3-term kept) ----
    if (qt == 0) {
        float pr[5][4];
#pragma unroll
        for (int i = 0; i < 5; i++)
#pragma unroll
            for (int c = 0; c < 4; c++) pr[i][c] = 0.f;
#pragma unroll
        for (int kk = 0; kk < 4; kk++) {
#pragma unroll
            for (int p2 = 0; p2 < 3; p2++) {
                uint32_t bh4[4], bl4[4];
                uint32_t ad = sb + AT_RKH + (uint32_t)(p2 * 16 + brow) * 144
                              + kk * 32 + bdb;
                LDMX4(bh4[0], bh4[1], bh4[2], bh4[3], ad);
                LDMX4(bl4[0], bl4[1], bl4[2], bl4[3], ad + (AT_RKL - AT_RKH));
                MMA16816(pr[2 * p2], qh[kk], bh4[0], bh4[1]);
                MMA16816(pr[2 * p2], ql[kk], bh4[0], bh4[1]);
                MMA16816(pr[2 * p2], qh[kk], bl4[0], bl4[1]);
                if (p2 < 2) {
                    MMA16816(pr[2 * p2 + 1], qh[kk], bh4[2], bh4[3]);
                    MMA16816(pr[2 * p2 + 1], ql[kk], bh4[2], bh4[3]);
                    MMA16816(pr[2 * p2 + 1], qh[kk], bl4[2], bl4[3]);
                }
            }
        }
#pragma unroll
        for (int nt = 0; nt < 5; nt++) {
            int c0 = nt * 8 + 2 * (lane & 3);
            if (c0 < NR_) {
                pS[r0l * 34 + c0] = pr[nt][0];
                pS[(r0l + 8) * 34 + c0] = pr[nt][2];
            }
            if (c0 + 1 < NR_) {
                pS[r0l * 34 + c0 + 1] = pr[nt][1];
                pS[(r0l + 8) * 34 + c0 + 1] = pr[nt][3];
            }
        }
        __syncwarp();
    }

    // ---- text scores (2-term: Qhi@Khi + Qlo@Khi) ----
    float s[10][4];
#pragma unroll
    for (int i = 0; i < 10; i++)
#pragma unroll
        for (int c = 0; c < 4; c++) s[i][c] = 0.f;
#pragma unroll
    for (int kk = 0; kk < 4; kk++) {
#pragma unroll
        for (int p2 = 0; p2 < 5; p2++) {
            uint32_t kh4[4];
            uint32_t ad = sb + AT_KHI + (uint32_t)(p2 * 16 + brow) * 144
                          + kk * 32 + bdb;
            LDMX4(kh4[0], kh4[1], kh4[2], kh4[3], ad);
            MMA16816(s[2 * p2], qh[kk], kh4[0], kh4[1]);
            MMA16816(s[2 * p2], ql[kk], kh4[0], kh4[1]);
            MMA16816(s[2 * p2 + 1], qh[kk], kh4[2], kh4[3]);
            MMA16816(s[2 * p2 + 1], ql[kk], kh4[2], kh4[3]);
        }
    }

#pragma unroll
    for (int nt = 0; nt < 10; nt++) {
        int c0 = nt * 8 + 2 * (lane & 3);
        if (qt == 0) {
            s[nt][0] += pS[r0l * 34 + bidx(c0, r0l)];
            s[nt][1] += pS[r0l * 34 + bidx(c0 + 1, r0l)];
            s[nt][2] += pS[(r0l + 8) * 34 + bidx(c0, r0l + 8)];
            s[nt][3] += pS[(r0l + 8) * 34 + bidx(c0 + 1, r0l + 8)];
        }
        if (c0 >= LT_) { s[nt][0] = -1e30f; s[nt][2] = -1e30f; }
        if (c0 + 1 >= LT_) { s[nt][1] = -1e30f; s[nt][3] = -1e30f; }
    }

    float m0 = -1e30f, m1 = -1e30f;
#pragma unroll
    for (int nt = 0; nt < 10; nt++) {
        m0 = fmaxf(m0, fmaxf(s[nt][0], s[nt][1]));
        m1 = fmaxf(m1, fmaxf(s[nt][2], s[nt][3]));
    }
    m0 = fmaxf(m0, __shfl_xor_sync(FULL, m0, 1));
    m0 = fmaxf(m0, __shfl_xor_sync(FULL, m0, 2));
    m1 = fmaxf(m1, __shfl_xor_sync(FULL, m1, 1));
    m1 = fmaxf(m1, __shfl_xor_sync(FULL, m1, 2));
    float l0 = 0.f, l1 = 0.f;
#pragma unroll
    for (int nt = 0; nt < 10; nt++) {
        s[nt][0] = __expf(s[nt][0] - m0); l0 += s[nt][0];
        s[nt][1] = __expf(s[nt][1] - m0); l0 += s[nt][1];
        s[nt][2] = __expf(s[nt][2] - m1); l1 += s[nt][2];
        s[nt][3] = __expf(s[nt][3] - m1); l1 += s[nt][3];
    }
    l0 += __shfl_xor_sync(FULL, l0, 1); l0 += __shfl_xor_sync(FULL, l0, 2);
    l1 += __shfl_xor_sync(FULL, l1, 1); l1 += __shfl_xor_sync(FULL, l1, 2);
    float inv0 = 1.f / l0, inv1 = 1.f / l1;
#pragma unroll
    for (int nt = 0; nt < 10; nt++) {
        s[nt][0] *= inv0; s[nt][1] *= inv0;
        s[nt][2] *= inv1; s[nt][3] *= inv1;
    }

    if (qt == 0) {
        for (int idx = lane; idx < 16 * 34; idx += 32)
            pS[(wr + idx / 34) * 34 + idx % 34] = 0.f;
        __syncwarp();
#pragma unroll
        for (int nt = 0; nt < 10; nt++) {
            int c0 = nt * 8 + 2 * (lane & 3);
            if (c0 < LT_) {
                atomicAdd(&pS[r0l * 34 + bidx(c0, r0l)], s[nt][0]);
                atomicAdd(&pS[(r0l + 8) * 34 + bidx(c0, r0l + 8)], s[nt][2]);
            }
            if (c0 + 1 < LT_) {
                atomicAdd(&pS[r0l * 34 + bidx(c0 + 1, r0l)], s[nt][1]);
                atomicAdd(&pS[(r0l + 8) * 34 + bidx(c0 + 1, r0l + 8)], s[nt][3]);
            }
        }
        __syncwarp();
    }

    // ---- O += W @ V_text (2-term: Whi@Vhi + Wlo@Vhi) ----
#pragma unroll
    for (int wk = 0; wk < 5; wk++) {
        uint32_t ahi[4], alo[4];
        wsplit(s[2 * wk], s[2 * wk + 1], ahi, alo);
#pragma unroll
        for (int dp = 0; dp < 4; dp++) {
            uint32_t vh4[4];
            uint32_t ad = sb + AT_VHI + (uint32_t)(wk * 16 + vrow) * 144
                          + dp * 32 + vdb;
            LDMX4T(vh4[0], vh4[1], vh4[2], vh4[3], ad);
            MMA16816(o[2 * dp], ahi, vh4[0], vh4[1]);
            MMA16816(o[2 * dp], alo, vh4[0], vh4[1]);
            MMA16816(o[2 * dp + 1], ahi, vh4[2], vh4[3]);
            MMA16816(o[2 * dp + 1], alo, vh4[2], vh4[3]);
        }
    }

    // ---- rel-V contribution ----
    if (qt == 0) {
#pragma unroll 1
        for (int r = 0; r < NR_; r++) {
            float w0 = pS[r0l * 34 + r];
            float w1 = pS[(r0l + 8) * 34 + r];
            const float* rv = relv + r * 64 + 2 * (lane & 3);
#pragma unroll
            for (int dt = 0; dt < 8; dt++) {
                float rv0 = rv[dt * 8], rv1 = rv[dt * 8 + 1];
                o[dt][0] += w0 * rv0; o[dt][1] += w0 * rv1;
                o[dt][2] += w1 * rv0; o[dt][3] += w1 * rv1;
            }
        }
    } else {
        const float* rv = relv + 2 * (lane & 3);
#pragma unroll
        for (int dt = 0; dt < 8; dt++) {
            float rv0 = rv[dt * 8], rv1 = rv[dt * 8 + 1];
            o[dt][0] += rv0; o[dt][1] += rv1;
            o[dt][2] += rv0; o[dt][3] += rv1;
        }
    }

    // ---- store fp16 hi/lo ----
    {
        size_t ob = ((size_t)(b * NQ_ + i0 + r0l)) * 1024 + h * 64 + 2 * (lane & 3);
#pragma unroll
        for (int dt = 0; dt < 8; dt++) {
            float v0 = o[dt][0];
            float v1 = o[dt][1];
            float v2 = o[dt][2];
            float v3 = o[dt][3];
            float h0 = __half2float(__float2half(v0));
            float h1 = __half2float(__float2half(v1));
            float h2 = __half2float(__float2half(v2));
            float h3 = __half2float(__float2half(v3));
            size_t o0 = ob + dt * 8;
            size_t o1 = o0 + 8 * 1024;
            *(uint32_t*)(atthi + o0) = packh(h0, h1);
            *(uint32_t*)(attlo + o0) = packh(v0 - h0, v1 - h1);
            *(uint32_t*)(atthi + o1) = packh(h2, h3);
            *(uint32_t*)(attlo + o1) = packh(v2 - h2, v3 - h3);
        }
    }
}

// ---------------------------------------------------------------------------
// Host launcher
// ---------------------------------------------------------------------------
extern "C" void kernel_launch(void* const* d_in, const int* in_sizes, int n_in,
                              void* d_out, int out_size)
{
    const float* x     = (const float*)d_in[0];
    const float* ctx   = (const float*)d_in[1];
    const float* Wq    = (const float*)d_in[2];
    const float* Wk    = (const float*)d_in[3];
    const float* Wv    = (const float*)d_in[4];
    const float* Wk_ip = (const float*)d_in[5];
    const float* Wv_ip = (const float*)d_in[6];
    const float* Wout  = (const float*)d_in[7];
    const float* bout  = (const float*)d_in[8];
    const float* relk  = (const float*)d_in[9];
    const float* relv  = (const float*)d_in[10];
    float* out = (float*)d_out;

    __half *pahi, *palo, *pqhi, *pqlo, *pchi, *pclo, *pwhi, *pwlo;
    __half *pkt, *pvt, *pki, *pvi;
    cudaGetSymbolAddress((void**)&pahi, g_ahi);
    cudaGetSymbolAddress((void**)&palo, g_alo);
    cudaGetSymbolAddress((void**)&pqhi, g_qhi);
    cudaGetSymbolAddress((void**)&pqlo, g_qlo);
    cudaGetSymbolAddress((void**)&pchi, g_chi);
    cudaGetSymbolAddress((void**)&pclo, g_clo);
    cudaGetSymbolAddress((void**)&pwhi, g_whi);
    cudaGetSymbolAddress((void**)&pwlo, g_wlo);
    cudaGetSymbolAddress((void**)&pkt, g_kt);
    cudaGetSymbolAddress((void**)&pvt, g_vt);
    cudaGetSymbolAddress((void**)&pki, g_ki);
    cudaGetSymbolAddress((void**)&pvi, g_vi);

    cudaFuncSetAttribute(gemm_mma<0>,
                         cudaFuncAttributeMaxDynamicSharedMemorySize, GM_SMEM);
    cudaFuncSetAttribute(gemm_mma<1>,
                         cudaFuncAttributeMaxDynamicSharedMemorySize, GM_SMEM);
    cudaFuncSetAttribute(gemm_mma<2>,
                         cudaFuncAttributeMaxDynamicSharedMemorySize, GM_SMEM);
    cudaFuncSetAttribute(attn_mma,
                         cudaFuncAttributeMaxDynamicSharedMemorySize, AT_SMEM);

    const size_t WSZ = (size_t)DM_ * DM_;
    size_t nx = (size_t)B_ * NQ_ * DM_;
    size_t nc = (size_t)B_ * CTXR * DM_;

    conv_wt<<<dim3(32, 32), dim3(32, 8)>>>(Wq, pwhi + 0 * WSZ, pwlo + 0 * WSZ);
    conv_rows<<<(unsigned)(nx / 4 / 256), 256>>>(x, pahi, palo, nx);
    conv_rows<<<(unsigned)((nc / 4 + 255) / 256), 256>>>(ctx, pchi, pclo, nc);
    conv_wt<<<dim3(32, 32), dim3(32, 8)>>>(Wk, pwhi + 1 * WSZ, pwlo + 1 * WSZ);
    conv_wt<<<dim3(32, 32), dim3(32, 8)>>>(Wv, pwhi + 2 * WSZ, pwlo + 2 * WSZ);

    // Q = (x @ Wq) * 0.125 -> fp16 hi/lo
    gemm_mma<2><<<dim3(8, 512), 256, GM_SMEM>>>(
        pahi, palo, pwhi + 0 * WSZ, nullptr, nullptr,
        pqhi, pqlo, B_ * NQ_, B_ * NQ_, B_ * NQ_, 0);

    conv_wt<<<dim3(32, 32), dim3(32, 8)>>>(Wk_ip, pwhi + 3 * WSZ, pwlo + 3 * WSZ);
    conv_wt<<<dim3(32, 32), dim3(32, 8)>>>(Wv_ip, pwhi + 4 * WSZ, pwlo + 4 * WSZ);
    conv_wt<<<dim3(32, 32), dim3(32, 8)>>>(Wout,  pwhi + 5 * WSZ, pwlo + 5 * WSZ);

    // K/V text -> [b][h][t][d] fp16 hi only
    gemm_mma<1><<<dim3(8, 39), 256, GM_SMEM>>>(
        pchi, pclo, pwhi + 1 * WSZ, nullptr, nullptr,
        pkt, nullptr, B_ * LT_, LT_, CTXR, 0);
    gemm_mma<1><<<dim3(8, 39), 256, GM_SMEM>>>(
        pchi, pclo, pwhi + 2 * WSZ, nullptr, nullptr,
        pvt, nullptr, B_ * LT_, LT_, CTXR, 0);

    // K/V image
    gemm_mma<1><<<dim3(8, 128), 256, GM_SMEM>>>(
        pchi, pclo, pwhi + 3 * WSZ, nullptr, nullptr,
        pki, nullptr, B_ * LI_, LI_, CTXR, LT_);
    gemm_mma<1><<<dim3(8, 128), 256, GM_SMEM>>>(
        pchi, pclo, pwhi + 4 * WSZ, nullptr, nullptr,
        pvi, nullptr, B_ * LI_, LI_, CTXR, LT_);

    // tensor-core attention (2-term, image-first) -> fp16 hi/lo
    attn_mma<<<B_ * H_ * 8, 256, AT_SMEM>>>(
        pqhi, pqlo, pkt, pvt, pki, pvi, relk, relv, pahi, palo);

    // final projection + bias
    gemm_mma<0><<<dim3(8, 512), 256, GM_SMEM>>>(
        pahi, palo, pwhi + 5 * WSZ, out, bout,
        nullptr, nullptr, B_ * NQ_, B_ * NQ_, B_ * NQ_, 0);
}

// round 13
// speedup vs baseline: 1.8253x; 1.1980x over previous
#include <cuda_runtime.h>
#include <cuda_fp16.h>
#include <cstdint>

// ---------------------------------------------------------------------------
// Problem constants
// ---------------------------------------------------------------------------
#define B_    64
#define NQ_   1024
#define DM_   1024
#define H_    16
#define D_    64
#define LT_   77
#define LI_   256
#define NR_   33
#define CTXR  (LT_ + LI_)     // 333

__device__ __forceinline__ uint32_t smem_to_u32(const void* p) {
    uint32_t a;
    asm("{ .reg .u64 t; cvta.to.shared.u64 t, %1; cvt.u32.u64 %0, t; }"
        : "=r"(a) : "l"(p));
    return a;
}

#define CPA16(dst, src) \
    asm volatile("cp.async.cg.shared.global [%0], [%1], 16;" \
                 :: "r"(dst), "l"(src))
#define CPA_COMMIT() asm volatile("cp.async.commit_group;" ::: "memory")
#define CPA_WAIT(n)  asm volatile("cp.async.wait_group %0;" :: "n"(n) : "memory")

#define LDMX4(r0, r1, r2, r3, addr) \
    asm volatile("ldmatrix.sync.aligned.m8n8.x4.shared.b16 {%0,%1,%2,%3}, [%4];" \
                 : "=r"(r0), "=r"(r1), "=r"(r2), "=r"(r3) : "r"(addr))
#define LDMX4T(r0, r1, r2, r3, addr) \
    asm volatile("ldmatrix.sync.aligned.m8n8.x4.trans.shared.b16 {%0,%1,%2,%3}, [%4];" \
                 : "=r"(r0), "=r"(r1), "=r"(r2), "=r"(r3) : "r"(addr))

#define MMA16816(c, a, b0, b1) \
    asm volatile("mma.sync.aligned.m16n8k16.row.col.f32.f16.f16.f32 " \
                 "{%0,%1,%2,%3}, {%4,%5,%6,%7}, {%8,%9}, {%0,%1,%2,%3};" \
                 : "+f"((c)[0]), "+f"((c)[1]), "+f"((c)[2]), "+f"((c)[3]) \
                 : "r"((a)[0]), "r"((a)[1]), "r"((a)[2]), "r"((a)[3]), \
                   "r"(b0), "r"(b1))

__device__ __forceinline__ uint32_t packh(float lo, float hi) {
    uint32_t d;
    asm("cvt.rn.f16x2.f32 %0, %1, %2;" : "=r"(d) : "f"(hi), "f"(lo));
    return d;
}

// ---------------------------------------------------------------------------
// Scratch (static device globals)
// ---------------------------------------------------------------------------
__device__ __half g_ahi[(size_t)B_ * NQ_ * DM_];  // x hi, later att hi
__device__ __half g_alo[(size_t)B_ * NQ_ * DM_];
__device__ __half g_qhi[(size_t)B_ * NQ_ * DM_];
__device__ __half g_qlo[(size_t)B_ * NQ_ * DM_];
__device__ __half g_chi[(size_t)B_ * CTXR * DM_];
__device__ __half g_clo[(size_t)B_ * CTXR * DM_];
__device__ __half g_whi[6 * (size_t)DM_ * DM_];
__device__ __half g_wlo[6 * (size_t)DM_ * DM_];
__device__ __half g_kt[(size_t)B_ * H_ * LT_ * D_];   // hi only
__device__ __half g_vt[(size_t)B_ * H_ * LT_ * D_];
__device__ __half g_ki[(size_t)B_ * H_ * LI_ * D_];
__device__ __half g_vi[(size_t)B_ * H_ * LI_ * D_];

// ---------------------------------------------------------------------------
// fp32 -> fp16 hi/lo split
// ---------------------------------------------------------------------------
__global__ void conv_rows(const float* __restrict__ src,
                          __half* __restrict__ hi,
                          __half* __restrict__ lo, size_t n)
{
    size_t i = ((size_t)blockIdx.x * blockDim.x + threadIdx.x) * 4;
    if (i >= n) return;
    float4 v = *(const float4*)(src + i);
    float h0 = __half2float(__float2half(v.x));
    float h1 = __half2float(__float2half(v.y));
    float h2 = __half2float(__float2half(v.z));
    float h3 = __half2float(__float2half(v.w));
    *(uint2*)(hi + i) = make_uint2(packh(h0, h1), packh(h2, h3));
    if (lo)
        *(uint2*)(lo + i) = make_uint2(packh(v.x - h0, v.y - h1),
                                       packh(v.z - h2, v.w - h3));
}

// W [K=1024, N=1024] -> Wt hi/lo [N, K]
__global__ void conv_wt(const float* __restrict__ W,
                        __half* __restrict__ hi,
                        __half* __restrict__ lo)
{
    __shared__ float tile[32][33];
    const int k0 = blockIdx.y * 32, n0 = blockIdx.x * 32;
    const int tx = threadIdx.x;
    for (int r = threadIdx.y; r < 32; r += 8)
        tile[r][tx] = W[(size_t)(k0 + r) * DM_ + n0 + tx];
    __syncthreads();
    for (int r = threadIdx.y; r < 32; r += 8) {
        float v = tile[tx][r];
        float h = __half2float(__float2half(v));
        size_t oi = (size_t)(n0 + r) * DM_ + k0 + tx;
        hi[oi] = __float2half(h);
        lo[oi] = __float2half(v - h);
    }
}

// ---------------------------------------------------------------------------
// fp16 split GEMM via mma.sync: C = remap(A) @ B^T.
// TERMS 2: AhiBhi + AloBhi.  TERMS 1: AhiBhi only (Alo never loaded).
// MODE 0: fp32 C + bias.  MODE 1: KV scatter fp16 hi only.  MODE 2: Q *0.125
// hi/lo.  CTA 128x128, BK=32, 3-stage cp.async pipeline, 2 CTAs/SM.
// ---------------------------------------------------------------------------
#define BUF_BYTES   30720
#define GM_SMEM     (3 * BUF_BYTES)   // 92160

template <int MODE, int TERMS>
__global__ void __launch_bounds__(256, 2)
gemm_mma(const __half* __restrict__ Ahi, const __half* __restrict__ Alo,
         const __half* __restrict__ Bhi,
         float* __restrict__ C, const float* __restrict__ bias,
         __half* __restrict__ Chi, __half* __restrict__ Clo,
         int M, int rows_per_seg, int seg_stride, int seg_base)
{
    extern __shared__ __align__(128) char smem[];
    const uint32_t sb = smem_to_u32(smem);
    const int tid = threadIdx.x;
    const int bn = blockIdx.x * 128;
    const int bm = blockIdx.y * 128;
    const int wid = tid >> 5, lane = tid & 31;
    const int Wm = (wid & 3) * 32;
    const int Wn = (wid >> 2) * 64;

    const int lrow = tid >> 1;
    const int lc = tid & 1;
    int m = bm + lrow; if (m > M - 1) m = M - 1;
    const int seg = m / rows_per_seg;
    const int t = m - seg * rows_per_seg;
    const size_t aoff = (size_t)(seg * seg_stride + seg_base + t) * 1024 + lc * 16;
    const size_t boff = (size_t)(bn + lrow) * 1024 + lc * 16;
    const uint32_t soff = (uint32_t)lrow * 80u + (uint32_t)lc * 32u;

    float acc[2][8][4];
#pragma unroll
    for (int i = 0; i < 2; i++)
#pragma unroll
        for (int j = 0; j < 8; j++)
#pragma unroll
            for (int c = 0; c < 4; c++) acc[i][j][c] = 0.f;

    const uint32_t a_frag_row = (uint32_t)(Wm + (lane & 15)) * 80u + ((lane >> 4) * 16u);
    const uint32_t b_frag_row =
        (uint32_t)(Wn + (lane & 7) + ((lane >> 4) << 3)) * 80u + (((lane >> 3) & 1) * 16u);

#define ISSUE(p, k0)                                                       \
    {                                                                      \
        uint32_t d = sb + (p) * BUF_BYTES + soff;                          \
        const __half* s;                                                   \
        s = Ahi + aoff + (k0); CPA16(d,           s); CPA16(d + 16,         s + 8); \
        if (TERMS == 2) {                                                  \
            s = Alo + aoff + (k0); CPA16(d + 10240, s); CPA16(d + 10240 + 16, s + 8); \
        }                                                                  \
        s = Bhi + boff + (k0); CPA16(d + 20480,   s); CPA16(d + 20480 + 16, s + 8); \
    }

    ISSUE(0, 0);
    CPA_COMMIT();
    ISSUE(1, 32);
    CPA_COMMIT();

    int stage = 0;
    for (int i = 0; i < 32; i++) {
        if (i < 31) { CPA_WAIT(1); } else { CPA_WAIT(0); }
        __syncthreads();
        if (i + 2 < 32) {
            int ns = stage + 2; if (ns >= 3) ns -= 3;
            ISSUE(ns, (i + 2) * 32);
            CPA_COMMIT();
        }

        const uint32_t base = sb + stage * BUF_BYTES;
#pragma unroll
        for (int kk = 0; kk < 2; kk++) {
            uint32_t ah[2][4], al[2][4], bh[4][4];
            const uint32_t ar = base + a_frag_row + kk * 32;
            LDMX4(ah[0][0], ah[0][1], ah[0][2], ah[0][3], ar);
            LDMX4(ah[1][0], ah[1][1], ah[1][2], ah[1][3], ar + 16 * 80);
            if (TERMS == 2) {
                LDMX4(al[0][0], al[0][1], al[0][2], al[0][3], ar + 10240);
                LDMX4(al[1][0], al[1][1], al[1][2], al[1][3], ar + 10240 + 16 * 80);
            }
#pragma unroll
            for (int j = 0; j < 4; j++) {
                const uint32_t br = base + 20480 + b_frag_row + kk * 32
                                    + (uint32_t)j * (16 * 80);
                LDMX4(bh[j][0], bh[j][1], bh[j][2], bh[j][3], br);
            }
#pragma unroll
            for (int j = 0; j < 4; j++)
#pragma unroll
                for (int mt = 0; mt < 2; mt++) {
                    MMA16816(acc[mt][2 * j],     ah[mt], bh[j][0], bh[j][1]);
                    MMA16816(acc[mt][2 * j + 1], ah[mt], bh[j][2], bh[j][3]);
                }
            if (TERMS == 2) {
#pragma unroll
                for (int j = 0; j < 4; j++)
#pragma unroll
                    for (int mt = 0; mt < 2; mt++) {
                        MMA16816(acc[mt][2 * j],     al[mt], bh[j][0], bh[j][1]);
                        MMA16816(acc[mt][2 * j + 1], al[mt], bh[j][2], bh[j][3]);
                    }
            }
        }
        stage++; if (stage >= 3) stage = 0;
    }
#undef ISSUE

    const int er = lane >> 2, ec = (lane & 3) * 2;
#pragma unroll
    for (int mt = 0; mt < 2; mt++) {
#pragma unroll
        for (int hrow = 0; hrow < 2; hrow++) {
            const int cm = bm + Wm + mt * 16 + er + hrow * 8;
            if (cm >= M) continue;
            if (MODE == 1) {
                const int segc = cm / rows_per_seg;
                const int tc = cm - segc * rows_per_seg;
#pragma unroll
                for (int nt = 0; nt < 8; nt++) {
                    const int cn = bn + Wn + nt * 8 + ec;
                    const int hh = cn >> 6, dd = cn & 63;
                    size_t oi = (((size_t)segc * H_ + hh) * rows_per_seg + tc) * 64 + dd;
                    *(uint32_t*)(Chi + oi) =
                        packh(acc[mt][nt][hrow * 2], acc[mt][nt][hrow * 2 + 1]);
                }
            } else if (MODE == 2) {
#pragma unroll
                for (int nt = 0; nt < 8; nt++) {
                    const int cn = bn + Wn + nt * 8 + ec;
                    size_t oi = (size_t)cm * DM_ + cn;
                    float v0 = acc[mt][nt][hrow * 2] * 0.125f;
                    float v1 = acc[mt][nt][hrow * 2 + 1] * 0.125f;
                    float h0 = __half2float(__float2half(v0));
                    float h1 = __half2float(__float2half(v1));
                    *(uint32_t*)(Chi + oi) = packh(h0, h1);
                    *(uint32_t*)(Clo + oi) = packh(v0 - h0, v1 - h1);
                }
            } else {
                float* Cp = C + (size_t)cm * DM_ + bn + Wn + ec;
                const float* bp = bias + bn + Wn + ec;
#pragma unroll
                for (int nt = 0; nt < 8; nt++) {
                    float2 v = make_float2(acc[mt][nt][hrow * 2] + bp[nt * 8],
                                           acc[mt][nt][hrow * 2 + 1] + bp[nt * 8 + 1]);
                    *(float2*)(Cp + nt * 8) = v;
                }
            }
        }
    }
}

// ---------------------------------------------------------------------------
// Tensor-core flash attention, 2-term, image-first merged accumulator.
// One CTA = (b, h, 128-query tile). smem ~131 KB.
// ---------------------------------------------------------------------------
#define AT_KHI 0
#define AT_VHI 48384
#define AT_QHI 96768
#define AT_QLO 115200
#define AT_PS  96768
#define AT_RKH 115200
#define AT_RKL 120960
#define AT_SMEM 133632

__device__ __forceinline__ int bidx(int j, int i)
{
    int d = j - i;
    d = max(-16, min(16, d));
    return d + 16;
}

__device__ __forceinline__ void wsplit(const float* s0, const float* s1,
                                       uint32_t* ahi, uint32_t* alo)
{
    float v[8] = {s0[0], s0[1], s0[2], s0[3], s1[0], s1[1], s1[2], s1[3]};
    float hv[8];
#pragma unroll
    for (int i = 0; i < 8; i++)
        hv[i] = __half2float(__float2half(v[i]));
    ahi[0] = packh(hv[0], hv[1]); ahi[1] = packh(hv[2], hv[3]);
    ahi[2] = packh(hv[4], hv[5]); ahi[3] = packh(hv[6], hv[7]);
    alo[0] = packh(v[0] - hv[0], v[1] - hv[1]);
    alo[1] = packh(v[2] - hv[2], v[3] - hv[3]);
    alo[2] = packh(v[4] - hv[4], v[5] - hv[5]);
    alo[3] = packh(v[6] - hv[6], v[7] - hv[7]);
}

__global__ void __launch_bounds__(256, 1)
attn_mma(const __half* __restrict__ qhi, const __half* __restrict__ qlo,
         const __half* __restrict__ kt, const __half* __restrict__ vt,
         const __half* __restrict__ ki, const __half* __restrict__ vi,
         const float* __restrict__ relk, const float* __restrict__ relv,
         __half* __restrict__ atthi, __half* __restrict__ attlo)
{
    extern __shared__ __align__(128) char sm[];
    const uint32_t sb = smem_to_u32(sm);
    const int tid = threadIdx.x, w = tid >> 5, lane = tid & 31;
    const int bh = blockIdx.x >> 3, qt = blockIdx.x & 7;
    const int b = bh >> 4, h = bh & 15;
    const int i0 = qt * 128;
    const unsigned FULL = 0xffffffffu;

    // ---- stage K/V (hi only) + Q (hi/lo) ----
    {
        size_t tb = (size_t)bh * (LT_ * 64);
        for (int idx = tid; idx < LT_ * 8; idx += 256) {
            int r = idx >> 3, c = idx & 7;
            uint32_t d = (uint32_t)r * 144 + c * 16;
            size_t s = tb + (size_t)r * 64 + c * 8;
            CPA16(sb + AT_KHI + d, kt + s);
            CPA16(sb + AT_VHI + d, vt + s);
        }
        size_t ib = (size_t)bh * (LI_ * 64);
        for (int idx = tid; idx < LI_ * 8; idx += 256) {
            int r = idx >> 3, c = idx & 7;
            uint32_t d = (uint32_t)(80 + r) * 144 + c * 16;
            size_t s = ib + (size_t)r * 64 + c * 8;
            CPA16(sb + AT_KHI + d, ki + s);
            CPA16(sb + AT_VHI + d, vi + s);
        }
        size_t qb = ((size_t)(b * NQ_ + i0)) * 1024 + h * 64;
        for (int idx = tid; idx < 128 * 8; idx += 256) {
            int r = idx >> 3, c = idx & 7;
            uint32_t d = (uint32_t)r * 144 + c * 16;
            size_t s = qb + (size_t)r * 1024 + c * 8;
            CPA16(sb + AT_QHI + d, qhi + s);
            CPA16(sb + AT_QLO + d, qlo + s);
        }
        for (int idx = tid; idx < 3 * 36; idx += 256) {
            uint32_t d = (uint32_t)(77 + idx / 36) * 144 + (idx % 36) * 4;
            *(uint32_t*)(sm + AT_KHI + d) = 0;
            *(uint32_t*)(sm + AT_VHI + d) = 0;
        }
        CPA_COMMIT();
        CPA_WAIT(0);
        __syncthreads();
    }

    const int wr = w * 16;
    const int r0l = wr + (lane >> 2);

    // ---- Q fragments ----
    uint32_t qh[4][4], ql[4][4];
    {
        int row = wr + (lane & 15);
        int kb = (lane >> 4) * 16;
#pragma unroll
        for (int kk = 0; kk < 4; kk++) {
            uint32_t a = sb + AT_QHI + (uint32_t)row * 144 + kk * 32 + kb;
            LDMX4(qh[kk][0], qh[kk][1], qh[kk][2], qh[kk][3], a);
            LDMX4(ql[kk][0], ql[kk][1], ql[kk][2], ql[kk][3], a + (AT_QLO - AT_QHI));
        }
    }
    __syncthreads();

    // ---- stage relk hi/lo (tile 0; published by the post-image sync) ----
    if (qt == 0) {
        for (int idx = tid; idx < NR_ * 64; idx += 256) {
            int r = idx >> 6, dc = idx & 63;
            float v = relk[idx];
            float hh = __half2float(__float2half(v));
            *(__half*)(sm + AT_RKH + r * 144 + dc * 2) = __float2half(hh);
            *(__half*)(sm + AT_RKL + r * 144 + dc * 2) = __float2half(v - hh);
        }
    }

    const int brow = ((lane >> 4) << 3) + (lane & 7);
    const int bdb = (lane & 8) * 2;
    const int vrow = (lane & 8) + (lane & 7);
    const int vdb = (lane >> 4) * 16;

    // ================= image branch first (merged accumulator) =============
    float o[8][4];
#pragma unroll
    for (int i = 0; i < 8; i++)
#pragma unroll
        for (int c = 0; c < 4; c++) o[i][c] = 0.f;
    float mi0 = -1e30f, mi1 = -1e30f, li0 = 0.f, li1 = 0.f;
#pragma unroll 1
    for (int ch = 0; ch < 8; ch++) {
        const int j0 = 80 + ch * 32;
        float sc[4][4];
#pragma unroll
        for (int i = 0; i < 4; i++)
#pragma unroll
            for (int c = 0; c < 4; c++) sc[i][c] = 0.f;
#pragma unroll
        for (int kk = 0; kk < 4; kk++) {
#pragma unroll
            for (int p2 = 0; p2 < 2; p2++) {
                uint32_t kh4[4];
                uint32_t ad = sb + AT_KHI + (uint32_t)(j0 + p2 * 16 + brow) * 144
                              + kk * 32 + bdb;
                LDMX4(kh4[0], kh4[1], kh4[2], kh4[3], ad);
                MMA16816(sc[2 * p2], qh[kk], kh4[0], kh4[1]);
                MMA16816(sc[2 * p2], ql[kk], kh4[0], kh4[1]);
                MMA16816(sc[2 * p2 + 1], qh[kk], kh4[2], kh4[3]);
                MMA16816(sc[2 * p2 + 1], ql[kk], kh4[2], kh4[3]);
            }
        }
        float cm0 = -1e30f, cm1 = -1e30f;
#pragma unroll
        for (int t = 0; t < 4; t++) {
            cm0 = fmaxf(cm0, fmaxf(sc[t][0], sc[t][1]));
            cm1 = fmaxf(cm1, fmaxf(sc[t][2], sc[t][3]));
        }
        cm0 = fmaxf(cm0, __shfl_xor_sync(FULL, cm0, 1));
        cm0 = fmaxf(cm0, __shfl_xor_sync(FULL, cm0, 2));
        cm1 = fmaxf(cm1, __shfl_xor_sync(FULL, cm1, 1));
        cm1 = fmaxf(cm1, __shfl_xor_sync(FULL, cm1, 2));
        float mn0 = fmaxf(mi0, cm0), mn1 = fmaxf(mi1, cm1);
        float al0 = __expf(mi0 - mn0), al1 = __expf(mi1 - mn1);
        float cs0 = 0.f, cs1 = 0.f;
#pragma unroll
        for (int t = 0; t < 4; t++) {
            sc[t][0] = __expf(sc[t][0] - mn0); cs0 += sc[t][0];
            sc[t][1] = __expf(sc[t][1] - mn0); cs0 += sc[t][1];
            sc[t][2] = __expf(sc[t][2] - mn1); cs1 += sc[t][2];
            sc[t][3] = __expf(sc[t][3] - mn1); cs1 += sc[t][3];
        }
        cs0 += __shfl_xor_sync(FULL, cs0, 1); cs0 += __shfl_xor_sync(FULL, cs0, 2);
        cs1 += __shfl_xor_sync(FULL, cs1, 1); cs1 += __shfl_xor_sync(FULL, cs1, 2);
        li0 = li0 * al0 + cs0; li1 = li1 * al1 + cs1;
        mi0 = mn0; mi1 = mn1;
#pragma unroll
        for (int dt = 0; dt < 8; dt++) {
            o[dt][0] *= al0; o[dt][1] *= al0;
            o[dt][2] *= al1; o[dt][3] *= al1;
        }
#pragma unroll
        for (int wk = 0; wk < 2; wk++) {
            uint32_t ahi[4], alo[4];
            wsplit(sc[2 * wk], sc[2 * wk + 1], ahi, alo);
#pragma unroll
            for (int dp = 0; dp < 4; dp++) {
                uint32_t vh4[4];
                uint32_t ad = sb + AT_VHI + (uint32_t)(j0 + wk * 16 + vrow) * 144
                              + dp * 32 + vdb;
                LDMX4T(vh4[0], vh4[1], vh4[2], vh4[3], ad);
                MMA16816(o[2 * dp], ahi, vh4[0], vh4[1]);
                MMA16816(o[2 * dp], alo, vh4[0], vh4[1]);
                MMA16816(o[2 * dp + 1], ahi, vh4[2], vh4[3]);
                MMA16816(o[2 * dp + 1], alo, vh4[2], vh4[3]);
            }
        }
    }
    {
        float ii0 = 1.f / li0, ii1 = 1.f / li1;
#pragma unroll
        for (int dt = 0; dt < 8; dt++) {
            o[dt][0] *= ii0; o[dt][1] *= ii0;
            o[dt][2] *= ii1; o[dt][3] *= ii1;
        }
    }

    __syncthreads();

    float* pS = (float*)(sm + AT_PS);

    // ---- rel-K projections (tile 0; 3-term kept) ----
    if (qt == 0) {
        float pr[5][4];
#pragma unroll
        for (int i = 0; i < 5; i++)
#pragma unroll
            for (int c = 0; c < 4; c++) pr[i][c] = 0.f;
#pragma unroll
        for (int kk = 0; kk < 4; kk++) {
#pragma unroll
            for (int p2 = 0; p2 < 3; p2++) {
                uint32_t bh4[4], bl4[4];
                uint32_t ad = sb + AT_RKH + (uint32_t)(p2 * 16 + brow) * 144
                              + kk * 32 + bdb;
                LDMX4(bh4[0], bh4[1], bh4[2], bh4[3], ad);
                LDMX4(bl4[0], bl4[1], bl4[2], bl4[3], ad + (AT_RKL - AT_RKH));
                MMA16816(pr[2 * p2], qh[kk], bh4[0], bh4[1]);
                MMA16816(pr[2 * p2], ql[kk], bh4[0], bh4[1]);
                MMA16816(pr[2 * p2], qh[kk], bl4[0], bl4[1]);
                if (p2 < 2) {
                    MMA16816(pr[2 * p2 + 1], qh[kk], bh4[2], bh4[3]);
                    MMA16816(pr[2 * p2 + 1], ql[kk], bh4[2], bh4[3]);
                    MMA16816(pr[2 * p2 + 1], qh[kk], bl4[2], bl4[3]);
                }
            }
        }
#pragma unroll
        for (int nt = 0; nt < 5; nt++) {
            int c0 = nt * 8 + 2 * (lane & 3);
            if (c0 < NR_) {
                pS[r0l * 34 + c0] = pr[nt][0];
                pS[(r0l + 8) * 34 + c0] = pr[nt][2];
            }
            if (c0 + 1 < NR_) {
                pS[r0l * 34 + c0 + 1] = pr[nt][1];
                pS[(r0l + 8) * 34 + c0 + 1] = pr[nt][3];
            }
        }
        __syncwarp();
    }

    // ---- text scores (2-term) ----
    float s[10][4];
#pragma unroll
    for (int i = 0; i < 10; i++)
#pragma unroll
        for (int c = 0; c < 4; c++) s[i][c] = 0.f;
#pragma unroll
    for (int kk = 0; kk < 4; kk++) {
#pragma unroll
        for (int p2 = 0; p2 < 5; p2++) {
            uint32_t kh4[4];
            uint32_t ad = sb + AT_KHI + (uint32_t)(p2 * 16 + brow) * 144
                          + kk * 32 + bdb;
            LDMX4(kh4[0], kh4[1], kh4[2], kh4[3], ad);
            MMA16816(s[2 * p2], qh[kk], kh4[0], kh4[1]);
            MMA16816(s[2 * p2], ql[kk], kh4[0], kh4[1]);
            MMA16816(s[2 * p2 + 1], qh[kk], kh4[2], kh4[3]);
            MMA16816(s[2 * p2 + 1], ql[kk], kh4[2], kh4[3]);
        }
    }

#pragma unroll
    for (int nt = 0; nt < 10; nt++) {
        int c0 = nt * 8 + 2 * (lane & 3);
        if (qt == 0) {
            s[nt][0] += pS[r0l * 34 + bidx(c0, r0l)];
            s[nt][1] += pS[r0l * 34 + bidx(c0 + 1, r0l)];
            s[nt][2] += pS[(r0l + 8) * 34 + bidx(c0, r0l + 8)];
            s[nt][3] += pS[(r0l + 8) * 34 + bidx(c0 + 1, r0l + 8)];
        }
        if (c0 >= LT_) { s[nt][0] = -1e30f; s[nt][2] = -1e30f; }
        if (c0 + 1 >= LT_) { s[nt][1] = -1e30f; s[nt][3] = -1e30f; }
    }

    float m0 = -1e30f, m1 = -1e30f;
#pragma unroll
    for (int nt = 0; nt < 10; nt++) {
        m0 = fmaxf(m0, fmaxf(s[nt][0], s[nt][1]));
        m1 = fmaxf(m1, fmaxf(s[nt][2], s[nt][3]));
    }
    m0 = fmaxf(m0, __shfl_xor_sync(FULL, m0, 1));
    m0 = fmaxf(m0, __shfl_xor_sync(FULL, m0, 2));
    m1 = fmaxf(m1, __shfl_xor_sync(FULL, m1, 1));
    m1 = fmaxf(m1, __shfl_xor_sync(FULL, m1, 2));
    float l0 = 0.f, l1 = 0.f;
#pragma unroll
    for (int nt = 0; nt < 10; nt++) {
        s[nt][0] = __expf(s[nt][0] - m0); l0 += s[nt][0];
        s[nt][1] = __expf(s[nt][1] - m0); l0 += s[nt][1];
        s[nt][2] = __expf(s[nt][2] - m1); l1 += s[nt][2];
        s[nt][3] = __expf(s[nt][3] - m1); l1 += s[nt][3];
    }
    l0 += __shfl_xor_sync(FULL, l0, 1); l0 += __shfl_xor_sync(FULL, l0, 2);
    l1 += __shfl_xor_sync(FULL, l1, 1); l1 += __shfl_xor_sync(FULL, l1, 2);
    float inv0 = 1.f / l0, inv1 = 1.f / l1;
#pragma unroll
    for (int nt = 0; nt < 10; nt++) {
        s[nt][0] *= inv0; s[nt][1] *= inv0;
        s[nt][2] *= inv1; s[nt][3] *= inv1;
    }

    if (qt == 0) {
        for (int idx = lane; idx < 16 * 34; idx += 32)
            pS[(wr + idx / 34) * 34 + idx % 34] = 0.f;
        __syncwarp();
#pragma unroll
        for (int nt = 0; nt < 10; nt++) {
            int c0 = nt * 8 + 2 * (lane & 3);
            if (c0 < LT_) {
                atomicAdd(&pS[r0l * 34 + bidx(c0, r0l)], s[nt][0]);
                atomicAdd(&pS[(r0l + 8) * 34 + bidx(c0, r0l + 8)], s[nt][2]);
            }
            if (c0 + 1 < LT_) {
                atomicAdd(&pS[r0l * 34 + bidx(c0 + 1, r0l)], s[nt][1]);
                atomicAdd(&pS[(r0l + 8) * 34 + bidx(c0 + 1, r0l + 8)], s[nt][3]);
            }
        }
        __syncwarp();
    }

    // ---- O += W @ V_text (2-term) ----
#pragma unroll
    for (int wk = 0; wk < 5; wk++) {
        uint32_t ahi[4], alo[4];
        wsplit(s[2 * wk], s[2 * wk + 1], ahi, alo);
#pragma unroll
        for (int dp = 0; dp < 4; dp++) {
            uint32_t vh4[4];
            uint32_t ad = sb + AT_VHI + (uint32_t)(wk * 16 + vrow) * 144
                          + dp * 32 + vdb;
            LDMX4T(vh4[0], vh4[1], vh4[2], vh4[3], ad);
            MMA16816(o[2 * dp], ahi, vh4[0], vh4[1]);
            MMA16816(o[2 * dp], alo, vh4[0], vh4[1]);
            MMA16816(o[2 * dp + 1], ahi, vh4[2], vh4[3]);
            MMA16816(o[2 * dp + 1], alo, vh4[2], vh4[3]);
        }
    }

    // ---- rel-V contribution ----
    if (qt == 0) {
#pragma unroll 1
        for (int r = 0; r < NR_; r++) {
            float w0 = pS[r0l * 34 + r];
            float w1 = pS[(r0l + 8) * 34 + r];
            const float* rv = relv + r * 64 + 2 * (lane & 3);
#pragma unroll
            for (int dt = 0; dt < 8; dt++) {
                float rv0 = rv[dt * 8], rv1 = rv[dt * 8 + 1];
                o[dt][0] += w0 * rv0; o[dt][1] += w0 * rv1;
                o[dt][2] += w1 * rv0; o[dt][3] += w1 * rv1;
            }
        }
    } else {
        const float* rv = relv + 2 * (lane & 3);
#pragma unroll
        for (int dt = 0; dt < 8; dt++) {
            float rv0 = rv[dt * 8], rv1 = rv[dt * 8 + 1];
            o[dt][0] += rv0; o[dt][1] += rv1;
            o[dt][2] += rv0; o[dt][3] += rv1;
        }
    }

    // ---- store fp16 hi/lo ----
    {
        size_t ob = ((size_t)(b * NQ_ + i0 + r0l)) * 1024 + h * 64 + 2 * (lane & 3);
#pragma unroll
        for (int dt = 0; dt < 8; dt++) {
            float v0 = o[dt][0];
            float v1 = o[dt][1];
            float v2 = o[dt][2];
            float v3 = o[dt][3];
            float h0 = __half2float(__float2half(v0));
            float h1 = __half2float(__float2half(v1));
            float h2 = __half2float(__float2half(v2));
            float h3 = __half2float(__float2half(v3));
            size_t o0 = ob + dt * 8;
            size_t o1 = o0 + 8 * 1024;
            *(uint32_t*)(atthi + o0) = packh(h0, h1);
            *(uint32_t*)(attlo + o0) = packh(v0 - h0, v1 - h1);
            *(uint32_t*)(atthi + o1) = packh(h2, h3);
            *(uint32_t*)(attlo + o1) = packh(v2 - h2, v3 - h3);
        }
    }
}

// ---------------------------------------------------------------------------
// Host launcher
// ---------------------------------------------------------------------------
extern "C" void kernel_launch(void* const* d_in, const int* in_sizes, int n_in,
                              void* d_out, int out_size)
{
    const float* x     = (const float*)d_in[0];
    const float* ctx   = (const float*)d_in[1];
    const float* Wq    = (const float*)d_in[2];
    const float* Wk    = (const float*)d_in[3];
    const float* Wv    = (const float*)d_in[4];
    const float* Wk_ip = (const float*)d_in[5];
    const float* Wv_ip = (const float*)d_in[6];
    const float* Wout  = (const float*)d_in[7];
    const float* bout  = (const float*)d_in[8];
    const float* relk  = (const float*)d_in[9];
    const float* relv  = (const float*)d_in[10];
    float* out = (float*)d_out;

    __half *pahi, *palo, *pqhi, *pqlo, *pchi, *pclo, *pwhi, *pwlo;
    __half *pkt, *pvt, *pki, *pvi;
    cudaGetSymbolAddress((void**)&pahi, g_ahi);
    cudaGetSymbolAddress((void**)&palo, g_alo);
    cudaGetSymbolAddress((void**)&pqhi, g_qhi);
    cudaGetSymbolAddress((void**)&pqlo, g_qlo);
    cudaGetSymbolAddress((void**)&pchi, g_chi);
    cudaGetSymbolAddress((void**)&pclo, g_clo);
    cudaGetSymbolAddress((void**)&pwhi, g_whi);
    cudaGetSymbolAddress((void**)&pwlo, g_wlo);
    cudaGetSymbolAddress((void**)&pkt, g_kt);
    cudaGetSymbolAddress((void**)&pvt, g_vt);
    cudaGetSymbolAddress((void**)&pki, g_ki);
    cudaGetSymbolAddress((void**)&pvi, g_vi);

    cudaFuncSetAttribute(gemm_mma<0, 2>,
                         cudaFuncAttributeMaxDynamicSharedMemorySize, GM_SMEM);
    cudaFuncSetAttribute(gemm_mma<1, 1>,
                         cudaFuncAttributeMaxDynamicSharedMemorySize, GM_SMEM);
    cudaFuncSetAttribute(gemm_mma<2, 1>,
                         cudaFuncAttributeMaxDynamicSharedMemorySize, GM_SMEM);
    cudaFuncSetAttribute(attn_mma,
                         cudaFuncAttributeMaxDynamicSharedMemorySize, AT_SMEM);

    const size_t WSZ = (size_t)DM_ * DM_;
    size_t nx = (size_t)B_ * NQ_ * DM_;
    size_t nc = (size_t)B_ * CTXR * DM_;

    conv_wt<<<dim3(32, 32), dim3(32, 8)>>>(Wq, pwhi + 0 * WSZ, pwlo + 0 * WSZ);
    conv_rows<<<(unsigned)(nx / 4 / 256), 256>>>(x, pahi, nullptr, nx);
    conv_rows<<<(unsigned)((nc / 4 + 255) / 256), 256>>>(ctx, pchi, nullptr, nc);
    conv_wt<<<dim3(32, 32), dim3(32, 8)>>>(Wk, pwhi + 1 * WSZ, pwlo + 1 * WSZ);
    conv_wt<<<dim3(32, 32), dim3(32, 8)>>>(Wv, pwhi + 2 * WSZ, pwlo + 2 * WSZ);

    // Q = (x_hi @ Wq_hi) * 0.125 -> fp16 hi/lo   (1-term)
    gemm_mma<2, 1><<<dim3(8, 512), 256, GM_SMEM>>>(
        pahi, nullptr, pwhi + 0 * WSZ, nullptr, nullptr,
        pqhi, pqlo, B_ * NQ_, B_ * NQ_, B_ * NQ_, 0);

    conv_wt<<<dim3(32, 32), dim3(32, 8)>>>(Wk_ip, pwhi + 3 * WSZ, pwlo + 3 * WSZ);
    conv_wt<<<dim3(32, 32), dim3(32, 8)>>>(Wv_ip, pwhi + 4 * WSZ, pwlo + 4 * WSZ);
    conv_wt<<<dim3(32, 32), dim3(32, 8)>>>(Wout,  pwhi + 5 * WSZ, pwlo + 5 * WSZ);

    // K/V text -> [b][h][t][d] fp16 hi only   (1-term)
    gemm_mma<1, 1><<<dim3(8, 39), 256, GM_SMEM>>>(
        pchi, nullptr, pwhi + 1 * WSZ, nullptr, nullptr,
        pkt, nullptr, B_ * LT_, LT_, CTXR, 0);
    gemm_mma<1, 1><<<dim3(8, 39), 256, GM_SMEM>>>(
        pchi, nullptr, pwhi + 2 * WSZ, nullptr, nullptr,
        pvt, nullptr, B_ * LT_, LT_, CTXR, 0);

    // K/V image   (1-term)
    gemm_mma<1, 1><<<dim3(8, 128), 256, GM_SMEM>>>(
        pchi, nullptr, pwhi + 3 * WSZ, nullptr, nullptr,
        pki, nullptr, B_ * LI_, LI_, CTXR, LT_);
    gemm_mma<1, 1><<<dim3(8, 128), 256, GM_SMEM>>>(
        pchi, nullptr, pwhi + 4 * WSZ, nullptr, nullptr,
        pvi, nullptr, B_ * LI_, LI_, CTXR, LT_);

    // tensor-core attention (2-term, image-first) -> fp16 hi/lo
    attn_mma<<<B_ * H_ * 8, 256, AT_SMEM>>>(
        pqhi, pqlo, pkt, pvt, pki, pvi, relk, relv, pahi, palo);

    // final projection + bias   (2-term kept)
    gemm_mma<0, 2><<<dim3(8, 512), 256, GM_SMEM>>>(
        pahi, palo, pwhi + 5 * WSZ, out, bout,
        nullptr, nullptr, B_ * NQ_, B_ * NQ_, B_ * NQ_, 0);
}

// round 14
// speedup vs baseline: 2.1814x; 1.1951x over previous
#include <cuda_runtime.h>
#include <cuda_fp16.h>
#include <cstdint>

// ---------------------------------------------------------------------------
// Problem constants
// ---------------------------------------------------------------------------
#define B_    64
#define NQ_   1024
#define DM_   1024
#define H_    16
#define D_    64
#define LT_   77
#define LI_   256
#define NR_   33
#define CTXR  (LT_ + LI_)     // 333

__device__ __forceinline__ uint32_t smem_to_u32(const void* p) {
    uint32_t a;
    asm("{ .reg .u64 t; cvta.to.shared.u64 t, %1; cvt.u32.u64 %0, t; }"
        : "=r"(a) : "l"(p));
    return a;
}

#define CPA16(dst, src) \
    asm volatile("cp.async.cg.shared.global [%0], [%1], 16;" \
                 :: "r"(dst), "l"(src))
#define CPA_COMMIT() asm volatile("cp.async.commit_group;" ::: "memory")
#define CPA_WAIT(n)  asm volatile("cp.async.wait_group %0;" :: "n"(n) : "memory")

#define LDMX4(r0, r1, r2, r3, addr) \
    asm volatile("ldmatrix.sync.aligned.m8n8.x4.shared.b16 {%0,%1,%2,%3}, [%4];" \
                 : "=r"(r0), "=r"(r1), "=r"(r2), "=r"(r3) : "r"(addr))
#define LDMX4T(r0, r1, r2, r3, addr) \
    asm volatile("ldmatrix.sync.aligned.m8n8.x4.trans.shared.b16 {%0,%1,%2,%3}, [%4];" \
                 : "=r"(r0), "=r"(r1), "=r"(r2), "=r"(r3) : "r"(addr))

#define MMA16816(c, a, b0, b1) \
    asm volatile("mma.sync.aligned.m16n8k16.row.col.f32.f16.f16.f32 " \
                 "{%0,%1,%2,%3}, {%4,%5,%6,%7}, {%8,%9}, {%0,%1,%2,%3};" \
                 : "+f"((c)[0]), "+f"((c)[1]), "+f"((c)[2]), "+f"((c)[3]) \
                 : "r"((a)[0]), "r"((a)[1]), "r"((a)[2]), "r"((a)[3]), \
                   "r"(b0), "r"(b1))

__device__ __forceinline__ uint32_t packh(float lo, float hi) {
    uint32_t d;
    asm("cvt.rn.f16x2.f32 %0, %1, %2;" : "=r"(d) : "f"(hi), "f"(lo));
    return d;
}

// ---------------------------------------------------------------------------
// Scratch (static device globals)
// ---------------------------------------------------------------------------
__device__ __half g_ahi[(size_t)B_ * NQ_ * DM_];  // x hi, later att (fp16)
__device__ __half g_qhi[(size_t)B_ * NQ_ * DM_];
__device__ __half g_qlo[(size_t)B_ * NQ_ * DM_];
__device__ __half g_chi[(size_t)B_ * CTXR * DM_];
__device__ __half g_whi[6 * (size_t)DM_ * DM_];
__device__ __half g_wlo[6 * (size_t)DM_ * DM_];
__device__ __half g_kt[(size_t)B_ * H_ * LT_ * D_];   // hi only
__device__ __half g_vt[(size_t)B_ * H_ * LT_ * D_];
__device__ __half g_ki[(size_t)B_ * H_ * LI_ * D_];
__device__ __half g_vi[(size_t)B_ * H_ * LI_ * D_];

// ---------------------------------------------------------------------------
// fp32 -> fp16 (hi only when lo == nullptr)
// ---------------------------------------------------------------------------
__global__ void conv_rows(const float* __restrict__ src,
                          __half* __restrict__ hi,
                          __half* __restrict__ lo, size_t n)
{
    size_t i = ((size_t)blockIdx.x * blockDim.x + threadIdx.x) * 4;
    if (i >= n) return;
    float4 v = *(const float4*)(src + i);
    float h0 = __half2float(__float2half(v.x));
    float h1 = __half2float(__float2half(v.y));
    float h2 = __half2float(__float2half(v.z));
    float h3 = __half2float(__float2half(v.w));
    *(uint2*)(hi + i) = make_uint2(packh(h0, h1), packh(h2, h3));
    if (lo)
        *(uint2*)(lo + i) = make_uint2(packh(v.x - h0, v.y - h1),
                                       packh(v.z - h2, v.w - h3));
}

// W [K=1024, N=1024] -> Wt hi/lo [N, K]
__global__ void conv_wt(const float* __restrict__ W,
                        __half* __restrict__ hi,
                        __half* __restrict__ lo)
{
    __shared__ float tile[32][33];
    const int k0 = blockIdx.y * 32, n0 = blockIdx.x * 32;
    const int tx = threadIdx.x;
    for (int r = threadIdx.y; r < 32; r += 8)
        tile[r][tx] = W[(size_t)(k0 + r) * DM_ + n0 + tx];
    __syncthreads();
    for (int r = threadIdx.y; r < 32; r += 8) {
        float v = tile[tx][r];
        float h = __half2float(__float2half(v));
        size_t oi = (size_t)(n0 + r) * DM_ + k0 + tx;
        hi[oi] = __float2half(h);
        if (lo) lo[oi] = __float2half(v - h);
    }
}

// ---------------------------------------------------------------------------
// fp16 split GEMM via mma.sync: C = remap(A) @ B^T.
// TERMS 2: AhiBhi + AloBhi.  TERMS 1: AhiBhi only.
// MODE 0: fp32 C + bias.  MODE 1: KV scatter fp16 hi only.  MODE 2: Q *0.125
// hi/lo.  CTA 128x128, BK=32, 3-stage cp.async pipeline, 2 CTAs/SM.
// ---------------------------------------------------------------------------
#define BUF_BYTES   30720
#define GM_SMEM     (3 * BUF_BYTES)   // 92160

template <int MODE, int TERMS>
__global__ void __launch_bounds__(256, 2)
gemm_mma(const __half* __restrict__ Ahi, const __half* __restrict__ Alo,
         const __half* __restrict__ Bhi,
         float* __restrict__ C, const float* __restrict__ bias,
         __half* __restrict__ Chi, __half* __restrict__ Clo,
         int M, int rows_per_seg, int seg_stride, int seg_base)
{
    extern __shared__ __align__(128) char smem[];
    const uint32_t sb = smem_to_u32(smem);
    const int tid = threadIdx.x;
    const int bn = blockIdx.x * 128;
    const int bm = blockIdx.y * 128;
    const int wid = tid >> 5, lane = tid & 31;
    const int Wm = (wid & 3) * 32;
    const int Wn = (wid >> 2) * 64;

    const int lrow = tid >> 1;
    const int lc = tid & 1;
    int m = bm + lrow; if (m > M - 1) m = M - 1;
    const int seg = m / rows_per_seg;
    const int t = m - seg * rows_per_seg;
    const size_t aoff = (size_t)(seg * seg_stride + seg_base + t) * 1024 + lc * 16;
    const size_t boff = (size_t)(bn + lrow) * 1024 + lc * 16;
    const uint32_t soff = (uint32_t)lrow * 80u + (uint32_t)lc * 32u;

    float acc[2][8][4];
#pragma unroll
    for (int i = 0; i < 2; i++)
#pragma unroll
        for (int j = 0; j < 8; j++)
#pragma unroll
            for (int c = 0; c < 4; c++) acc[i][j][c] = 0.f;

    const uint32_t a_frag_row = (uint32_t)(Wm + (lane & 15)) * 80u + ((lane >> 4) * 16u);
    const uint32_t b_frag_row =
        (uint32_t)(Wn + (lane & 7) + ((lane >> 4) << 3)) * 80u + (((lane >> 3) & 1) * 16u);

#define ISSUE(p, k0)                                                       \
    {                                                                      \
        uint32_t d = sb + (p) * BUF_BYTES + soff;                          \
        const __half* s;                                                   \
        s = Ahi + aoff + (k0); CPA16(d,           s); CPA16(d + 16,         s + 8); \
        if (TERMS == 2) {                                                  \
            s = Alo + aoff + (k0); CPA16(d + 10240, s); CPA16(d + 10240 + 16, s + 8); \
        }                                                                  \
        s = Bhi + boff + (k0); CPA16(d + 20480,   s); CPA16(d + 20480 + 16, s + 8); \
    }

    ISSUE(0, 0);
    CPA_COMMIT();
    ISSUE(1, 32);
    CPA_COMMIT();

    int stage = 0;
    for (int i = 0; i < 32; i++) {
        if (i < 31) { CPA_WAIT(1); } else { CPA_WAIT(0); }
        __syncthreads();
        if (i + 2 < 32) {
            int ns = stage + 2; if (ns >= 3) ns -= 3;
            ISSUE(ns, (i + 2) * 32);
            CPA_COMMIT();
        }

        const uint32_t base = sb + stage * BUF_BYTES;
#pragma unroll
        for (int kk = 0; kk < 2; kk++) {
            uint32_t ah[2][4], al[2][4], bh[4][4];
            const uint32_t ar = base + a_frag_row + kk * 32;
            LDMX4(ah[0][0], ah[0][1], ah[0][2], ah[0][3], ar);
            LDMX4(ah[1][0], ah[1][1], ah[1][2], ah[1][3], ar + 16 * 80);
            if (TERMS == 2) {
                LDMX4(al[0][0], al[0][1], al[0][2], al[0][3], ar + 10240);
                LDMX4(al[1][0], al[1][1], al[1][2], al[1][3], ar + 10240 + 16 * 80);
            }
#pragma unroll
            for (int j = 0; j < 4; j++) {
                const uint32_t br = base + 20480 + b_frag_row + kk * 32
                                    + (uint32_t)j * (16 * 80);
                LDMX4(bh[j][0], bh[j][1], bh[j][2], bh[j][3], br);
            }
#pragma unroll
            for (int j = 0; j < 4; j++)
#pragma unroll
                for (int mt = 0; mt < 2; mt++) {
                    MMA16816(acc[mt][2 * j],     ah[mt], bh[j][0], bh[j][1]);
                    MMA16816(acc[mt][2 * j + 1], ah[mt], bh[j][2], bh[j][3]);
                }
            if (TERMS == 2) {
#pragma unroll
                for (int j = 0; j < 4; j++)
#pragma unroll
                    for (int mt = 0; mt < 2; mt++) {
                        MMA16816(acc[mt][2 * j],     al[mt], bh[j][0], bh[j][1]);
                        MMA16816(acc[mt][2 * j + 1], al[mt], bh[j][2], bh[j][3]);
                    }
            }
        }
        stage++; if (stage >= 3) stage = 0;
    }
#undef ISSUE

    const int er = lane >> 2, ec = (lane & 3) * 2;
#pragma unroll
    for (int mt = 0; mt < 2; mt++) {
#pragma unroll
        for (int hrow = 0; hrow < 2; hrow++) {
            const int cm = bm + Wm + mt * 16 + er + hrow * 8;
            if (cm >= M) continue;
            if (MODE == 1) {
                const int segc = cm / rows_per_seg;
                const int tc = cm - segc * rows_per_seg;
#pragma unroll
                for (int nt = 0; nt < 8; nt++) {
                    const int cn = bn + Wn + nt * 8 + ec;
                    const int hh = cn >> 6, dd = cn & 63;
                    size_t oi = (((size_t)segc * H_ + hh) * rows_per_seg + tc) * 64 + dd;
                    *(uint32_t*)(Chi + oi) =
                        packh(acc[mt][nt][hrow * 2], acc[mt][nt][hrow * 2 + 1]);
                }
            } else if (MODE == 2) {
#pragma unroll
                for (int nt = 0; nt < 8; nt++) {
                    const int cn = bn + Wn + nt * 8 + ec;
                    size_t oi = (size_t)cm * DM_ + cn;
                    float v0 = acc[mt][nt][hrow * 2] * 0.125f;
                    float v1 = acc[mt][nt][hrow * 2 + 1] * 0.125f;
                    float h0 = __half2float(__float2half(v0));
                    float h1 = __half2float(__float2half(v1));
                    *(uint32_t*)(Chi + oi) = packh(h0, h1);
                    *(uint32_t*)(Clo + oi) = packh(v0 - h0, v1 - h1);
                }
            } else {
                float* Cp = C + (size_t)cm * DM_ + bn + Wn + ec;
                const float* bp = bias + bn + Wn + ec;
#pragma unroll
                for (int nt = 0; nt < 8; nt++) {
                    float2 v = make_float2(acc[mt][nt][hrow * 2] + bp[nt * 8],
                                           acc[mt][nt][hrow * 2 + 1] + bp[nt * 8 + 1]);
                    *(float2*)(Cp + nt * 8) = v;
                }
            }
        }
    }
}

// ---------------------------------------------------------------------------
// Tensor-core flash attention: QK 2-term, W@V 1-term (fp16 weights),
// image-first merged accumulator, fp16 output (no lo plane).
// One CTA = (b, h, 128-query tile). smem ~131 KB.
// ---------------------------------------------------------------------------
#define AT_KHI 0
#define AT_VHI 48384
#define AT_QHI 96768
#define AT_QLO 115200
#define AT_PS  96768
#define AT_RKH 115200
#define AT_RKL 120960
#define AT_SMEM 133632

__device__ __forceinline__ int bidx(int j, int i)
{
    int d = j - i;
    d = max(-16, min(16, d));
    return d + 16;
}

__global__ void __launch_bounds__(256, 1)
attn_mma(const __half* __restrict__ qhi, const __half* __restrict__ qlo,
         const __half* __restrict__ kt, const __half* __restrict__ vt,
         const __half* __restrict__ ki, const __half* __restrict__ vi,
         const float* __restrict__ relk, const float* __restrict__ relv,
         __half* __restrict__ atthi)
{
    extern __shared__ __align__(128) char sm[];
    const uint32_t sb = smem_to_u32(sm);
    const int tid = threadIdx.x, w = tid >> 5, lane = tid & 31;
    const int bh = blockIdx.x >> 3, qt = blockIdx.x & 7;
    const int b = bh >> 4, h = bh & 15;
    const int i0 = qt * 128;
    const unsigned FULL = 0xffffffffu;

    // ---- stage K/V (hi only) + Q (hi/lo) ----
    {
        size_t tb = (size_t)bh * (LT_ * 64);
        for (int idx = tid; idx < LT_ * 8; idx += 256) {
            int r = idx >> 3, c = idx & 7;
            uint32_t d = (uint32_t)r * 144 + c * 16;
            size_t s = tb + (size_t)r * 64 + c * 8;
            CPA16(sb + AT_KHI + d, kt + s);
            CPA16(sb + AT_VHI + d, vt + s);
        }
        size_t ib = (size_t)bh * (LI_ * 64);
        for (int idx = tid; idx < LI_ * 8; idx += 256) {
            int r = idx >> 3, c = idx & 7;
            uint32_t d = (uint32_t)(80 + r) * 144 + c * 16;
            size_t s = ib + (size_t)r * 64 + c * 8;
            CPA16(sb + AT_KHI + d, ki + s);
            CPA16(sb + AT_VHI + d, vi + s);
        }
        size_t qb = ((size_t)(b * NQ_ + i0)) * 1024 + h * 64;
        for (int idx = tid; idx < 128 * 8; idx += 256) {
            int r = idx >> 3, c = idx & 7;
            uint32_t d = (uint32_t)r * 144 + c * 16;
            size_t s = qb + (size_t)r * 1024 + c * 8;
            CPA16(sb + AT_QHI + d, qhi + s);
            CPA16(sb + AT_QLO + d, qlo + s);
        }
        for (int idx = tid; idx < 3 * 36; idx += 256) {
            uint32_t d = (uint32_t)(77 + idx / 36) * 144 + (idx % 36) * 4;
            *(uint32_t*)(sm + AT_KHI + d) = 0;
            *(uint32_t*)(sm + AT_VHI + d) = 0;
        }
        CPA_COMMIT();
        CPA_WAIT(0);
        __syncthreads();
    }

    const int wr = w * 16;
    const int r0l = wr + (lane >> 2);

    // ---- Q fragments ----
    uint32_t qh[4][4], ql[4][4];
    {
        int row = wr + (lane & 15);
        int kb = (lane >> 4) * 16;
#pragma unroll
        for (int kk = 0; kk < 4; kk++) {
            uint32_t a = sb + AT_QHI + (uint32_t)row * 144 + kk * 32 + kb;
            LDMX4(qh[kk][0], qh[kk][1], qh[kk][2], qh[kk][3], a);
            LDMX4(ql[kk][0], ql[kk][1], ql[kk][2], ql[kk][3], a + (AT_QLO - AT_QHI));
        }
    }
    __syncthreads();

    // ---- stage relk hi/lo (tile 0; published by the post-image sync) ----
    if (qt == 0) {
        for (int idx = tid; idx < NR_ * 64; idx += 256) {
            int r = idx >> 6, dc = idx & 63;
            float v = relk[idx];
            float hh = __half2float(__float2half(v));
            *(__half*)(sm + AT_RKH + r * 144 + dc * 2) = __float2half(hh);
            *(__half*)(sm + AT_RKL + r * 144 + dc * 2) = __float2half(v - hh);
        }
    }

    const int brow = ((lane >> 4) << 3) + (lane & 7);
    const int bdb = (lane & 8) * 2;
    const int vrow = (lane & 8) + (lane & 7);
    const int vdb = (lane >> 4) * 16;

    // ================= image branch first (merged accumulator) =============
    float o[8][4];
#pragma unroll
    for (int i = 0; i < 8; i++)
#pragma unroll
        for (int c = 0; c < 4; c++) o[i][c] = 0.f;
    float mi0 = -1e30f, mi1 = -1e30f, li0 = 0.f, li1 = 0.f;
#pragma unroll 1
    for (int ch = 0; ch < 8; ch++) {
        const int j0 = 80 + ch * 32;
        float sc[4][4];
#pragma unroll
        for (int i = 0; i < 4; i++)
#pragma unroll
            for (int c = 0; c < 4; c++) sc[i][c] = 0.f;
#pragma unroll
        for (int kk = 0; kk < 4; kk++) {
#pragma unroll
            for (int p2 = 0; p2 < 2; p2++) {
                uint32_t kh4[4];
                uint32_t ad = sb + AT_KHI + (uint32_t)(j0 + p2 * 16 + brow) * 144
                              + kk * 32 + bdb;
                LDMX4(kh4[0], kh4[1], kh4[2], kh4[3], ad);
                MMA16816(sc[2 * p2], qh[kk], kh4[0], kh4[1]);
                MMA16816(sc[2 * p2], ql[kk], kh4[0], kh4[1]);
                MMA16816(sc[2 * p2 + 1], qh[kk], kh4[2], kh4[3]);
                MMA16816(sc[2 * p2 + 1], ql[kk], kh4[2], kh4[3]);
            }
        }
        float cm0 = -1e30f, cm1 = -1e30f;
#pragma unroll
        for (int t = 0; t < 4; t++) {
            cm0 = fmaxf(cm0, fmaxf(sc[t][0], sc[t][1]));
            cm1 = fmaxf(cm1, fmaxf(sc[t][2], sc[t][3]));
        }
        cm0 = fmaxf(cm0, __shfl_xor_sync(FULL, cm0, 1));
        cm0 = fmaxf(cm0, __shfl_xor_sync(FULL, cm0, 2));
        cm1 = fmaxf(cm1, __shfl_xor_sync(FULL, cm1, 1));
        cm1 = fmaxf(cm1, __shfl_xor_sync(FULL, cm1, 2));
        float mn0 = fmaxf(mi0, cm0), mn1 = fmaxf(mi1, cm1);
        float al0 = __expf(mi0 - mn0), al1 = __expf(mi1 - mn1);
        float cs0 = 0.f, cs1 = 0.f;
#pragma unroll
        for (int t = 0; t < 4; t++) {
            sc[t][0] = __expf(sc[t][0] - mn0); cs0 += sc[t][0];
            sc[t][1] = __expf(sc[t][1] - mn0); cs0 += sc[t][1];
            sc[t][2] = __expf(sc[t][2] - mn1); cs1 += sc[t][2];
            sc[t][3] = __expf(sc[t][3] - mn1); cs1 += sc[t][3];
        }
        cs0 += __shfl_xor_sync(FULL, cs0, 1); cs0 += __shfl_xor_sync(FULL, cs0, 2);
        cs1 += __shfl_xor_sync(FULL, cs1, 1); cs1 += __shfl_xor_sync(FULL, cs1, 2);
        li0 = li0 * al0 + cs0; li1 = li1 * al1 + cs1;
        mi0 = mn0; mi1 = mn1;
#pragma unroll
        for (int dt = 0; dt < 8; dt++) {
            o[dt][0] *= al0; o[dt][1] *= al0;
            o[dt][2] *= al1; o[dt][3] *= al1;
        }
#pragma unroll
        for (int wk = 0; wk < 2; wk++) {
            uint32_t ahi[4];
            const float* s0 = sc[2 * wk];
            const float* s1 = sc[2 * wk + 1];
            ahi[0] = packh(s0[0], s0[1]); ahi[1] = packh(s0[2], s0[3]);
            ahi[2] = packh(s1[0], s1[1]); ahi[3] = packh(s1[2], s1[3]);
#pragma unroll
            for (int dp = 0; dp < 4; dp++) {
                uint32_t vh4[4];
                uint32_t ad = sb + AT_VHI + (uint32_t)(j0 + wk * 16 + vrow) * 144
                              + dp * 32 + vdb;
                LDMX4T(vh4[0], vh4[1], vh4[2], vh4[3], ad);
                MMA16816(o[2 * dp], ahi, vh4[0], vh4[1]);
                MMA16816(o[2 * dp + 1], ahi, vh4[2], vh4[3]);
            }
        }
    }
    {
        float ii0 = 1.f / li0, ii1 = 1.f / li1;
#pragma unroll
        for (int dt = 0; dt < 8; dt++) {
            o[dt][0] *= ii0; o[dt][1] *= ii0;
            o[dt][2] *= ii1; o[dt][3] *= ii1;
        }
    }

    __syncthreads();

    float* pS = (float*)(sm + AT_PS);

    // ---- rel-K projections (tile 0; 3-term kept) ----
    if (qt == 0) {
        float pr[5][4];
#pragma unroll
        for (int i = 0; i < 5; i++)
#pragma unroll
            for (int c = 0; c < 4; c++) pr[i][c] = 0.f;
#pragma unroll
        for (int kk = 0; kk < 4; kk++) {
#pragma unroll
            for (int p2 = 0; p2 < 3; p2++) {
                uint32_t bh4[4], bl4[4];
                uint32_t ad = sb + AT_RKH + (uint32_t)(p2 * 16 + brow) * 144
                              + kk * 32 + bdb;
                LDMX4(bh4[0], bh4[1], bh4[2], bh4[3], ad);
                LDMX4(bl4[0], bl4[1], bl4[2], bl4[3], ad + (AT_RKL - AT_RKH));
                MMA16816(pr[2 * p2], qh[kk], bh4[0], bh4[1]);
                MMA16816(pr[2 * p2], ql[kk], bh4[0], bh4[1]);
                MMA16816(pr[2 * p2], qh[kk], bl4[0], bl4[1]);
                if (p2 < 2) {
                    MMA16816(pr[2 * p2 + 1], qh[kk], bh4[2], bh4[3]);
                    MMA16816(pr[2 * p2 + 1], ql[kk], bh4[2], bh4[3]);
                    MMA16816(pr[2 * p2 + 1], qh[kk], bl4[2], bl4[3]);
                }
            }
        }
#pragma unroll
        for (int nt = 0; nt < 5; nt++) {
            int c0 = nt * 8 + 2 * (lane & 3);
            if (c0 < NR_) {
                pS[r0l * 34 + c0] = pr[nt][0];
                pS[(r0l + 8) * 34 + c0] = pr[nt][2];
            }
            if (c0 + 1 < NR_) {
                pS[r0l * 34 + c0 + 1] = pr[nt][1];
                pS[(r0l + 8) * 34 + c0 + 1] = pr[nt][3];
            }
        }
        __syncwarp();
    }

    // ---- text scores (2-term) ----
    float s[10][4];
#pragma unroll
    for (int i = 0; i < 10; i++)
#pragma unroll
        for (int c = 0; c < 4; c++) s[i][c] = 0.f;
#pragma unroll
    for (int kk = 0; kk < 4; kk++) {
#pragma unroll
        for (int p2 = 0; p2 < 5; p2++) {
            uint32_t kh4[4];
            uint32_t ad = sb + AT_KHI + (uint32_t)(p2 * 16 + brow) * 144
                          + kk * 32 + bdb;
            LDMX4(kh4[0], kh4[1], kh4[2], kh4[3], ad);
            MMA16816(s[2 * p2], qh[kk], kh4[0], kh4[1]);
            MMA16816(s[2 * p2], ql[kk], kh4[0], kh4[1]);
            MMA16816(s[2 * p2 + 1], qh[kk], kh4[2], kh4[3]);
            MMA16816(s[2 * p2 + 1], ql[kk], kh4[2], kh4[3]);
        }
    }

#pragma unroll
    for (int nt = 0; nt < 10; nt++) {
        int c0 = nt * 8 + 2 * (lane & 3);
        if (qt == 0) {
            s[nt][0] += pS[r0l * 34 + bidx(c0, r0l)];
            s[nt][1] += pS[r0l * 34 + bidx(c0 + 1, r0l)];
            s[nt][2] += pS[(r0l + 8) * 34 + bidx(c0, r0l + 8)];
            s[nt][3] += pS[(r0l + 8) * 34 + bidx(c0 + 1, r0l + 8)];
        }
        if (c0 >= LT_) { s[nt][0] = -1e30f; s[nt][2] = -1e30f; }
        if (c0 + 1 >= LT_) { s[nt][1] = -1e30f; s[nt][3] = -1e30f; }
    }

    float m0 = -1e30f, m1 = -1e30f;
#pragma unroll
    for (int nt = 0; nt < 10; nt++) {
        m0 = fmaxf(m0, fmaxf(s[nt][0], s[nt][1]));
        m1 = fmaxf(m1, fmaxf(s[nt][2], s[nt][3]));
    }
    m0 = fmaxf(m0, __shfl_xor_sync(FULL, m0, 1));
    m0 = fmaxf(m0, __shfl_xor_sync(FULL, m0, 2));
    m1 = fmaxf(m1, __shfl_xor_sync(FULL, m1, 1));
    m1 = fmaxf(m1, __shfl_xor_sync(FULL, m1, 2));
    float l0 = 0.f, l1 = 0.f;
#pragma unroll
    for (int nt = 0; nt < 10; nt++) {
        s[nt][0] = __expf(s[nt][0] - m0); l0 += s[nt][0];
        s[nt][1] = __expf(s[nt][1] - m0); l0 += s[nt][1];
        s[nt][2] = __expf(s[nt][2] - m1); l1 += s[nt][2];
        s[nt][3] = __expf(s[nt][3] - m1); l1 += s[nt][3];
    }
    l0 += __shfl_xor_sync(FULL, l0, 1); l0 += __shfl_xor_sync(FULL, l0, 2);
    l1 += __shfl_xor_sync(FULL, l1, 1); l1 += __shfl_xor_sync(FULL, l1, 2);
    float inv0 = 1.f / l0, inv1 = 1.f / l1;
#pragma unroll
    for (int nt = 0; nt < 10; nt++) {
        s[nt][0] *= inv0; s[nt][1] *= inv0;
        s[nt][2] *= inv1; s[nt][3] *= inv1;
    }

    if (qt == 0) {
        for (int idx = lane; idx < 16 * 34; idx += 32)
            pS[(wr + idx / 34) * 34 + idx % 34] = 0.f;
        __syncwarp();
#pragma unroll
        for (int nt = 0; nt < 10; nt++) {
            int c0 = nt * 8 + 2 * (lane & 3);
            if (c0 < LT_) {
                atomicAdd(&pS[r0l * 34 + bidx(c0, r0l)], s[nt][0]);
                atomicAdd(&pS[(r0l + 8) * 34 + bidx(c0, r0l + 8)], s[nt][2]);
            }
            if (c0 + 1 < LT_) {
                atomicAdd(&pS[r0l * 34 + bidx(c0 + 1, r0l)], s[nt][1]);
                atomicAdd(&pS[(r0l + 8) * 34 + bidx(c0 + 1, r0l + 8)], s[nt][3]);
            }
        }
        __syncwarp();
    }

    // ---- O += W @ V_text (1-term, fp16 weights) ----
#pragma unroll
    for (int wk = 0; wk < 5; wk++) {
        uint32_t ahi[4];
        const float* s0 = s[2 * wk];
        const float* s1 = s[2 * wk + 1];
        ahi[0] = packh(s0[0], s0[1]); ahi[1] = packh(s0[2], s0[3]);
        ahi[2] = packh(s1[0], s1[1]); ahi[3] = packh(s1[2], s1[3]);
#pragma unroll
        for (int dp = 0; dp < 4; dp++) {
            uint32_t vh4[4];
            uint32_t ad = sb + AT_VHI + (uint32_t)(wk * 16 + vrow) * 144
                          + dp * 32 + vdb;
            LDMX4T(vh4[0], vh4[1], vh4[2], vh4[3], ad);
            MMA16816(o[2 * dp], ahi, vh4[0], vh4[1]);
            MMA16816(o[2 * dp + 1], ahi, vh4[2], vh4[3]);
        }
    }

    // ---- rel-V contribution ----
    if (qt == 0) {
#pragma unroll 1
        for (int r = 0; r < NR_; r++) {
            float w0 = pS[r0l * 34 + r];
            float w1 = pS[(r0l + 8) * 34 + r];
            const float* rv = relv + r * 64 + 2 * (lane & 3);
#pragma unroll
            for (int dt = 0; dt < 8; dt++) {
                float rv0 = rv[dt * 8], rv1 = rv[dt * 8 + 1];
                o[dt][0] += w0 * rv0; o[dt][1] += w0 * rv1;
                o[dt][2] += w1 * rv0; o[dt][3] += w1 * rv1;
            }
        }
    } else {
        const float* rv = relv + 2 * (lane & 3);
#pragma unroll
        for (int dt = 0; dt < 8; dt++) {
            float rv0 = rv[dt * 8], rv1 = rv[dt * 8 + 1];
            o[dt][0] += rv0; o[dt][1] += rv1;
            o[dt][2] += rv0; o[dt][3] += rv1;
        }
    }

    // ---- store fp16 (hi only) ----
    {
        size_t ob = ((size_t)(b * NQ_ + i0 + r0l)) * 1024 + h * 64 + 2 * (lane & 3);
#pragma unroll
        for (int dt = 0; dt < 8; dt++) {
            size_t o0 = ob + dt * 8;
            size_t o1 = o0 + 8 * 1024;
            *(uint32_t*)(atthi + o0) = packh(o[dt][0], o[dt][1]);
            *(uint32_t*)(atthi + o1) = packh(o[dt][2], o[dt][3]);
        }
    }
}

// ---------------------------------------------------------------------------
// Host launcher
// ---------------------------------------------------------------------------
extern "C" void kernel_launch(void* const* d_in, const int* in_sizes, int n_in,
                              void* d_out, int out_size)
{
    const float* x     = (const float*)d_in[0];
    const float* ctx   = (const float*)d_in[1];
    const float* Wq    = (const float*)d_in[2];
    const float* Wk    = (const float*)d_in[3];
    const float* Wv    = (const float*)d_in[4];
    const float* Wk_ip = (const float*)d_in[5];
    const float* Wv_ip = (const float*)d_in[6];
    const float* Wout  = (const float*)d_in[7];
    const float* bout  = (const float*)d_in[8];
    const float* relk  = (const float*)d_in[9];
    const float* relv  = (const float*)d_in[10];
    float* out = (float*)d_out;

    __half *pahi, *pqhi, *pqlo, *pchi, *pwhi, *pwlo;
    __half *pkt, *pvt, *pki, *pvi;
    cudaGetSymbolAddress((void**)&pahi, g_ahi);
    cudaGetSymbolAddress((void**)&pqhi, g_qhi);
    cudaGetSymbolAddress((void**)&pqlo, g_qlo);
    cudaGetSymbolAddress((void**)&pchi, g_chi);
    cudaGetSymbolAddress((void**)&pwhi, g_whi);
    cudaGetSymbolAddress((void**)&pwlo, g_wlo);
    cudaGetSymbolAddress((void**)&pkt, g_kt);
    cudaGetSymbolAddress((void**)&pvt, g_vt);
    cudaGetSymbolAddress((void**)&pki, g_ki);
    cudaGetSymbolAddress((void**)&pvi, g_vi);

    cudaFuncSetAttribute(gemm_mma<0, 1>,
                         cudaFuncAttributeMaxDynamicSharedMemorySize, GM_SMEM);
    cudaFuncSetAttribute(gemm_mma<1, 1>,
                         cudaFuncAttributeMaxDynamicSharedMemorySize, GM_SMEM);
    cudaFuncSetAttribute(gemm_mma<2, 1>,
                         cudaFuncAttributeMaxDynamicSharedMemorySize, GM_SMEM);
    cudaFuncSetAttribute(attn_mma,
                         cudaFuncAttributeMaxDynamicSharedMemorySize, AT_SMEM);

    const size_t WSZ = (size_t)DM_ * DM_;
    size_t nx = (size_t)B_ * NQ_ * DM_;
    size_t nc = (size_t)B_ * CTXR * DM_;

    conv_wt<<<dim3(32, 32), dim3(32, 8)>>>(Wq, pwhi + 0 * WSZ, pwlo + 0 * WSZ);
    conv_rows<<<(unsigned)(nx / 4 / 256), 256>>>(x, pahi, nullptr, nx);
    conv_rows<<<(unsigned)((nc / 4 + 255) / 256), 256>>>(ctx, pchi, nullptr, nc);
    conv_wt<<<dim3(32, 32), dim3(32, 8)>>>(Wk, pwhi + 1 * WSZ, pwlo + 1 * WSZ);
    conv_wt<<<dim3(32, 32), dim3(32, 8)>>>(Wv, pwhi + 2 * WSZ, pwlo + 2 * WSZ);

    // Q = (x_hi @ Wq_hi) * 0.125 -> fp16 hi/lo   (1-term)
    gemm_mma<2, 1><<<dim3(8, 512), 256, GM_SMEM>>>(
        pahi, nullptr, pwhi + 0 * WSZ, nullptr, nullptr,
        pqhi, pqlo, B_ * NQ_, B_ * NQ_, B_ * NQ_, 0);

    conv_wt<<<dim3(32, 32), dim3(32, 8)>>>(Wk_ip, pwhi + 3 * WSZ, pwlo + 3 * WSZ);
    conv_wt<<<dim3(32, 32), dim3(32, 8)>>>(Wv_ip, pwhi + 4 * WSZ, pwlo + 4 * WSZ);
    conv_wt<<<dim3(32, 32), dim3(32, 8)>>>(Wout,  pwhi + 5 * WSZ, pwlo + 5 * WSZ);

    // K/V text -> [b][h][t][d] fp16 hi only   (1-term)
    gemm_mma<1, 1><<<dim3(8, 39), 256, GM_SMEM>>>(
        pchi, nullptr, pwhi + 1 * WSZ, nullptr, nullptr,
        pkt, nullptr, B_ * LT_, LT_, CTXR, 0);
    gemm_mma<1, 1><<<dim3(8, 39), 256, GM_SMEM>>>(
        pchi, nullptr, pwhi + 2 * WSZ, nullptr, nullptr,
        pvt, nullptr, B_ * LT_, LT_, CTXR, 0);

    // K/V image   (1-term)
    gemm_mma<1, 1><<<dim3(8, 128), 256, GM_SMEM>>>(
        pchi, nullptr, pwhi + 3 * WSZ, nullptr, nullptr,
        pki, nullptr, B_ * LI_, LI_, CTXR, LT_);
    gemm_mma<1, 1><<<dim3(8, 128), 256, GM_SMEM>>>(
        pchi, nullptr, pwhi + 4 * WSZ, nullptr, nullptr,
        pvi, nullptr, B_ * LI_, LI_, CTXR, LT_);

    // tensor-core attention -> fp16 into final-GEMM input
    attn_mma<<<B_ * H_ * 8, 256, AT_SMEM>>>(
        pqhi, pqlo, pkt, pvt, pki, pvi, relk, relv, pahi);

    // final projection + bias   (1-term)
    gemm_mma<0, 1><<<dim3(8, 512), 256, GM_SMEM>>>(
        pahi, nullptr, pwhi + 5 * WSZ, out, bout,
        nullptr, nullptr, B_ * NQ_, B_ * NQ_, B_ * NQ_, 0);
}

// round 15
// speedup vs baseline: 2.4647x; 1.1299x over previous
#include <cuda_runtime.h>
#include <cuda_fp16.h>
#include <cstdint>

// ---------------------------------------------------------------------------
// Problem constants
// ---------------------------------------------------------------------------
#define B_    64
#define NQ_   1024
#define DM_   1024
#define H_    16
#define D_    64
#define LT_   77
#define LI_   256
#define NR_   33
#define CTXR  (LT_ + LI_)     // 333

__device__ __forceinline__ uint32_t smem_to_u32(const void* p) {
    uint32_t a;
    asm("{ .reg .u64 t; cvta.to.shared.u64 t, %1; cvt.u32.u64 %0, t; }"
        : "=r"(a) : "l"(p));
    return a;
}

#define CPA16(dst, src) \
    asm volatile("cp.async.cg.shared.global [%0], [%1], 16;" \
                 :: "r"(dst), "l"(src))
#define CPA_COMMIT() asm volatile("cp.async.commit_group;" ::: "memory")
#define CPA_WAIT(n)  asm volatile("cp.async.wait_group %0;" :: "n"(n) : "memory")

#define LDMX4(r0, r1, r2, r3, addr) \
    asm volatile("ldmatrix.sync.aligned.m8n8.x4.shared.b16 {%0,%1,%2,%3}, [%4];" \
                 : "=r"(r0), "=r"(r1), "=r"(r2), "=r"(r3) : "r"(addr))
#define LDMX4T(r0, r1, r2, r3, addr) \
    asm volatile("ldmatrix.sync.aligned.m8n8.x4.trans.shared.b16 {%0,%1,%2,%3}, [%4];" \
                 : "=r"(r0), "=r"(r1), "=r"(r2), "=r"(r3) : "r"(addr))

#define MMA16816(c, a, b0, b1) \
    asm volatile("mma.sync.aligned.m16n8k16.row.col.f32.f16.f16.f32 " \
                 "{%0,%1,%2,%3}, {%4,%5,%6,%7}, {%8,%9}, {%0,%1,%2,%3};" \
                 : "+f"((c)[0]), "+f"((c)[1]), "+f"((c)[2]), "+f"((c)[3]) \
                 : "r"((a)[0]), "r"((a)[1]), "r"((a)[2]), "r"((a)[3]), \
                   "r"(b0), "r"(b1))

__device__ __forceinline__ uint32_t packh(float lo, float hi) {
    uint32_t d;
    asm("cvt.rn.f16x2.f32 %0, %1, %2;" : "=r"(d) : "f"(hi), "f"(lo));
    return d;
}

// ---------------------------------------------------------------------------
// Scratch (static device globals)
// ---------------------------------------------------------------------------
__device__ __half g_ahi[(size_t)B_ * NQ_ * DM_];  // x hi, later att (fp16)
__device__ __half g_qhi[(size_t)B_ * NQ_ * DM_];
__device__ __half g_chi[(size_t)B_ * CTXR * DM_];
__device__ __half g_whi[6 * (size_t)DM_ * DM_];
__device__ __half g_wlo[6 * (size_t)DM_ * DM_];
__device__ __half g_kt[(size_t)B_ * H_ * LT_ * D_];   // hi only
__device__ __half g_vt[(size_t)B_ * H_ * LT_ * D_];
__device__ __half g_ki[(size_t)B_ * H_ * LI_ * D_];
__device__ __half g_vi[(size_t)B_ * H_ * LI_ * D_];

// ---------------------------------------------------------------------------
// fp32 -> fp16 (hi only when lo == nullptr)
// ---------------------------------------------------------------------------
__global__ void conv_rows(const float* __restrict__ src,
                          __half* __restrict__ hi,
                          __half* __restrict__ lo, size_t n)
{
    size_t i = ((size_t)blockIdx.x * blockDim.x + threadIdx.x) * 4;
    if (i >= n) return;
    float4 v = *(const float4*)(src + i);
    float h0 = __half2float(__float2half(v.x));
    float h1 = __half2float(__float2half(v.y));
    float h2 = __half2float(__float2half(v.z));
    float h3 = __half2float(__float2half(v.w));
    *(uint2*)(hi + i) = make_uint2(packh(h0, h1), packh(h2, h3));
    if (lo)
        *(uint2*)(lo + i) = make_uint2(packh(v.x - h0, v.y - h1),
                                       packh(v.z - h2, v.w - h3));
}

// W [K=1024, N=1024] -> Wt hi/lo [N, K]
__global__ void conv_wt(const float* __restrict__ W,
                        __half* __restrict__ hi,
                        __half* __restrict__ lo)
{
    __shared__ float tile[32][33];
    const int k0 = blockIdx.y * 32, n0 = blockIdx.x * 32;
    const int tx = threadIdx.x;
    for (int r = threadIdx.y; r < 32; r += 8)
        tile[r][tx] = W[(size_t)(k0 + r) * DM_ + n0 + tx];
    __syncthreads();
    for (int r = threadIdx.y; r < 32; r += 8) {
        float v = tile[tx][r];
        float h = __half2float(__float2half(v));
        size_t oi = (size_t)(n0 + r) * DM_ + k0 + tx;
        hi[oi] = __float2half(h);
        if (lo) lo[oi] = __float2half(v - h);
    }
}

// ---------------------------------------------------------------------------
// fp16 1-term GEMM via mma.sync: C = remap(A)_hi @ Bhi^T.
// MODE 0: fp32 C + bias.  MODE 1: KV scatter fp16.  MODE 2: Q *0.125 fp16.
// CTA 128x128, BK=32, 3-stage cp.async pipeline, 2 CTAs/SM.
// ---------------------------------------------------------------------------
#define BUF_BYTES   30720
#define GM_SMEM     (3 * BUF_BYTES)   // 92160

template <int MODE>
__global__ void __launch_bounds__(256, 2)
gemm_mma(const __half* __restrict__ Ahi,
         const __half* __restrict__ Bhi,
         float* __restrict__ C, const float* __restrict__ bias,
         __half* __restrict__ Chi,
         int M, int rows_per_seg, int seg_stride, int seg_base)
{
    extern __shared__ __align__(128) char smem[];
    const uint32_t sb = smem_to_u32(smem);
    const int tid = threadIdx.x;
    const int bn = blockIdx.x * 128;
    const int bm = blockIdx.y * 128;
    const int wid = tid >> 5, lane = tid & 31;
    const int Wm = (wid & 3) * 32;
    const int Wn = (wid >> 2) * 64;

    const int lrow = tid >> 1;
    const int lc = tid & 1;
    int m = bm + lrow; if (m > M - 1) m = M - 1;
    const int seg = m / rows_per_seg;
    const int t = m - seg * rows_per_seg;
    const size_t aoff = (size_t)(seg * seg_stride + seg_base + t) * 1024 + lc * 16;
    const size_t boff = (size_t)(bn + lrow) * 1024 + lc * 16;
    const uint32_t soff = (uint32_t)lrow * 80u + (uint32_t)lc * 32u;

    float acc[2][8][4];
#pragma unroll
    for (int i = 0; i < 2; i++)
#pragma unroll
        for (int j = 0; j < 8; j++)
#pragma unroll
            for (int c = 0; c < 4; c++) acc[i][j][c] = 0.f;

    const uint32_t a_frag_row = (uint32_t)(Wm + (lane & 15)) * 80u + ((lane >> 4) * 16u);
    const uint32_t b_frag_row =
        (uint32_t)(Wn + (lane & 7) + ((lane >> 4) << 3)) * 80u + (((lane >> 3) & 1) * 16u);

#define ISSUE(p, k0)                                                       \
    {                                                                      \
        uint32_t d = sb + (p) * BUF_BYTES + soff;                          \
        const __half* s;                                                   \
        s = Ahi + aoff + (k0); CPA16(d,           s); CPA16(d + 16,         s + 8); \
        s = Bhi + boff + (k0); CPA16(d + 20480,   s); CPA16(d + 20480 + 16, s + 8); \
    }

    ISSUE(0, 0);
    CPA_COMMIT();
    ISSUE(1, 32);
    CPA_COMMIT();

    int stage = 0;
    for (int i = 0; i < 32; i++) {
        if (i < 31) { CPA_WAIT(1); } else { CPA_WAIT(0); }
        __syncthreads();
        if (i + 2 < 32) {
            int ns = stage + 2; if (ns >= 3) ns -= 3;
            ISSUE(ns, (i + 2) * 32);
            CPA_COMMIT();
        }

        const uint32_t base = sb + stage * BUF_BYTES;
#pragma unroll
        for (int kk = 0; kk < 2; kk++) {
            uint32_t ah[2][4], bh[4][4];
            const uint32_t ar = base + a_frag_row + kk * 32;
            LDMX4(ah[0][0], ah[0][1], ah[0][2], ah[0][3], ar);
            LDMX4(ah[1][0], ah[1][1], ah[1][2], ah[1][3], ar + 16 * 80);
#pragma unroll
            for (int j = 0; j < 4; j++) {
                const uint32_t br = base + 20480 + b_frag_row + kk * 32
                                    + (uint32_t)j * (16 * 80);
                LDMX4(bh[j][0], bh[j][1], bh[j][2], bh[j][3], br);
            }
#pragma unroll
            for (int j = 0; j < 4; j++)
#pragma unroll
                for (int mt = 0; mt < 2; mt++) {
                    MMA16816(acc[mt][2 * j],     ah[mt], bh[j][0], bh[j][1]);
                    MMA16816(acc[mt][2 * j + 1], ah[mt], bh[j][2], bh[j][3]);
                }
        }
        stage++; if (stage >= 3) stage = 0;
    }
#undef ISSUE

    const int er = lane >> 2, ec = (lane & 3) * 2;
#pragma unroll
    for (int mt = 0; mt < 2; mt++) {
#pragma unroll
        for (int hrow = 0; hrow < 2; hrow++) {
            const int cm = bm + Wm + mt * 16 + er + hrow * 8;
            if (cm >= M) continue;
            if (MODE == 1) {
                const int segc = cm / rows_per_seg;
                const int tc = cm - segc * rows_per_seg;
#pragma unroll
                for (int nt = 0; nt < 8; nt++) {
                    const int cn = bn + Wn + nt * 8 + ec;
                    const int hh = cn >> 6, dd = cn & 63;
                    size_t oi = (((size_t)segc * H_ + hh) * rows_per_seg + tc) * 64 + dd;
                    *(uint32_t*)(Chi + oi) =
                        packh(acc[mt][nt][hrow * 2], acc[mt][nt][hrow * 2 + 1]);
                }
            } else if (MODE == 2) {
#pragma unroll
                for (int nt = 0; nt < 8; nt++) {
                    const int cn = bn + Wn + nt * 8 + ec;
                    size_t oi = (size_t)cm * DM_ + cn;
                    *(uint32_t*)(Chi + oi) =
                        packh(acc[mt][nt][hrow * 2] * 0.125f,
                              acc[mt][nt][hrow * 2 + 1] * 0.125f);
                }
            } else {
                float* Cp = C + (size_t)cm * DM_ + bn + Wn + ec;
                const float* bp = bias + bn + Wn + ec;
#pragma unroll
                for (int nt = 0; nt < 8; nt++) {
                    float2 v = make_float2(acc[mt][nt][hrow * 2] + bp[nt * 8],
                                           acc[mt][nt][hrow * 2 + 1] + bp[nt * 8 + 1]);
                    *(float2*)(Cp + nt * 8) = v;
                }
            }
        }
    }
}

// ---------------------------------------------------------------------------
// Tensor-core flash attention: QK 1-term, W@V 1-term (fp16 weights),
// image-first merged accumulator, fp16 output. 2 CTAs/SM.
// smem: K 0..48384, V 48384..96768, then overlay region 96768..113664:
//   Q staging (128B rows, freed after frag load) -> relk hi/lo -> pS[128][33]
// ---------------------------------------------------------------------------
#define AT_KHI 0
#define AT_VHI 48384
#define AT_QS  96768             /* 128 rows x 128 B = 16384 */
#define AT_RKH 96768             /* relk hi, 40 rows x 144 B region */
#define AT_RKL 102528
#define AT_PS  96768             /* fp32 [128][33] = 16896 */
#define AT_SMEM 113664

__device__ __forceinline__ int bidx(int j, int i)
{
    int d = j - i;
    d = max(-16, min(16, d));
    return d + 16;
}

__global__ void __launch_bounds__(256, 2)
attn_mma(const __half* __restrict__ qhi,
         const __half* __restrict__ kt, const __half* __restrict__ vt,
         const __half* __restrict__ ki, const __half* __restrict__ vi,
         const float* __restrict__ relk, const float* __restrict__ relv,
         __half* __restrict__ atthi)
{
    extern __shared__ __align__(128) char sm[];
    const uint32_t sb = smem_to_u32(sm);
    const int tid = threadIdx.x, w = tid >> 5, lane = tid & 31;
    const int bh = blockIdx.x >> 3, qt = blockIdx.x & 7;
    const int b = bh >> 4, h = bh & 15;
    const int i0 = qt * 128;
    const unsigned FULL = 0xffffffffu;

    // ---- stage K/V (144B rows) + Q (128B rows) ----
    {
        size_t tb = (size_t)bh * (LT_ * 64);
        for (int idx = tid; idx < LT_ * 8; idx += 256) {
            int r = idx >> 3, c = idx & 7;
            uint32_t d = (uint32_t)r * 144 + c * 16;
            size_t s = tb + (size_t)r * 64 + c * 8;
            CPA16(sb + AT_KHI + d, kt + s);
            CPA16(sb + AT_VHI + d, vt + s);
        }
        size_t ib = (size_t)bh * (LI_ * 64);
        for (int idx = tid; idx < LI_ * 8; idx += 256) {
            int r = idx >> 3, c = idx & 7;
            uint32_t d = (uint32_t)(80 + r) * 144 + c * 16;
            size_t s = ib + (size_t)r * 64 + c * 8;
            CPA16(sb + AT_KHI + d, ki + s);
            CPA16(sb + AT_VHI + d, vi + s);
        }
        size_t qb = ((size_t)(b * NQ_ + i0)) * 1024 + h * 64;
        for (int idx = tid; idx < 128 * 8; idx += 256) {
            int r = idx >> 3, c = idx & 7;
            uint32_t d = (uint32_t)r * 128 + c * 16;
            size_t s = qb + (size_t)r * 1024 + c * 8;
            CPA16(sb + AT_QS + d, qhi + s);
        }
        for (int idx = tid; idx < 3 * 36; idx += 256) {
            uint32_t d = (uint32_t)(77 + idx / 36) * 144 + (idx % 36) * 4;
            *(uint32_t*)(sm + AT_KHI + d) = 0;
            *(uint32_t*)(sm + AT_VHI + d) = 0;
        }
        CPA_COMMIT();
        CPA_WAIT(0);
        __syncthreads();
    }

    const int wr = w * 16;
    const int r0l = wr + (lane >> 2);

    // ---- Q fragments (128B-stride staging; one-time bank conflicts OK) ----
    uint32_t qh[4][4];
    {
        int row = wr + (lane & 15);
        int kb = (lane >> 4) * 16;
#pragma unroll
        for (int kk = 0; kk < 4; kk++) {
            uint32_t a = sb + AT_QS + (uint32_t)row * 128 + kk * 32 + kb;
            LDMX4(qh[kk][0], qh[kk][1], qh[kk][2], qh[kk][3], a);
        }
    }
    __syncthreads();   // Q staging region now reusable

    // ---- stage relk hi/lo into reused region (tile 0 only) ----
    if (qt == 0) {
        for (int idx = tid; idx < NR_ * 64; idx += 256) {
            int r = idx >> 6, dc = idx & 63;
            float v = relk[idx];
            float hh = __half2float(__float2half(v));
            *(__half*)(sm + AT_RKH + r * 144 + dc * 2) = __float2half(hh);
            *(__half*)(sm + AT_RKL + r * 144 + dc * 2) = __float2half(v - hh);
        }
    }

    const int brow = ((lane >> 4) << 3) + (lane & 7);
    const int bdb = (lane & 8) * 2;
    const int vrow = (lane & 8) + (lane & 7);
    const int vdb = (lane >> 4) * 16;

    // ================= image branch first (merged accumulator) =============
    float o[8][4];
#pragma unroll
    for (int i = 0; i < 8; i++)
#pragma unroll
        for (int c = 0; c < 4; c++) o[i][c] = 0.f;
    float mi0 = -1e30f, mi1 = -1e30f, li0 = 0.f, li1 = 0.f;
#pragma unroll 1
    for (int ch = 0; ch < 8; ch++) {
        const int j0 = 80 + ch * 32;
        float sc[4][4];
#pragma unroll
        for (int i = 0; i < 4; i++)
#pragma unroll
            for (int c = 0; c < 4; c++) sc[i][c] = 0.f;
#pragma unroll
        for (int kk = 0; kk < 4; kk++) {
#pragma unroll
            for (int p2 = 0; p2 < 2; p2++) {
                uint32_t kh4[4];
                uint32_t ad = sb + AT_KHI + (uint32_t)(j0 + p2 * 16 + brow) * 144
                              + kk * 32 + bdb;
                LDMX4(kh4[0], kh4[1], kh4[2], kh4[3], ad);
                MMA16816(sc[2 * p2], qh[kk], kh4[0], kh4[1]);
                MMA16816(sc[2 * p2 + 1], qh[kk], kh4[2], kh4[3]);
            }
        }
        float cm0 = -1e30f, cm1 = -1e30f;
#pragma unroll
        for (int t = 0; t < 4; t++) {
            cm0 = fmaxf(cm0, fmaxf(sc[t][0], sc[t][1]));
            cm1 = fmaxf(cm1, fmaxf(sc[t][2], sc[t][3]));
        }
        cm0 = fmaxf(cm0, __shfl_xor_sync(FULL, cm0, 1));
        cm0 = fmaxf(cm0, __shfl_xor_sync(FULL, cm0, 2));
        cm1 = fmaxf(cm1, __shfl_xor_sync(FULL, cm1, 1));
        cm1 = fmaxf(cm1, __shfl_xor_sync(FULL, cm1, 2));
        float mn0 = fmaxf(mi0, cm0), mn1 = fmaxf(mi1, cm1);
        float al0 = __expf(mi0 - mn0), al1 = __expf(mi1 - mn1);
        float cs0 = 0.f, cs1 = 0.f;
#pragma unroll
        for (int t = 0; t < 4; t++) {
            sc[t][0] = __expf(sc[t][0] - mn0); cs0 += sc[t][0];
            sc[t][1] = __expf(sc[t][1] - mn0); cs0 += sc[t][1];
            sc[t][2] = __expf(sc[t][2] - mn1); cs1 += sc[t][2];
            sc[t][3] = __expf(sc[t][3] - mn1); cs1 += sc[t][3];
        }
        cs0 += __shfl_xor_sync(FULL, cs0, 1); cs0 += __shfl_xor_sync(FULL, cs0, 2);
        cs1 += __shfl_xor_sync(FULL, cs1, 1); cs1 += __shfl_xor_sync(FULL, cs1, 2);
        li0 = li0 * al0 + cs0; li1 = li1 * al1 + cs1;
        mi0 = mn0; mi1 = mn1;
#pragma unroll
        for (int dt = 0; dt < 8; dt++) {
            o[dt][0] *= al0; o[dt][1] *= al0;
            o[dt][2] *= al1; o[dt][3] *= al1;
        }
#pragma unroll
        for (int wk = 0; wk < 2; wk++) {
            uint32_t ahi[4];
            const float* s0 = sc[2 * wk];
            const float* s1 = sc[2 * wk + 1];
            ahi[0] = packh(s0[0], s0[1]); ahi[1] = packh(s0[2], s0[3]);
            ahi[2] = packh(s1[0], s1[1]); ahi[3] = packh(s1[2], s1[3]);
#pragma unroll
            for (int dp = 0; dp < 4; dp++) {
                uint32_t vh4[4];
                uint32_t ad = sb + AT_VHI + (uint32_t)(j0 + wk * 16 + vrow) * 144
                              + dp * 32 + vdb;
                LDMX4T(vh4[0], vh4[1], vh4[2], vh4[3], ad);
                MMA16816(o[2 * dp], ahi, vh4[0], vh4[1]);
                MMA16816(o[2 * dp + 1], ahi, vh4[2], vh4[3]);
            }
        }
    }
    {
        float ii0 = 1.f / li0, ii1 = 1.f / li1;
#pragma unroll
        for (int dt = 0; dt < 8; dt++) {
            o[dt][0] *= ii0; o[dt][1] *= ii0;
            o[dt][2] *= ii1; o[dt][3] *= ii1;
        }
    }

    __syncthreads();   // relk staging visible to all warps

    float* pS = (float*)(sm + AT_PS);   // [128][33], overlays relk region

    // ---- rel-K projections (tile 0; relk hi+lo vs Q hi) ----
    if (qt == 0) {
        float pr[5][4];
#pragma unroll
        for (int i = 0; i < 5; i++)
#pragma unroll
            for (int c = 0; c < 4; c++) pr[i][c] = 0.f;
#pragma unroll
        for (int kk = 0; kk < 4; kk++) {
#pragma unroll
            for (int p2 = 0; p2 < 3; p2++) {
                uint32_t bh4[4], bl4[4];
                uint32_t ad = sb + AT_RKH + (uint32_t)(p2 * 16 + brow) * 144
                              + kk * 32 + bdb;
                LDMX4(bh4[0], bh4[1], bh4[2], bh4[3], ad);
                LDMX4(bl4[0], bl4[1], bl4[2], bl4[3], ad + (AT_RKL - AT_RKH));
                MMA16816(pr[2 * p2], qh[kk], bh4[0], bh4[1]);
                MMA16816(pr[2 * p2], qh[kk], bl4[0], bl4[1]);
                if (p2 < 2) {
                    MMA16816(pr[2 * p2 + 1], qh[kk], bh4[2], bh4[3]);
                    MMA16816(pr[2 * p2 + 1], qh[kk], bl4[2], bl4[3]);
                }
            }
        }
        // pS overlays the relk region: all warps must finish reading relk
        __syncthreads();
#pragma unroll
        for (int nt = 0; nt < 5; nt++) {
            int c0 = nt * 8 + 2 * (lane & 3);
            if (c0 < NR_) {
                pS[r0l * 33 + c0] = pr[nt][0];
                pS[(r0l + 8) * 33 + c0] = pr[nt][2];
            }
            if (c0 + 1 < NR_) {
                pS[r0l * 33 + c0 + 1] = pr[nt][1];
                pS[(r0l + 8) * 33 + c0 + 1] = pr[nt][3];
            }
        }
        __syncwarp();
    }

    // ---- text scores (1-term) ----
    float s[10][4];
#pragma unroll
    for (int i = 0; i < 10; i++)
#pragma unroll
        for (int c = 0; c < 4; c++) s[i][c] = 0.f;
#pragma unroll
    for (int kk = 0; kk < 4; kk++) {
#pragma unroll
        for (int p2 = 0; p2 < 5; p2++) {
            uint32_t kh4[4];
            uint32_t ad = sb + AT_KHI + (uint32_t)(p2 * 16 + brow) * 144
                          + kk * 32 + bdb;
            LDMX4(kh4[0], kh4[1], kh4[2], kh4[3], ad);
            MMA16816(s[2 * p2], qh[kk], kh4[0], kh4[1]);
            MMA16816(s[2 * p2 + 1], qh[kk], kh4[2], kh4[3]);
        }
    }

#pragma unroll
    for (int nt = 0; nt < 10; nt++) {
        int c0 = nt * 8 + 2 * (lane & 3);
        if (qt == 0) {
            s[nt][0] += pS[r0l * 33 + bidx(c0, r0l)];
            s[nt][1] += pS[r0l * 33 + bidx(c0 + 1, r0l)];
            s[nt][2] += pS[(r0l + 8) * 33 + bidx(c0, r0l + 8)];
            s[nt][3] += pS[(r0l + 8) * 33 + bidx(c0 + 1, r0l + 8)];
        }
        if (c0 >= LT_) { s[nt][0] = -1e30f; s[nt][2] = -1e30f; }
        if (c0 + 1 >= LT_) { s[nt][1] = -1e30f; s[nt][3] = -1e30f; }
    }

    float m0 = -1e30f, m1 = -1e30f;
#pragma unroll
    for (int nt = 0; nt < 10; nt++) {
        m0 = fmaxf(m0, fmaxf(s[nt][0], s[nt][1]));
        m1 = fmaxf(m1, fmaxf(s[nt][2], s[nt][3]));
    }
    m0 = fmaxf(m0, __shfl_xor_sync(FULL, m0, 1));
    m0 = fmaxf(m0, __shfl_xor_sync(FULL, m0, 2));
    m1 = fmaxf(m1, __shfl_xor_sync(FULL, m1, 1));
    m1 = fmaxf(m1, __shfl_xor_sync(FULL, m1, 2));
    float l0 = 0.f, l1 = 0.f;
#pragma unroll
    for (int nt = 0; nt < 10; nt++) {
        s[nt][0] = __expf(s[nt][0] - m0); l0 += s[nt][0];
        s[nt][1] = __expf(s[nt][1] - m0); l0 += s[nt][1];
        s[nt][2] = __expf(s[nt][2] - m1); l1 += s[nt][2];
        s[nt][3] = __expf(s[nt][3] - m1); l1 += s[nt][3];
    }
    l0 += __shfl_xor_sync(FULL, l0, 1); l0 += __shfl_xor_sync(FULL, l0, 2);
    l1 += __shfl_xor_sync(FULL, l1, 1); l1 += __shfl_xor_sync(FULL, l1, 2);
    float inv0 = 1.f / l0, inv1 = 1.f / l1;
#pragma unroll
    for (int nt = 0; nt < 10; nt++) {
        s[nt][0] *= inv0; s[nt][1] *= inv0;
        s[nt][2] *= inv1; s[nt][3] *= inv1;
    }

    if (qt == 0) {
        for (int idx = lane; idx < 16 * 33; idx += 32)
            pS[(wr + idx / 33) * 33 + idx % 33] = 0.f;
        __syncwarp();
#pragma unroll
        for (int nt = 0; nt < 10; nt++) {
            int c0 = nt * 8 + 2 * (lane & 3);
            if (c0 < LT_) {
                atomicAdd(&pS[r0l * 33 + bidx(c0, r0l)], s[nt][0]);
                atomicAdd(&pS[(r0l + 8) * 33 + bidx(c0, r0l + 8)], s[nt][2]);
            }
            if (c0 + 1 < LT_) {
                atomicAdd(&pS[r0l * 33 + bidx(c0 + 1, r0l)], s[nt][1]);
                atomicAdd(&pS[(r0l + 8) * 33 + bidx(c0 + 1, r0l + 8)], s[nt][3]);
            }
        }
        __syncwarp();
    }

    // ---- O += W @ V_text (1-term, fp16 weights) ----
#pragma unroll
    for (int wk = 0; wk < 5; wk++) {
        uint32_t ahi[4];
        const float* s0 = s[2 * wk];
        const float* s1 = s[2 * wk + 1];
        ahi[0] = packh(s0[0], s0[1]); ahi[1] = packh(s0[2], s0[3]);
        ahi[2] = packh(s1[0], s1[1]); ahi[3] = packh(s1[2], s1[3]);
#pragma unroll
        for (int dp = 0; dp < 4; dp++) {
            uint32_t vh4[4];
            uint32_t ad = sb + AT_VHI + (uint32_t)(wk * 16 + vrow) * 144
                          + dp * 32 + vdb;
            LDMX4T(vh4[0], vh4[1], vh4[2], vh4[3], ad);
            MMA16816(o[2 * dp], ahi, vh4[0], vh4[1]);
            MMA16816(o[2 * dp + 1], ahi, vh4[2], vh4[3]);
        }
    }

    // ---- rel-V contribution ----
    if (qt == 0) {
#pragma unroll 1
        for (int r = 0; r < NR_; r++) {
            float w0 = pS[r0l * 33 + r];
            float w1 = pS[(r0l + 8) * 33 + r];
            const float* rv = relv + r * 64 + 2 * (lane & 3);
#pragma unroll
            for (int dt = 0; dt < 8; dt++) {
                float rv0 = rv[dt * 8], rv1 = rv[dt * 8 + 1];
                o[dt][0] += w0 * rv0; o[dt][1] += w0 * rv1;
                o[dt][2] += w1 * rv0; o[dt][3] += w1 * rv1;
            }
        }
    } else {
        const float* rv = relv + 2 * (lane & 3);
#pragma unroll
        for (int dt = 0; dt < 8; dt++) {
            float rv0 = rv[dt * 8], rv1 = rv[dt * 8 + 1];
            o[dt][0] += rv0; o[dt][1] += rv1;
            o[dt][2] += rv0; o[dt][3] += rv1;
        }
    }

    // ---- store fp16 ----
    {
        size_t ob = ((size_t)(b * NQ_ + i0 + r0l)) * 1024 + h * 64 + 2 * (lane & 3);
#pragma unroll
        for (int dt = 0; dt < 8; dt++) {
            size_t o0 = ob + dt * 8;
            size_t o1 = o0 + 8 * 1024;
            *(uint32_t*)(atthi + o0) = packh(o[dt][0], o[dt][1]);
            *(uint32_t*)(atthi + o1) = packh(o[dt][2], o[dt][3]);
        }
    }
}

// ---------------------------------------------------------------------------
// Host launcher
// ---------------------------------------------------------------------------
extern "C" void kernel_launch(void* const* d_in, const int* in_sizes, int n_in,
                              void* d_out, int out_size)
{
    const float* x     = (const float*)d_in[0];
    const float* ctx   = (const float*)d_in[1];
    const float* Wq    = (const float*)d_in[2];
    const float* Wk    = (const float*)d_in[3];
    const float* Wv    = (const float*)d_in[4];
    const float* Wk_ip = (const float*)d_in[5];
    const float* Wv_ip = (const float*)d_in[6];
    const float* Wout  = (const float*)d_in[7];
    const float* bout  = (const float*)d_in[8];
    const float* relk  = (const float*)d_in[9];
    const float* relv  = (const float*)d_in[10];
    float* out = (float*)d_out;

    __half *pahi, *pqhi, *pchi, *pwhi, *pwlo;
    __half *pkt, *pvt, *pki, *pvi;
    cudaGetSymbolAddress((void**)&pahi, g_ahi);
    cudaGetSymbolAddress((void**)&pqhi, g_qhi);
    cudaGetSymbolAddress((void**)&pchi, g_chi);
    cudaGetSymbolAddress((void**)&pwhi, g_whi);
    cudaGetSymbolAddress((void**)&pwlo, g_wlo);
    cudaGetSymbolAddress((void**)&pkt, g_kt);
    cudaGetSymbolAddress((void**)&pvt, g_vt);
    cudaGetSymbolAddress((void**)&pki, g_ki);
    cudaGetSymbolAddress((void**)&pvi, g_vi);

    cudaFuncSetAttribute(gemm_mma<0>,
                         cudaFuncAttributeMaxDynamicSharedMemorySize, GM_SMEM);
    cudaFuncSetAttribute(gemm_mma<1>,
                         cudaFuncAttributeMaxDynamicSharedMemorySize, GM_SMEM);
    cudaFuncSetAttribute(gemm_mma<2>,
                         cudaFuncAttributeMaxDynamicSharedMemorySize, GM_SMEM);
    cudaFuncSetAttribute(attn_mma,
                         cudaFuncAttributeMaxDynamicSharedMemorySize, AT_SMEM);

    const size_t WSZ = (size_t)DM_ * DM_;
    size_t nx = (size_t)B_ * NQ_ * DM_;
    size_t nc = (size_t)B_ * CTXR * DM_;

    conv_wt<<<dim3(32, 32), dim3(32, 8)>>>(Wq, pwhi + 0 * WSZ, pwlo + 0 * WSZ);
    conv_rows<<<(unsigned)(nx / 4 / 256), 256>>>(x, pahi, nullptr, nx);
    conv_rows<<<(unsigned)((nc / 4 + 255) / 256), 256>>>(ctx, pchi, nullptr, nc);
    conv_wt<<<dim3(32, 32), dim3(32, 8)>>>(Wk, pwhi + 1 * WSZ, pwlo + 1 * WSZ);
    conv_wt<<<dim3(32, 32), dim3(32, 8)>>>(Wv, pwhi + 2 * WSZ, pwlo + 2 * WSZ);

    // Q = (x_hi @ Wq_hi) * 0.125 -> fp16
    gemm_mma<2><<<dim3(8, 512), 256, GM_SMEM>>>(
        pahi, pwhi + 0 * WSZ, nullptr, nullptr,
        pqhi, B_ * NQ_, B_ * NQ_, B_ * NQ_, 0);

    conv_wt<<<dim3(32, 32), dim3(32, 8)>>>(Wk_ip, pwhi + 3 * WSZ, pwlo + 3 * WSZ);
    conv_wt<<<dim3(32, 32), dim3(32, 8)>>>(Wv_ip, pwhi + 4 * WSZ, pwlo + 4 * WSZ);
    conv_wt<<<dim3(32, 32), dim3(32, 8)>>>(Wout,  pwhi + 5 * WSZ, pwlo + 5 * WSZ);

    // K/V text -> [b][h][t][d] fp16
    gemm_mma<1><<<dim3(8, 39), 256, GM_SMEM>>>(
        pchi, pwhi + 1 * WSZ, nullptr, nullptr,
        pkt, B_ * LT_, LT_, CTXR, 0);
    gemm_mma<1><<<dim3(8, 39), 256, GM_SMEM>>>(
        pchi, pwhi + 2 * WSZ, nullptr, nullptr,
        pvt, B_ * LT_, LT_, CTXR, 0);

    // K/V image
    gemm_mma<1><<<dim3(8, 128), 256, GM_SMEM>>>(
        pchi, pwhi + 3 * WSZ, nullptr, nullptr,
        pki, B_ * LI_, LI_, CTXR, LT_);
    gemm_mma<1><<<dim3(8, 128), 256, GM_SMEM>>>(
        pchi, pwhi + 4 * WSZ, nullptr, nullptr,
        pvi, B_ * LI_, LI_, CTXR, LT_);

    // tensor-core attention -> fp16 into final-GEMM input
    attn_mma<<<B_ * H_ * 8, 256, AT_SMEM>>>(
        pqhi, pkt, pvt, pki, pvi, relk, relv, pahi);

    // final projection + bias (1-term)
    gemm_mma<0><<<dim3(8, 512), 256, GM_SMEM>>>(
        pahi, pwhi + 5 * WSZ, out, bout,
        nullptr, B_ * NQ_, B_ * NQ_, B_ * NQ_, 0);
}

// round 16
// speedup vs baseline: 2.4785x; 1.0056x over previous
#include <cuda_runtime.h>
#include <cuda_fp16.h>
#include <cstdint>

// ---------------------------------------------------------------------------
// Problem constants
// ---------------------------------------------------------------------------
#define B_    64
#define NQ_   1024
#define DM_   1024
#define H_    16
#define D_    64
#define LT_   77
#define LI_   256
#define NR_   33
#define CTXR  (LT_ + LI_)     // 333

__device__ __forceinline__ uint32_t smem_to_u32(const void* p) {
    uint32_t a;
    asm("{ .reg .u64 t; cvta.to.shared.u64 t, %1; cvt.u32.u64 %0, t; }"
        : "=r"(a) : "l"(p));
    return a;
}

#define CPA16(dst, src) \
    asm volatile("cp.async.cg.shared.global [%0], [%1], 16;" \
                 :: "r"(dst), "l"(src))
#define CPA_COMMIT() asm volatile("cp.async.commit_group;" ::: "memory")
#define CPA_WAIT(n)  asm volatile("cp.async.wait_group %0;" :: "n"(n) : "memory")

#define LDMX4(r0, r1, r2, r3, addr) \
    asm volatile("ldmatrix.sync.aligned.m8n8.x4.shared.b16 {%0,%1,%2,%3}, [%4];" \
                 : "=r"(r0), "=r"(r1), "=r"(r2), "=r"(r3) : "r"(addr))
#define LDMX4T(r0, r1, r2, r3, addr) \
    asm volatile("ldmatrix.sync.aligned.m8n8.x4.trans.shared.b16 {%0,%1,%2,%3}, [%4];" \
                 : "=r"(r0), "=r"(r1), "=r"(r2), "=r"(r3) : "r"(addr))

#define MMA16816(c, a, b0, b1) \
    asm volatile("mma.sync.aligned.m16n8k16.row.col.f32.f16.f16.f32 " \
                 "{%0,%1,%2,%3}, {%4,%5,%6,%7}, {%8,%9}, {%0,%1,%2,%3};" \
                 : "+f"((c)[0]), "+f"((c)[1]), "+f"((c)[2]), "+f"((c)[3]) \
                 : "r"((a)[0]), "r"((a)[1]), "r"((a)[2]), "r"((a)[3]), \
                   "r"(b0), "r"(b1))

__device__ __forceinline__ uint32_t packh(float lo, float hi) {
    uint32_t d;
    asm("cvt.rn.f16x2.f32 %0, %1, %2;" : "=r"(d) : "f"(hi), "f"(lo));
    return d;
}

// ---------------------------------------------------------------------------
// Scratch (static device globals)
// ---------------------------------------------------------------------------
__device__ __half g_ahi[(size_t)B_ * NQ_ * DM_];  // x hi, later att (fp16)
__device__ __half g_qhi[(size_t)B_ * NQ_ * DM_];
__device__ __half g_chi[(size_t)B_ * CTXR * DM_];
__device__ __half g_whi[6 * (size_t)DM_ * DM_];
__device__ __half g_kt[(size_t)B_ * H_ * LT_ * D_];
__device__ __half g_vt[(size_t)B_ * H_ * LT_ * D_];
__device__ __half g_ki[(size_t)B_ * H_ * LI_ * D_];
__device__ __half g_vi[(size_t)B_ * H_ * LI_ * D_];

// ---------------------------------------------------------------------------
// fp32 -> fp16 (hi only)
// ---------------------------------------------------------------------------
__global__ void conv_rows(const float* __restrict__ src,
                          __half* __restrict__ hi, size_t n)
{
    size_t i = ((size_t)blockIdx.x * blockDim.x + threadIdx.x) * 4;
    if (i >= n) return;
    float4 v = *(const float4*)(src + i);
    *(uint2*)(hi + i) = make_uint2(packh(v.x, v.y), packh(v.z, v.w));
}

// W [K=1024, N=1024] -> Wt hi [N, K]
__global__ void conv_wt(const float* __restrict__ W,
                        __half* __restrict__ hi)
{
    __shared__ float tile[32][33];
    const int k0 = blockIdx.y * 32, n0 = blockIdx.x * 32;
    const int tx = threadIdx.x;
    for (int r = threadIdx.y; r < 32; r += 8)
        tile[r][tx] = W[(size_t)(k0 + r) * DM_ + n0 + tx];
    __syncthreads();
    for (int r = threadIdx.y; r < 32; r += 8)
        hi[(size_t)(n0 + r) * DM_ + k0 + tx] = __float2half(tile[tx][r]);
}

// ---------------------------------------------------------------------------
// fp16 1-term GEMM via mma.sync: C = remap(A)_hi @ Bhi^T.
// MODE 0: fp32 C + bias.  MODE 1: KV scatter fp16 (grouped: blockIdx.z
// selects B/C pair).  MODE 2: Q *0.125 fp16.
// CTA 128x128, BK=32, 3-stage cp.async pipeline, 2 CTAs/SM.
// ---------------------------------------------------------------------------
#define BUF_BYTES   30720
#define GM_SMEM     (3 * BUF_BYTES)   // 92160

template <int MODE>
__global__ void __launch_bounds__(256, 2)
gemm_mma(const __half* __restrict__ Ahi,
         const __half* __restrict__ Bhi, const __half* __restrict__ Bhi1,
         float* __restrict__ C, const float* __restrict__ bias,
         __half* __restrict__ Chi, __half* __restrict__ Chi1,
         int M, int rows_per_seg, int seg_stride, int seg_base)
{
    extern __shared__ __align__(128) char smem[];
    const uint32_t sb = smem_to_u32(smem);
    const int tid = threadIdx.x;
    const int bn = blockIdx.x * 128;
    const int bm = blockIdx.y * 128;
    const __half* Bp = blockIdx.z ? Bhi1 : Bhi;
    __half* Cp16 = blockIdx.z ? Chi1 : Chi;
    const int wid = tid >> 5, lane = tid & 31;
    const int Wm = (wid & 3) * 32;
    const int Wn = (wid >> 2) * 64;

    const int lrow = tid >> 1;
    const int lc = tid & 1;
    int m = bm + lrow; if (m > M - 1) m = M - 1;
    const int seg = m / rows_per_seg;
    const int t = m - seg * rows_per_seg;
    const size_t aoff = (size_t)(seg * seg_stride + seg_base + t) * 1024 + lc * 16;
    const size_t boff = (size_t)(bn + lrow) * 1024 + lc * 16;
    const uint32_t soff = (uint32_t)lrow * 80u + (uint32_t)lc * 32u;

    float acc[2][8][4];
#pragma unroll
    for (int i = 0; i < 2; i++)
#pragma unroll
        for (int j = 0; j < 8; j++)
#pragma unroll
            for (int c = 0; c < 4; c++) acc[i][j][c] = 0.f;

    const uint32_t a_frag_row = (uint32_t)(Wm + (lane & 15)) * 80u + ((lane >> 4) * 16u);
    const uint32_t b_frag_row =
        (uint32_t)(Wn + (lane & 7) + ((lane >> 4) << 3)) * 80u + (((lane >> 3) & 1) * 16u);

#define ISSUE(p, k0)                                                       \
    {                                                                      \
        uint32_t d = sb + (p) * BUF_BYTES + soff;                          \
        const __half* s;                                                   \
        s = Ahi + aoff + (k0); CPA16(d,           s); CPA16(d + 16,         s + 8); \
        s = Bp + boff + (k0);  CPA16(d + 20480,   s); CPA16(d + 20480 + 16, s + 8); \
    }

    ISSUE(0, 0);
    CPA_COMMIT();
    ISSUE(1, 32);
    CPA_COMMIT();

    int stage = 0;
    for (int i = 0; i < 32; i++) {
        if (i < 31) { CPA_WAIT(1); } else { CPA_WAIT(0); }
        __syncthreads();
        if (i + 2 < 32) {
            int ns = stage + 2; if (ns >= 3) ns -= 3;
            ISSUE(ns, (i + 2) * 32);
            CPA_COMMIT();
        }

        const uint32_t base = sb + stage * BUF_BYTES;
#pragma unroll
        for (int kk = 0; kk < 2; kk++) {
            uint32_t ah[2][4], bh[4][4];
            const uint32_t ar = base + a_frag_row + kk * 32;
            LDMX4(ah[0][0], ah[0][1], ah[0][2], ah[0][3], ar);
            LDMX4(ah[1][0], ah[1][1], ah[1][2], ah[1][3], ar + 16 * 80);
#pragma unroll
            for (int j = 0; j < 4; j++) {
                const uint32_t br = base + 20480 + b_frag_row + kk * 32
                                    + (uint32_t)j * (16 * 80);
                LDMX4(bh[j][0], bh[j][1], bh[j][2], bh[j][3], br);
            }
#pragma unroll
            for (int j = 0; j < 4; j++)
#pragma unroll
                for (int mt = 0; mt < 2; mt++) {
                    MMA16816(acc[mt][2 * j],     ah[mt], bh[j][0], bh[j][1]);
                    MMA16816(acc[mt][2 * j + 1], ah[mt], bh[j][2], bh[j][3]);
                }
        }
        stage++; if (stage >= 3) stage = 0;
    }
#undef ISSUE

    const int er = lane >> 2, ec = (lane & 3) * 2;
#pragma unroll
    for (int mt = 0; mt < 2; mt++) {
#pragma unroll
        for (int hrow = 0; hrow < 2; hrow++) {
            const int cm = bm + Wm + mt * 16 + er + hrow * 8;
            if (cm >= M) continue;
            if (MODE == 1) {
                const int segc = cm / rows_per_seg;
                const int tc = cm - segc * rows_per_seg;
#pragma unroll
                for (int nt = 0; nt < 8; nt++) {
                    const int cn = bn + Wn + nt * 8 + ec;
                    const int hh = cn >> 6, dd = cn & 63;
                    size_t oi = (((size_t)segc * H_ + hh) * rows_per_seg + tc) * 64 + dd;
                    *(uint32_t*)(Cp16 + oi) =
                        packh(acc[mt][nt][hrow * 2], acc[mt][nt][hrow * 2 + 1]);
                }
            } else if (MODE == 2) {
#pragma unroll
                for (int nt = 0; nt < 8; nt++) {
                    const int cn = bn + Wn + nt * 8 + ec;
                    size_t oi = (size_t)cm * DM_ + cn;
                    *(uint32_t*)(Cp16 + oi) =
                        packh(acc[mt][nt][hrow * 2] * 0.125f,
                              acc[mt][nt][hrow * 2 + 1] * 0.125f);
                }
            } else {
                float* Cp = C + (size_t)cm * DM_ + bn + Wn + ec;
                const float* bp = bias + bn + Wn + ec;
#pragma unroll
                for (int nt = 0; nt < 8; nt++) {
                    float2 v = make_float2(acc[mt][nt][hrow * 2] + bp[nt * 8],
                                           acc[mt][nt][hrow * 2 + 1] + bp[nt * 8 + 1]);
                    *(float2*)(Cp + nt * 8) = v;
                }
            }
        }
    }
}

// ---------------------------------------------------------------------------
// Persistent tensor-core flash attention: one CTA per (b,h), loops over the
// 8 query tiles; K/V staged once. QK/WV 1-term, image-first merged acc,
// fp16 output. 2 CTAs/SM.
// smem: K 0..48384, V 48384..96768, overlay 96768..113664:
//   Q staging (128B rows) / relk hi+lo (tile 0) / pS[128][33]
// ---------------------------------------------------------------------------
#define AT_KHI 0
#define AT_VHI 48384
#define AT_QS  96768
#define AT_RKH 96768
#define AT_RKL 102528
#define AT_PS  96768
#define AT_SMEM 113664

__device__ __forceinline__ int bidx(int j, int i)
{
    int d = j - i;
    d = max(-16, min(16, d));
    return d + 16;
}

__global__ void __launch_bounds__(256, 2)
attn_mma(const __half* __restrict__ qhi,
         const __half* __restrict__ kt, const __half* __restrict__ vt,
         const __half* __restrict__ ki, const __half* __restrict__ vi,
         const float* __restrict__ relk, const float* __restrict__ relv,
         __half* __restrict__ atthi)
{
    extern __shared__ __align__(128) char sm[];
    const uint32_t sb = smem_to_u32(sm);
    const int tid = threadIdx.x, w = tid >> 5, lane = tid & 31;
    const int bh = blockIdx.x;
    const int b = bh >> 4, h = bh & 15;
    const unsigned FULL = 0xffffffffu;

    // ---- stage K/V once (144B rows) ----
    {
        size_t tb = (size_t)bh * (LT_ * 64);
        for (int idx = tid; idx < LT_ * 8; idx += 256) {
            int r = idx >> 3, c = idx & 7;
            uint32_t d = (uint32_t)r * 144 + c * 16;
            size_t s = tb + (size_t)r * 64 + c * 8;
            CPA16(sb + AT_KHI + d, kt + s);
            CPA16(sb + AT_VHI + d, vt + s);
        }
        size_t ib = (size_t)bh * (LI_ * 64);
        for (int idx = tid; idx < LI_ * 8; idx += 256) {
            int r = idx >> 3, c = idx & 7;
            uint32_t d = (uint32_t)(80 + r) * 144 + c * 16;
            size_t s = ib + (size_t)r * 64 + c * 8;
            CPA16(sb + AT_KHI + d, ki + s);
            CPA16(sb + AT_VHI + d, vi + s);
        }
        for (int idx = tid; idx < 3 * 36; idx += 256) {
            uint32_t d = (uint32_t)(77 + idx / 36) * 144 + (idx % 36) * 4;
            *(uint32_t*)(sm + AT_KHI + d) = 0;
            *(uint32_t*)(sm + AT_VHI + d) = 0;
        }
        CPA_COMMIT();
    }

    const int wr = w * 16;
    const int r0l = wr + (lane >> 2);
    const int brow = ((lane >> 4) << 3) + (lane & 7);
    const int bdb = (lane & 8) * 2;
    const int vrow = (lane & 8) + (lane & 7);
    const int vdb = (lane >> 4) * 16;

    float* pS = (float*)(sm + AT_PS);

#pragma unroll 1
    for (int qt = 0; qt < 8; qt++) {
        const int i0 = qt * 128;

        __syncthreads();   // overlay region free (prior pS reads / K,V stage done)

        // ---- stage Q tile (128B rows) ----
        {
            size_t qb = ((size_t)(b * NQ_ + i0)) * 1024 + h * 64;
            for (int idx = tid; idx < 128 * 8; idx += 256) {
                int r = idx >> 3, c = idx & 7;
                uint32_t d = (uint32_t)r * 128 + c * 16;
                size_t s = qb + (size_t)r * 1024 + c * 8;
                CPA16(sb + AT_QS + d, qhi + s);
            }
            CPA_COMMIT();
            CPA_WAIT(0);
            __syncthreads();
        }

        // ---- Q fragments ----
        uint32_t qh[4][4];
        {
            int row = wr + (lane & 15);
            int kb = (lane >> 4) * 16;
#pragma unroll
            for (int kk = 0; kk < 4; kk++) {
                uint32_t a = sb + AT_QS + (uint32_t)row * 128 + kk * 32 + kb;
                LDMX4(qh[kk][0], qh[kk][1], qh[kk][2], qh[kk][3], a);
            }
        }
        __syncthreads();   // Q staging region reusable

        // ---- stage relk hi/lo into overlay (tile 0 only) ----
        if (qt == 0) {
            for (int idx = tid; idx < NR_ * 64; idx += 256) {
                int r = idx >> 6, dc = idx & 63;
                float v = relk[idx];
                float hh = __half2float(__float2half(v));
                *(__half*)(sm + AT_RKH + r * 144 + dc * 2) = __float2half(hh);
                *(__half*)(sm + AT_RKL + r * 144 + dc * 2) = __float2half(v - hh);
            }
        }

        // ===== image branch first (merged accumulator) =====
        float o[8][4];
#pragma unroll
        for (int i = 0; i < 8; i++)
#pragma unroll
            for (int c = 0; c < 4; c++) o[i][c] = 0.f;
        float mi0 = -1e30f, mi1 = -1e30f, li0 = 0.f, li1 = 0.f;
#pragma unroll 1
        for (int ch = 0; ch < 8; ch++) {
            const int j0 = 80 + ch * 32;
            float sc[4][4];
#pragma unroll
            for (int i = 0; i < 4; i++)
#pragma unroll
                for (int c = 0; c < 4; c++) sc[i][c] = 0.f;
#pragma unroll
            for (int kk = 0; kk < 4; kk++) {
#pragma unroll
                for (int p2 = 0; p2 < 2; p2++) {
                    uint32_t kh4[4];
                    uint32_t ad = sb + AT_KHI + (uint32_t)(j0 + p2 * 16 + brow) * 144
                                  + kk * 32 + bdb;
                    LDMX4(kh4[0], kh4[1], kh4[2], kh4[3], ad);
                    MMA16816(sc[2 * p2], qh[kk], kh4[0], kh4[1]);
                    MMA16816(sc[2 * p2 + 1], qh[kk], kh4[2], kh4[3]);
                }
            }
            float cm0 = -1e30f, cm1 = -1e30f;
#pragma unroll
            for (int t = 0; t < 4; t++) {
                cm0 = fmaxf(cm0, fmaxf(sc[t][0], sc[t][1]));
                cm1 = fmaxf(cm1, fmaxf(sc[t][2], sc[t][3]));
            }
            cm0 = fmaxf(cm0, __shfl_xor_sync(FULL, cm0, 1));
            cm0 = fmaxf(cm0, __shfl_xor_sync(FULL, cm0, 2));
            cm1 = fmaxf(cm1, __shfl_xor_sync(FULL, cm1, 1));
            cm1 = fmaxf(cm1, __shfl_xor_sync(FULL, cm1, 2));
            float mn0 = fmaxf(mi0, cm0), mn1 = fmaxf(mi1, cm1);
            float al0 = __expf(mi0 - mn0), al1 = __expf(mi1 - mn1);
            float cs0 = 0.f, cs1 = 0.f;
#pragma unroll
            for (int t = 0; t < 4; t++) {
                sc[t][0] = __expf(sc[t][0] - mn0); cs0 += sc[t][0];
                sc[t][1] = __expf(sc[t][1] - mn0); cs0 += sc[t][1];
                sc[t][2] = __expf(sc[t][2] - mn1); cs1 += sc[t][2];
                sc[t][3] = __expf(sc[t][3] - mn1); cs1 += sc[t][3];
            }
            cs0 += __shfl_xor_sync(FULL, cs0, 1); cs0 += __shfl_xor_sync(FULL, cs0, 2);
            cs1 += __shfl_xor_sync(FULL, cs1, 1); cs1 += __shfl_xor_sync(FULL, cs1, 2);
            li0 = li0 * al0 + cs0; li1 = li1 * al1 + cs1;
            mi0 = mn0; mi1 = mn1;
#pragma unroll
            for (int dt = 0; dt < 8; dt++) {
                o[dt][0] *= al0; o[dt][1] *= al0;
                o[dt][2] *= al1; o[dt][3] *= al1;
            }
#pragma unroll
            for (int wk = 0; wk < 2; wk++) {
                uint32_t ahi[4];
                const float* s0 = sc[2 * wk];
                const float* s1 = sc[2 * wk + 1];
                ahi[0] = packh(s0[0], s0[1]); ahi[1] = packh(s0[2], s0[3]);
                ahi[2] = packh(s1[0], s1[1]); ahi[3] = packh(s1[2], s1[3]);
#pragma unroll
                for (int dp = 0; dp < 4; dp++) {
                    uint32_t vh4[4];
                    uint32_t ad = sb + AT_VHI + (uint32_t)(j0 + wk * 16 + vrow) * 144
                                  + dp * 32 + vdb;
                    LDMX4T(vh4[0], vh4[1], vh4[2], vh4[3], ad);
                    MMA16816(o[2 * dp], ahi, vh4[0], vh4[1]);
                    MMA16816(o[2 * dp + 1], ahi, vh4[2], vh4[3]);
                }
            }
        }
        {
            float ii0 = 1.f / li0, ii1 = 1.f / li1;
#pragma unroll
            for (int dt = 0; dt < 8; dt++) {
                o[dt][0] *= ii0; o[dt][1] *= ii0;
                o[dt][2] *= ii1; o[dt][3] *= ii1;
            }
        }

        __syncthreads();   // relk staging visible (tile 0); uniform barrier

        // ---- rel-K projections (tile 0) ----
        if (qt == 0) {
            float pr[5][4];
#pragma unroll
            for (int i = 0; i < 5; i++)
#pragma unroll
                for (int c = 0; c < 4; c++) pr[i][c] = 0.f;
#pragma unroll
            for (int kk = 0; kk < 4; kk++) {
#pragma unroll
                for (int p2 = 0; p2 < 3; p2++) {
                    uint32_t bh4[4], bl4[4];
                    uint32_t ad = sb + AT_RKH + (uint32_t)(p2 * 16 + brow) * 144
                                  + kk * 32 + bdb;
                    LDMX4(bh4[0], bh4[1], bh4[2], bh4[3], ad);
                    LDMX4(bl4[0], bl4[1], bl4[2], bl4[3], ad + (AT_RKL - AT_RKH));
                    MMA16816(pr[2 * p2], qh[kk], bh4[0], bh4[1]);
                    MMA16816(pr[2 * p2], qh[kk], bl4[0], bl4[1]);
                    if (p2 < 2) {
                        MMA16816(pr[2 * p2 + 1], qh[kk], bh4[2], bh4[3]);
                        MMA16816(pr[2 * p2 + 1], qh[kk], bl4[2], bl4[3]);
                    }
                }
            }
            __syncthreads();   // all warps done reading relk; pS overlays it
#pragma unroll
            for (int nt = 0; nt < 5; nt++) {
                int c0 = nt * 8 + 2 * (lane & 3);
                if (c0 < NR_) {
                    pS[r0l * 33 + c0] = pr[nt][0];
                    pS[(r0l + 8) * 33 + c0] = pr[nt][2];
                }
                if (c0 + 1 < NR_) {
                    pS[r0l * 33 + c0 + 1] = pr[nt][1];
                    pS[(r0l + 8) * 33 + c0 + 1] = pr[nt][3];
                }
            }
            __syncwarp();
        }

        // ---- text scores (1-term) ----
        float s[10][4];
#pragma unroll
        for (int i = 0; i < 10; i++)
#pragma unroll
            for (int c = 0; c < 4; c++) s[i][c] = 0.f;
#pragma unroll
        for (int kk = 0; kk < 4; kk++) {
#pragma unroll
            for (int p2 = 0; p2 < 5; p2++) {
                uint32_t kh4[4];
                uint32_t ad = sb + AT_KHI + (uint32_t)(p2 * 16 + brow) * 144
                              + kk * 32 + bdb;
                LDMX4(kh4[0], kh4[1], kh4[2], kh4[3], ad);
                MMA16816(s[2 * p2], qh[kk], kh4[0], kh4[1]);
                MMA16816(s[2 * p2 + 1], qh[kk], kh4[2], kh4[3]);
            }
        }

#pragma unroll
        for (int nt = 0; nt < 10; nt++) {
            int c0 = nt * 8 + 2 * (lane & 3);
            if (qt == 0) {
                s[nt][0] += pS[r0l * 33 + bidx(c0, r0l)];
                s[nt][1] += pS[r0l * 33 + bidx(c0 + 1, r0l)];
                s[nt][2] += pS[(r0l + 8) * 33 + bidx(c0, r0l + 8)];
                s[nt][3] += pS[(r0l + 8) * 33 + bidx(c0 + 1, r0l + 8)];
            }
            if (c0 >= LT_) { s[nt][0] = -1e30f; s[nt][2] = -1e30f; }
            if (c0 + 1 >= LT_) { s[nt][1] = -1e30f; s[nt][3] = -1e30f; }
        }

        float m0 = -1e30f, m1 = -1e30f;
#pragma unroll
        for (int nt = 0; nt < 10; nt++) {
            m0 = fmaxf(m0, fmaxf(s[nt][0], s[nt][1]));
            m1 = fmaxf(m1, fmaxf(s[nt][2], s[nt][3]));
        }
        m0 = fmaxf(m0, __shfl_xor_sync(FULL, m0, 1));
        m0 = fmaxf(m0, __shfl_xor_sync(FULL, m0, 2));
        m1 = fmaxf(m1, __shfl_xor_sync(FULL, m1, 1));
        m1 = fmaxf(m1, __shfl_xor_sync(FULL, m1, 2));
        float l0 = 0.f, l1 = 0.f;
#pragma unroll
        for (int nt = 0; nt < 10; nt++) {
            s[nt][0] = __expf(s[nt][0] - m0); l0 += s[nt][0];
            s[nt][1] = __expf(s[nt][1] - m0); l0 += s[nt][1];
            s[nt][2] = __expf(s[nt][2] - m1); l1 += s[nt][2];
            s[nt][3] = __expf(s[nt][3] - m1); l1 += s[nt][3];
        }
        l0 += __shfl_xor_sync(FULL, l0, 1); l0 += __shfl_xor_sync(FULL, l0, 2);
        l1 += __shfl_xor_sync(FULL, l1, 1); l1 += __shfl_xor_sync(FULL, l1, 2);
        float inv0 = 1.f / l0, inv1 = 1.f / l1;
#pragma unroll
        for (int nt = 0; nt < 10; nt++) {
            s[nt][0] *= inv0; s[nt][1] *= inv0;
            s[nt][2] *= inv1; s[nt][3] *= inv1;
        }

        if (qt == 0) {
            for (int idx = lane; idx < 16 * 33; idx += 32)
                pS[(wr + idx / 33) * 33 + idx % 33] = 0.f;
            __syncwarp();
#pragma unroll
            for (int nt = 0; nt < 10; nt++) {
                int c0 = nt * 8 + 2 * (lane & 3);
                if (c0 < LT_) {
                    atomicAdd(&pS[r0l * 33 + bidx(c0, r0l)], s[nt][0]);
                    atomicAdd(&pS[(r0l + 8) * 33 + bidx(c0, r0l + 8)], s[nt][2]);
                }
                if (c0 + 1 < LT_) {
                    atomicAdd(&pS[r0l * 33 + bidx(c0 + 1, r0l)], s[nt][1]);
                    atomicAdd(&pS[(r0l + 8) * 33 + bidx(c0 + 1, r0l + 8)], s[nt][3]);
                }
            }
            __syncwarp();
        }

        // ---- O += W @ V_text (1-term, fp16 weights) ----
#pragma unroll
        for (int wk = 0; wk < 5; wk++) {
            uint32_t ahi[4];
            const float* s0 = s[2 * wk];
            const float* s1 = s[2 * wk + 1];
            ahi[0] = packh(s0[0], s0[1]); ahi[1] = packh(s0[2], s0[3]);
            ahi[2] = packh(s1[0], s1[1]); ahi[3] = packh(s1[2], s1[3]);
#pragma unroll
            for (int dp = 0; dp < 4; dp++) {
                uint32_t vh4[4];
                uint32_t ad = sb + AT_VHI + (uint32_t)(wk * 16 + vrow) * 144
                              + dp * 32 + vdb;
                LDMX4T(vh4[0], vh4[1], vh4[2], vh4[3], ad);
                MMA16816(o[2 * dp], ahi, vh4[0], vh4[1]);
                MMA16816(o[2 * dp + 1], ahi, vh4[2], vh4[3]);
            }
        }

        // ---- rel-V contribution ----
        if (qt == 0) {
#pragma unroll 1
            for (int r = 0; r < NR_; r++) {
                float w0 = pS[r0l * 33 + r];
                float w1 = pS[(r0l + 8) * 33 + r];
                const float* rv = relv + r * 64 + 2 * (lane & 3);
#pragma unroll
                for (int dt = 0; dt < 8; dt++) {
                    float rv0 = rv[dt * 8], rv1 = rv[dt * 8 + 1];
                    o[dt][0] += w0 * rv0; o[dt][1] += w0 * rv1;
                    o[dt][2] += w1 * rv0; o[dt][3] += w1 * rv1;
                }
            }
        } else {
            const float* rv = relv + 2 * (lane & 3);
#pragma unroll
            for (int dt = 0; dt < 8; dt++) {
                float rv0 = rv[dt * 8], rv1 = rv[dt * 8 + 1];
                o[dt][0] += rv0; o[dt][1] += rv1;
                o[dt][2] += rv0; o[dt][3] += rv1;
            }
        }

        // ---- store fp16 ----
        {
            size_t ob = ((size_t)(b * NQ_ + i0 + r0l)) * 1024 + h * 64
                        + 2 * (lane & 3);
#pragma unroll
            for (int dt = 0; dt < 8; dt++) {
                size_t o0 = ob + dt * 8;
                size_t o1 = o0 + 8 * 1024;
                *(uint32_t*)(atthi + o0) = packh(o[dt][0], o[dt][1]);
                *(uint32_t*)(atthi + o1) = packh(o[dt][2], o[dt][3]);
            }
        }
    }
}

// ---------------------------------------------------------------------------
// Host launcher
// ---------------------------------------------------------------------------
extern "C" void kernel_launch(void* const* d_in, const int* in_sizes, int n_in,
                              void* d_out, int out_size)
{
    const float* x     = (const float*)d_in[0];
    const float* ctx   = (const float*)d_in[1];
    const float* Wq    = (const float*)d_in[2];
    const float* Wk    = (const float*)d_in[3];
    const float* Wv    = (const float*)d_in[4];
    const float* Wk_ip = (const float*)d_in[5];
    const float* Wv_ip = (const float*)d_in[6];
    const float* Wout  = (const float*)d_in[7];
    const float* bout  = (const float*)d_in[8];
    const float* relk  = (const float*)d_in[9];
    const float* relv  = (const float*)d_in[10];
    float* out = (float*)d_out;

    __half *pahi, *pqhi, *pchi, *pwhi;
    __half *pkt, *pvt, *pki, *pvi;
    cudaGetSymbolAddress((void**)&pahi, g_ahi);
    cudaGetSymbolAddress((void**)&pqhi, g_qhi);
    cudaGetSymbolAddress((void**)&pchi, g_chi);
    cudaGetSymbolAddress((void**)&pwhi, g_whi);
    cudaGetSymbolAddress((void**)&pkt, g_kt);
    cudaGetSymbolAddress((void**)&pvt, g_vt);
    cudaGetSymbolAddress((void**)&pki, g_ki);
    cudaGetSymbolAddress((void**)&pvi, g_vi);

    cudaFuncSetAttribute(gemm_mma<0>,
                         cudaFuncAttributeMaxDynamicSharedMemorySize, GM_SMEM);
    cudaFuncSetAttribute(gemm_mma<1>,
                         cudaFuncAttributeMaxDynamicSharedMemorySize, GM_SMEM);
    cudaFuncSetAttribute(gemm_mma<2>,
                         cudaFuncAttributeMaxDynamicSharedMemorySize, GM_SMEM);
    cudaFuncSetAttribute(attn_mma,
                         cudaFuncAttributeMaxDynamicSharedMemorySize, AT_SMEM);

    const size_t WSZ = (size_t)DM_ * DM_;
    size_t nx = (size_t)B_ * NQ_ * DM_;
    size_t nc = (size_t)B_ * CTXR * DM_;

    conv_wt<<<dim3(32, 32), dim3(32, 8)>>>(Wq, pwhi + 0 * WSZ);
    conv_rows<<<(unsigned)(nx / 4 / 256), 256>>>(x, pahi, nx);
    conv_rows<<<(unsigned)((nc / 4 + 255) / 256), 256>>>(ctx, pchi, nc);
    conv_wt<<<dim3(32, 32), dim3(32, 8)>>>(Wk, pwhi + 1 * WSZ);
    conv_wt<<<dim3(32, 32), dim3(32, 8)>>>(Wv, pwhi + 2 * WSZ);

    // Q = (x_hi @ Wq_hi) * 0.125 -> fp16
    gemm_mma<2><<<dim3(8, 512), 256, GM_SMEM>>>(
        pahi, pwhi + 0 * WSZ, nullptr, nullptr, nullptr,
        pqhi, nullptr, B_ * NQ_, B_ * NQ_, B_ * NQ_, 0);

    conv_wt<<<dim3(32, 32), dim3(32, 8)>>>(Wk_ip, pwhi + 3 * WSZ);
    conv_wt<<<dim3(32, 32), dim3(32, 8)>>>(Wv_ip, pwhi + 4 * WSZ);
    conv_wt<<<dim3(32, 32), dim3(32, 8)>>>(Wout,  pwhi + 5 * WSZ);

    // K+V text (grouped: z=0 -> Wk->kt, z=1 -> Wv->vt)
    gemm_mma<1><<<dim3(8, 39, 2), 256, GM_SMEM>>>(
        pchi, pwhi + 1 * WSZ, pwhi + 2 * WSZ, nullptr, nullptr,
        pkt, pvt, B_ * LT_, LT_, CTXR, 0);

    // K+V image (grouped)
    gemm_mma<1><<<dim3(8, 128, 2), 256, GM_SMEM>>>(
        pchi, pwhi + 3 * WSZ, pwhi + 4 * WSZ, nullptr, nullptr,
        pki, pvi, B_ * LI_, LI_, CTXR, LT_);

    // persistent tensor-core attention (one CTA per (b,h))
    attn_mma<<<B_ * H_, 256, AT_SMEM>>>(
        pqhi, pkt, pvt, pki, pvi, relk, relv, pahi);

    // final projection + bias (1-term)
    gemm_mma<0><<<dim3(8, 512), 256, GM_SMEM>>>(
        pahi, pwhi + 5 * WSZ, nullptr, out, bout,
        nullptr, nullptr, B_ * NQ_, B_ * NQ_, B_ * NQ_, 0);
}

// round 17
// speedup vs baseline: 2.5280x; 1.0200x over previous
#include <cuda_runtime.h>
#include <cuda_fp16.h>
#include <cstdint>

// ---------------------------------------------------------------------------
// Problem constants
// ---------------------------------------------------------------------------
#define B_    64
#define NQ_   1024
#define DM_   1024
#define H_    16
#define D_    64
#define LT_   77
#define LI_   256
#define NR_   33
#define CTXR  (LT_ + LI_)     // 333

__device__ __forceinline__ uint32_t smem_to_u32(const void* p) {
    uint32_t a;
    asm("{ .reg .u64 t; cvta.to.shared.u64 t, %1; cvt.u32.u64 %0, t; }"
        : "=r"(a) : "l"(p));
    return a;
}

#define CPA16(dst, src) \
    asm volatile("cp.async.cg.shared.global [%0], [%1], 16;" \
                 :: "r"(dst), "l"(src))
#define CPA_COMMIT() asm volatile("cp.async.commit_group;" ::: "memory")
#define CPA_WAIT(n)  asm volatile("cp.async.wait_group %0;" :: "n"(n) : "memory")

#define LDMX4(r0, r1, r2, r3, addr) \
    asm volatile("ldmatrix.sync.aligned.m8n8.x4.shared.b16 {%0,%1,%2,%3}, [%4];" \
                 : "=r"(r0), "=r"(r1), "=r"(r2), "=r"(r3) : "r"(addr))
#define LDMX4T(r0, r1, r2, r3, addr) \
    asm volatile("ldmatrix.sync.aligned.m8n8.x4.trans.shared.b16 {%0,%1,%2,%3}, [%4];" \
                 : "=r"(r0), "=r"(r1), "=r"(r2), "=r"(r3) : "r"(addr))

#define MMA16816(c, a, b0, b1) \
    asm volatile("mma.sync.aligned.m16n8k16.row.col.f32.f16.f16.f32 " \
                 "{%0,%1,%2,%3}, {%4,%5,%6,%7}, {%8,%9}, {%0,%1,%2,%3};" \
                 : "+f"((c)[0]), "+f"((c)[1]), "+f"((c)[2]), "+f"((c)[3]) \
                 : "r"((a)[0]), "r"((a)[1]), "r"((a)[2]), "r"((a)[3]), \
                   "r"(b0), "r"(b1))

__device__ __forceinline__ uint32_t packh(float lo, float hi) {
    uint32_t d;
    asm("cvt.rn.f16x2.f32 %0, %1, %2;" : "=r"(d) : "f"(hi), "f"(lo));
    return d;
}

// ---------------------------------------------------------------------------
// Scratch (static device globals)
// ---------------------------------------------------------------------------
__device__ __half g_ahi[(size_t)B_ * NQ_ * DM_];  // x hi, later att (fp16)
__device__ __half g_qhi[(size_t)B_ * NQ_ * DM_];
__device__ __half g_chi[(size_t)B_ * CTXR * DM_];
__device__ __half g_whi[6 * (size_t)DM_ * DM_];
__device__ __half g_kt[(size_t)B_ * H_ * LT_ * D_];
__device__ __half g_vt[(size_t)B_ * H_ * LT_ * D_];
__device__ __half g_ki[(size_t)B_ * H_ * LI_ * D_];
__device__ __half g_vi[(size_t)B_ * H_ * LI_ * D_];

// ---------------------------------------------------------------------------
// Fused fp32 -> fp16 conversion of x and context (one launch)
// ---------------------------------------------------------------------------
__global__ void conv_rows2(const float* __restrict__ x,
                           const float* __restrict__ ctx,
                           __half* __restrict__ xh,
                           __half* __restrict__ ch,
                           size_t nx, size_t ntot)
{
    size_t i = ((size_t)blockIdx.x * blockDim.x + threadIdx.x) * 4;
    if (i >= ntot) return;
    const float* src;
    __half* dst;
    size_t off;
    if (i < nx) { src = x; dst = xh; off = i; }
    else        { src = ctx; dst = ch; off = i - nx; }
    float4 v = *(const float4*)(src + off);
    *(uint2*)(dst + off) = make_uint2(packh(v.x, v.y), packh(v.z, v.w));
}

// All six W [K,N] -> Wt hi [N,K] in one launch (blockIdx.z selects)
__global__ void conv_wt6(const float* __restrict__ W0, const float* __restrict__ W1,
                         const float* __restrict__ W2, const float* __restrict__ W3,
                         const float* __restrict__ W4, const float* __restrict__ W5,
                         __half* __restrict__ hi)
{
    const float* Ws[6] = {W0, W1, W2, W3, W4, W5};
    const float* W = Ws[blockIdx.z];
    __half* out = hi + (size_t)blockIdx.z * DM_ * DM_;
    __shared__ float tile[32][33];
    const int k0 = blockIdx.y * 32, n0 = blockIdx.x * 32;
    const int tx = threadIdx.x;
    for (int r = threadIdx.y; r < 32; r += 8)
        tile[r][tx] = W[(size_t)(k0 + r) * DM_ + n0 + tx];
    __syncthreads();
    for (int r = threadIdx.y; r < 32; r += 8)
        out[(size_t)(n0 + r) * DM_ + k0 + tx] = __float2half(tile[tx][r]);
}

// ---------------------------------------------------------------------------
// GEMM mainloop (shared by fused Q/KV kernel and Wout kernel).
// CTA 128x128, BK=32, 3-stage cp.async pipeline, 2 CTAs/SM, 1-term fp16.
// ---------------------------------------------------------------------------
#define BUF_BYTES   30720
#define GM_SMEM     (3 * BUF_BYTES)   // 92160

#define GEMM_BODY(Aptr, Bptr)                                                  \
    float acc[2][8][4];                                                        \
    _Pragma("unroll")                                                          \
    for (int i = 0; i < 2; i++)                                                \
        _Pragma("unroll")                                                      \
        for (int j = 0; j < 8; j++)                                            \
            _Pragma("unroll")                                                  \
            for (int c = 0; c < 4; c++) acc[i][j][c] = 0.f;                    \
    const uint32_t a_frag_row =                                                \
        (uint32_t)(Wm + (lane & 15)) * 80u + ((lane >> 4) * 16u);              \
    const uint32_t b_frag_row =                                                \
        (uint32_t)(Wn + (lane & 7) + ((lane >> 4) << 3)) * 80u                 \
        + (((lane >> 3) & 1) * 16u);                                           \
    {                                                                          \
        uint32_t d = sb + 0 * BUF_BYTES + soff;                                \
        const __half* s;                                                       \
        s = Aptr + aoff + 0; CPA16(d, s); CPA16(d + 16, s + 8);                \
        s = Bptr + boff + 0; CPA16(d + 20480, s); CPA16(d + 20480 + 16, s + 8);\
    }                                                                          \
    CPA_COMMIT();                                                              \
    {                                                                          \
        uint32_t d = sb + 1 * BUF_BYTES + soff;                                \
        const __half* s;                                                       \
        s = Aptr + aoff + 32; CPA16(d, s); CPA16(d + 16, s + 8);               \
        s = Bptr + boff + 32; CPA16(d + 20480, s); CPA16(d + 20480 + 16, s + 8);\
    }                                                                          \
    CPA_COMMIT();                                                              \
    int stage = 0;                                                             \
    for (int i = 0; i < 32; i++) {                                             \
        if (i < 31) { CPA_WAIT(1); } else { CPA_WAIT(0); }                     \
        __syncthreads();                                                       \
        if (i + 2 < 32) {                                                      \
            int ns = stage + 2; if (ns >= 3) ns -= 3;                          \
            uint32_t d = sb + ns * BUF_BYTES + soff;                           \
            const __half* s;                                                   \
            uint32_t k0 = (i + 2) * 32;                                        \
            s = Aptr + aoff + k0; CPA16(d, s); CPA16(d + 16, s + 8);           \
            s = Bptr + boff + k0; CPA16(d + 20480, s);                         \
            CPA16(d + 20480 + 16, s + 8);                                      \
            CPA_COMMIT();                                                      \
        }                                                                      \
        const uint32_t base = sb + stage * BUF_BYTES;                          \
        _Pragma("unroll")                                                      \
        for (int kk = 0; kk < 2; kk++) {                                       \
            uint32_t ah[2][4], bh[4][4];                                       \
            const uint32_t ar = base + a_frag_row + kk * 32;                   \
            LDMX4(ah[0][0], ah[0][1], ah[0][2], ah[0][3], ar);                 \
            LDMX4(ah[1][0], ah[1][1], ah[1][2], ah[1][3], ar + 16 * 80);       \
            _Pragma("unroll")                                                  \
            for (int j = 0; j < 4; j++) {                                      \
                const uint32_t br = base + 20480 + b_frag_row + kk * 32        \
                                    + (uint32_t)j * (16 * 80);                 \
                LDMX4(bh[j][0], bh[j][1], bh[j][2], bh[j][3], br);             \
            }                                                                  \
            _Pragma("unroll")                                                  \
            for (int j = 0; j < 4; j++)                                        \
                _Pragma("unroll")                                              \
                for (int mt = 0; mt < 2; mt++) {                               \
                    MMA16816(acc[mt][2 * j],     ah[mt], bh[j][0], bh[j][1]);  \
                    MMA16816(acc[mt][2 * j + 1], ah[mt], bh[j][2], bh[j][3]);  \
                }                                                              \
        }                                                                      \
        stage++; if (stage >= 3) stage = 0;                                    \
    }

// ---------------------------------------------------------------------------
// Fused Q + KV GEMMs in one launch: 6768 CTAs.
//   [0,4096):   Q = x_hi @ Wq_hi * 0.125 -> g_qhi            (row-major)
//   [4096,4720): KV text: z in {0,1} -> Wk/Wv, kt/vt scatter (312 each)
//   [4720,6768): KV image: z in {0,1} -> Wk_ip/Wv_ip, ki/vi  (1024 each)
// ---------------------------------------------------------------------------
__global__ void __launch_bounds__(256, 2)
gemm_fused(const __half* __restrict__ xh, const __half* __restrict__ ch,
           const __half* __restrict__ whi,
           __half* __restrict__ qh_out,
           __half* __restrict__ kt, __half* __restrict__ vt,
           __half* __restrict__ ki, __half* __restrict__ vi)
{
    extern __shared__ __align__(128) char smem[];
    const uint32_t sb = smem_to_u32(smem);
    const int tid = threadIdx.x;
    const int wid = tid >> 5, lane = tid & 31;
    const int Wm = (wid & 3) * 32;
    const int Wn = (wid >> 2) * 64;
    const size_t WSZ = (size_t)DM_ * DM_;

    int cid = blockIdx.x;
    int mode, bn, bm, M, rps, ss, sbase;
    const __half *A, *Bp;
    __half* Cp;
    if (cid < 4096) {
        mode = 2; A = xh; Bp = whi; Cp = qh_out;
        M = B_ * NQ_; rps = M; ss = 0; sbase = 0;
        bn = (cid & 7) * 128; bm = (cid >> 3) * 128;
    } else if (cid < 4720) {
        int c = cid - 4096;
        int z = (c >= 312); c -= z * 312;
        mode = 1; A = ch; Bp = whi + (size_t)(1 + z) * WSZ; Cp = z ? vt : kt;
        M = B_ * LT_; rps = LT_; ss = CTXR; sbase = 0;
        bn = (c & 7) * 128; bm = (c >> 3) * 128;
    } else {
        int c = cid - 4720;
        int z = (c >= 1024); c -= z * 1024;
        mode = 1; A = ch; Bp = whi + (size_t)(3 + z) * WSZ; Cp = z ? vi : ki;
        M = B_ * LI_; rps = LI_; ss = CTXR; sbase = LT_;
        bn = (c & 7) * 128; bm = (c >> 3) * 128;
    }

    const int lrow = tid >> 1;
    const int lc = tid & 1;
    int m = bm + lrow; if (m > M - 1) m = M - 1;
    const int seg = m / rps;
    const int t = m - seg * rps;
    const size_t aoff = (size_t)(seg * ss + sbase + t) * 1024 + lc * 16;
    const size_t boff = (size_t)(bn + lrow) * 1024 + lc * 16;
    const uint32_t soff = (uint32_t)lrow * 80u + (uint32_t)lc * 32u;

    GEMM_BODY(A, Bp)

    const int er = lane >> 2, ec = (lane & 3) * 2;
#pragma unroll
    for (int mt = 0; mt < 2; mt++) {
#pragma unroll
        for (int hrow = 0; hrow < 2; hrow++) {
            const int cm = bm + Wm + mt * 16 + er + hrow * 8;
            if (cm >= M) continue;
            if (mode == 1) {
                const int segc = cm / rps;
                const int tc = cm - segc * rps;
#pragma unroll
                for (int nt = 0; nt < 8; nt++) {
                    const int cn = bn + Wn + nt * 8 + ec;
                    const int hh = cn >> 6, dd = cn & 63;
                    size_t oi = (((size_t)segc * H_ + hh) * rps + tc) * 64 + dd;
                    *(uint32_t*)(Cp + oi) =
                        packh(acc[mt][nt][hrow * 2], acc[mt][nt][hrow * 2 + 1]);
                }
            } else {
#pragma unroll
                for (int nt = 0; nt < 8; nt++) {
                    const int cn = bn + Wn + nt * 8 + ec;
                    size_t oi = (size_t)cm * DM_ + cn;
                    *(uint32_t*)(Cp + oi) =
                        packh(acc[mt][nt][hrow * 2] * 0.125f,
                              acc[mt][nt][hrow * 2 + 1] * 0.125f);
                }
            }
        }
    }
}

// ---------------------------------------------------------------------------
// Wout GEMM: fp32 C + bias (depends on attention output)
// ---------------------------------------------------------------------------
__global__ void __launch_bounds__(256, 2)
gemm_out(const __half* __restrict__ Ahi, const __half* __restrict__ Bhi,
         float* __restrict__ C, const float* __restrict__ bias)
{
    extern __shared__ __align__(128) char smem[];
    const uint32_t sb = smem_to_u32(smem);
    const int tid = threadIdx.x;
    const int bn = blockIdx.x * 128;
    const int bm = blockIdx.y * 128;
    const int wid = tid >> 5, lane = tid & 31;
    const int Wm = (wid & 3) * 32;
    const int Wn = (wid >> 2) * 64;

    const int lrow = tid >> 1;
    const int lc = tid & 1;
    const size_t aoff = (size_t)(bm + lrow) * 1024 + lc * 16;
    const size_t boff = (size_t)(bn + lrow) * 1024 + lc * 16;
    const uint32_t soff = (uint32_t)lrow * 80u + (uint32_t)lc * 32u;

    GEMM_BODY(Ahi, Bhi)

    const int er = lane >> 2, ec = (lane & 3) * 2;
#pragma unroll
    for (int mt = 0; mt < 2; mt++) {
#pragma unroll
        for (int hrow = 0; hrow < 2; hrow++) {
            const int cm = bm + Wm + mt * 16 + er + hrow * 8;
            float* Cp = C + (size_t)cm * DM_ + bn + Wn + ec;
            const float* bp = bias + bn + Wn + ec;
#pragma unroll
            for (int nt = 0; nt < 8; nt++) {
                float2 v = make_float2(acc[mt][nt][hrow * 2] + bp[nt * 8],
                                       acc[mt][nt][hrow * 2 + 1] + bp[nt * 8 + 1]);
                *(float2*)(Cp + nt * 8) = v;
            }
        }
    }
}

// ---------------------------------------------------------------------------
// Persistent tensor-core flash attention: one CTA per (b,h), 8 query tiles.
// QK/WV 1-term, image-first merged acc (64-key online-softmax chunks),
// fp16 output. 2 CTAs/SM.
// ---------------------------------------------------------------------------
#define AT_KHI 0
#define AT_VHI 48384
#define AT_QS  96768
#define AT_RKH 96768
#define AT_RKL 102528
#define AT_PS  96768
#define AT_SMEM 113664

__device__ __forceinline__ int bidx(int j, int i)
{
    int d = j - i;
    d = max(-16, min(16, d));
    return d + 16;
}

__global__ void __launch_bounds__(256, 2)
attn_mma(const __half* __restrict__ qhi,
         const __half* __restrict__ kt, const __half* __restrict__ vt,
         const __half* __restrict__ ki, const __half* __restrict__ vi,
         const float* __restrict__ relk, const float* __restrict__ relv,
         __half* __restrict__ atthi)
{
    extern __shared__ __align__(128) char sm[];
    const uint32_t sb = smem_to_u32(sm);
    const int tid = threadIdx.x, w = tid >> 5, lane = tid & 31;
    const int bh = blockIdx.x;
    const int b = bh >> 4, h = bh & 15;
    const unsigned FULL = 0xffffffffu;

    // ---- stage K/V once (144B rows) ----
    {
        size_t tb = (size_t)bh * (LT_ * 64);
        for (int idx = tid; idx < LT_ * 8; idx += 256) {
            int r = idx >> 3, c = idx & 7;
            uint32_t d = (uint32_t)r * 144 + c * 16;
            size_t s = tb + (size_t)r * 64 + c * 8;
            CPA16(sb + AT_KHI + d, kt + s);
            CPA16(sb + AT_VHI + d, vt + s);
        }
        size_t ib = (size_t)bh * (LI_ * 64);
        for (int idx = tid; idx < LI_ * 8; idx += 256) {
            int r = idx >> 3, c = idx & 7;
            uint32_t d = (uint32_t)(80 + r) * 144 + c * 16;
            size_t s = ib + (size_t)r * 64 + c * 8;
            CPA16(sb + AT_KHI + d, ki + s);
            CPA16(sb + AT_VHI + d, vi + s);
        }
        for (int idx = tid; idx < 3 * 36; idx += 256) {
            uint32_t d = (uint32_t)(77 + idx / 36) * 144 + (idx % 36) * 4;
            *(uint32_t*)(sm + AT_KHI + d) = 0;
            *(uint32_t*)(sm + AT_VHI + d) = 0;
        }
        CPA_COMMIT();
    }

    const int wr = w * 16;
    const int r0l = wr + (lane >> 2);
    const int brow = ((lane >> 4) << 3) + (lane & 7);
    const int bdb = (lane & 8) * 2;
    const int vrow = (lane & 8) + (lane & 7);
    const int vdb = (lane >> 4) * 16;

    float* pS = (float*)(sm + AT_PS);

#pragma unroll 1
    for (int qt = 0; qt < 8; qt++) {
        const int i0 = qt * 128;

        __syncthreads();

        // ---- stage Q tile (128B rows) ----
        {
            size_t qb = ((size_t)(b * NQ_ + i0)) * 1024 + h * 64;
            for (int idx = tid; idx < 128 * 8; idx += 256) {
                int r = idx >> 3, c = idx & 7;
                uint32_t d = (uint32_t)r * 128 + c * 16;
                size_t s = qb + (size_t)r * 1024 + c * 8;
                CPA16(sb + AT_QS + d, qhi + s);
            }
            CPA_COMMIT();
            CPA_WAIT(0);
            __syncthreads();
        }

        // ---- Q fragments ----
        uint32_t qh[4][4];
        {
            int row = wr + (lane & 15);
            int kb = (lane >> 4) * 16;
#pragma unroll
            for (int kk = 0; kk < 4; kk++) {
                uint32_t a = sb + AT_QS + (uint32_t)row * 128 + kk * 32 + kb;
                LDMX4(qh[kk][0], qh[kk][1], qh[kk][2], qh[kk][3], a);
            }
        }
        __syncthreads();

        // ---- stage relk hi/lo into overlay (tile 0 only) ----
        if (qt == 0) {
            for (int idx = tid; idx < NR_ * 64; idx += 256) {
                int r = idx >> 6, dc = idx & 63;
                float v = relk[idx];
                float hh = __half2float(__float2half(v));
                *(__half*)(sm + AT_RKH + r * 144 + dc * 2) = __float2half(hh);
                *(__half*)(sm + AT_RKL + r * 144 + dc * 2) = __float2half(v - hh);
            }
        }

        // ===== image branch first, 64-key chunks (merged accumulator) =====
        float o[8][4];
#pragma unroll
        for (int i = 0; i < 8; i++)
#pragma unroll
            for (int c = 0; c < 4; c++) o[i][c] = 0.f;
        float mi0 = -1e30f, mi1 = -1e30f, li0 = 0.f, li1 = 0.f;
#pragma unroll 1
        for (int ch = 0; ch < 4; ch++) {
            const int j0 = 80 + ch * 64;
            float sc[8][4];
#pragma unroll
            for (int i = 0; i < 8; i++)
#pragma unroll
                for (int c = 0; c < 4; c++) sc[i][c] = 0.f;
#pragma unroll
            for (int kk = 0; kk < 4; kk++) {
#pragma unroll
                for (int p2 = 0; p2 < 4; p2++) {
                    uint32_t kh4[4];
                    uint32_t ad = sb + AT_KHI + (uint32_t)(j0 + p2 * 16 + brow) * 144
                                  + kk * 32 + bdb;
                    LDMX4(kh4[0], kh4[1], kh4[2], kh4[3], ad);
                    MMA16816(sc[2 * p2], qh[kk], kh4[0], kh4[1]);
                    MMA16816(sc[2 * p2 + 1], qh[kk], kh4[2], kh4[3]);
                }
            }
            float cm0 = -1e30f, cm1 = -1e30f;
#pragma unroll
            for (int t = 0; t < 8; t++) {
                cm0 = fmaxf(cm0, fmaxf(sc[t][0], sc[t][1]));
                cm1 = fmaxf(cm1, fmaxf(sc[t][2], sc[t][3]));
            }
            cm0 = fmaxf(cm0, __shfl_xor_sync(FULL, cm0, 1));
            cm0 = fmaxf(cm0, __shfl_xor_sync(FULL, cm0, 2));
            cm1 = fmaxf(cm1, __shfl_xor_sync(FULL, cm1, 1));
            cm1 = fmaxf(cm1, __shfl_xor_sync(FULL, cm1, 2));
            float mn0 = fmaxf(mi0, cm0), mn1 = fmaxf(mi1, cm1);
            float al0 = __expf(mi0 - mn0), al1 = __expf(mi1 - mn1);
            float cs0 = 0.f, cs1 = 0.f;
#pragma unroll
            for (int t = 0; t < 8; t++) {
                sc[t][0] = __expf(sc[t][0] - mn0); cs0 += sc[t][0];
                sc[t][1] = __expf(sc[t][1] - mn0); cs0 += sc[t][1];
                sc[t][2] = __expf(sc[t][2] - mn1); cs1 += sc[t][2];
                sc[t][3] = __expf(sc[t][3] - mn1); cs1 += sc[t][3];
            }
            cs0 += __shfl_xor_sync(FULL, cs0, 1); cs0 += __shfl_xor_sync(FULL, cs0, 2);
            cs1 += __shfl_xor_sync(FULL, cs1, 1); cs1 += __shfl_xor_sync(FULL, cs1, 2);
            li0 = li0 * al0 + cs0; li1 = li1 * al1 + cs1;
            mi0 = mn0; mi1 = mn1;
#pragma unroll
            for (int dt = 0; dt < 8; dt++) {
                o[dt][0] *= al0; o[dt][1] *= al0;
                o[dt][2] *= al1; o[dt][3] *= al1;
            }
#pragma unroll
            for (int wk = 0; wk < 4; wk++) {
                uint32_t ahi[4];
                const float* s0 = sc[2 * wk];
                const float* s1 = sc[2 * wk + 1];
                ahi[0] = packh(s0[0], s0[1]); ahi[1] = packh(s0[2], s0[3]);
                ahi[2] = packh(s1[0], s1[1]); ahi[3] = packh(s1[2], s1[3]);
#pragma unroll
                for (int dp = 0; dp < 4; dp++) {
                    uint32_t vh4[4];
                    uint32_t ad = sb + AT_VHI + (uint32_t)(j0 + wk * 16 + vrow) * 144
                                  + dp * 32 + vdb;
                    LDMX4T(vh4[0], vh4[1], vh4[2], vh4[3], ad);
                    MMA16816(o[2 * dp], ahi, vh4[0], vh4[1]);
                    MMA16816(o[2 * dp + 1], ahi, vh4[2], vh4[3]);
                }
            }
        }
        {
            float ii0 = 1.f / li0, ii1 = 1.f / li1;
#pragma unroll
            for (int dt = 0; dt < 8; dt++) {
                o[dt][0] *= ii0; o[dt][1] *= ii0;
                o[dt][2] *= ii1; o[dt][3] *= ii1;
            }
        }

        __syncthreads();   // relk staging visible (tile 0); uniform barrier

        // ---- rel-K projections (tile 0) ----
        if (qt == 0) {
            float pr[5][4];
#pragma unroll
            for (int i = 0; i < 5; i++)
#pragma unroll
                for (int c = 0; c < 4; c++) pr[i][c] = 0.f;
#pragma unroll
            for (int kk = 0; kk < 4; kk++) {
#pragma unroll
                for (int p2 = 0; p2 < 3; p2++) {
                    uint32_t bh4[4], bl4[4];
                    uint32_t ad = sb + AT_RKH + (uint32_t)(p2 * 16 + brow) * 144
                                  + kk * 32 + bdb;
                    LDMX4(bh4[0], bh4[1], bh4[2], bh4[3], ad);
                    LDMX4(bl4[0], bl4[1], bl4[2], bl4[3], ad + (AT_RKL - AT_RKH));
                    MMA16816(pr[2 * p2], qh[kk], bh4[0], bh4[1]);
                    MMA16816(pr[2 * p2], qh[kk], bl4[0], bl4[1]);
                    if (p2 < 2) {
                        MMA16816(pr[2 * p2 + 1], qh[kk], bh4[2], bh4[3]);
                        MMA16816(pr[2 * p2 + 1], qh[kk], bl4[2], bl4[3]);
                    }
                }
            }
            __syncthreads();   // all warps done reading relk; pS overlays it
#pragma unroll
            for (int nt = 0; nt < 5; nt++) {
                int c0 = nt * 8 + 2 * (lane & 3);
                if (c0 < NR_) {
                    pS[r0l * 33 + c0] = pr[nt][0];
                    pS[(r0l + 8) * 33 + c0] = pr[nt][2];
                }
                if (c0 + 1 < NR_) {
                    pS[r0l * 33 + c0 + 1] = pr[nt][1];
                    pS[(r0l + 8) * 33 + c0 + 1] = pr[nt][3];
                }
            }
            __syncwarp();
        }

        // ---- text scores (1-term) ----
        float s[10][4];
#pragma unroll
        for (int i = 0; i < 10; i++)
#pragma unroll
            for (int c = 0; c < 4; c++) s[i][c] = 0.f;
#pragma unroll
        for (int kk = 0; kk < 4; kk++) {
#pragma unroll
            for (int p2 = 0; p2 < 5; p2++) {
                uint32_t kh4[4];
                uint32_t ad = sb + AT_KHI + (uint32_t)(p2 * 16 + brow) * 144
                              + kk * 32 + bdb;
                LDMX4(kh4[0], kh4[1], kh4[2], kh4[3], ad);
                MMA16816(s[2 * p2], qh[kk], kh4[0], kh4[1]);
                MMA16816(s[2 * p2 + 1], qh[kk], kh4[2], kh4[3]);
            }
        }

#pragma unroll
        for (int nt = 0; nt < 10; nt++) {
            int c0 = nt * 8 + 2 * (lane & 3);
            if (qt == 0) {
                s[nt][0] += pS[r0l * 33 + bidx(c0, r0l)];
                s[nt][1] += pS[r0l * 33 + bidx(c0 + 1, r0l)];
                s[nt][2] += pS[(r0l + 8) * 33 + bidx(c0, r0l + 8)];
                s[nt][3] += pS[(r0l + 8) * 33 + bidx(c0 + 1, r0l + 8)];
            }
            if (c0 >= LT_) { s[nt][0] = -1e30f; s[nt][2] = -1e30f; }
            if (c0 + 1 >= LT_) { s[nt][1] = -1e30f; s[nt][3] = -1e30f; }
        }

        float m0 = -1e30f, m1 = -1e30f;
#pragma unroll
        for (int nt = 0; nt < 10; nt++) {
            m0 = fmaxf(m0, fmaxf(s[nt][0], s[nt][1]));
            m1 = fmaxf(m1, fmaxf(s[nt][2], s[nt][3]));
        }
        m0 = fmaxf(m0, __shfl_xor_sync(FULL, m0, 1));
        m0 = fmaxf(m0, __shfl_xor_sync(FULL, m0, 2));
        m1 = fmaxf(m1, __shfl_xor_sync(FULL, m1, 1));
        m1 = fmaxf(m1, __shfl_xor_sync(FULL, m1, 2));
        float l0 = 0.f, l1 = 0.f;
#pragma unroll
        for (int nt = 0; nt < 10; nt++) {
            s[nt][0] = __expf(s[nt][0] - m0); l0 += s[nt][0];
            s[nt][1] = __expf(s[nt][1] - m0); l0 += s[nt][1];
            s[nt][2] = __expf(s[nt][2] - m1); l1 += s[nt][2];
            s[nt][3] = __expf(s[nt][3] - m1); l1 += s[nt][3];
        }
        l0 += __shfl_xor_sync(FULL, l0, 1); l0 += __shfl_xor_sync(FULL, l0, 2);
        l1 += __shfl_xor_sync(FULL, l1, 1); l1 += __shfl_xor_sync(FULL, l1, 2);
        float inv0 = 1.f / l0, inv1 = 1.f / l1;
#pragma unroll
        for (int nt = 0; nt < 10; nt++) {
            s[nt][0] *= inv0; s[nt][1] *= inv0;
            s[nt][2] *= inv1; s[nt][3] *= inv1;
        }

        if (qt == 0) {
            for (int idx = lane; idx < 16 * 33; idx += 32)
                pS[(wr + idx / 33) * 33 + idx % 33] = 0.f;
            __syncwarp();
#pragma unroll
            for (int nt = 0; nt < 10; nt++) {
                int c0 = nt * 8 + 2 * (lane & 3);
                if (c0 < LT_) {
                    atomicAdd(&pS[r0l * 33 + bidx(c0, r0l)], s[nt][0]);
                    atomicAdd(&pS[(r0l + 8) * 33 + bidx(c0, r0l + 8)], s[nt][2]);
                }
                if (c0 + 1 < LT_) {
                    atomicAdd(&pS[r0l * 33 + bidx(c0 + 1, r0l)], s[nt][1]);
                    atomicAdd(&pS[(r0l + 8) * 33 + bidx(c0 + 1, r0l + 8)], s[nt][3]);
                }
            }
            __syncwarp();
        }

        // ---- O += W @ V_text (1-term, fp16 weights) ----
#pragma unroll
        for (int wk = 0; wk < 5; wk++) {
            uint32_t ahi[4];
            const float* s0 = s[2 * wk];
            const float* s1 = s[2 * wk + 1];
            ahi[0] = packh(s0[0], s0[1]); ahi[1] = packh(s0[2], s0[3]);
            ahi[2] = packh(s1[0], s1[1]); ahi[3] = packh(s1[2], s1[3]);
#pragma unroll
            for (int dp = 0; dp < 4; dp++) {
                uint32_t vh4[4];
                uint32_t ad = sb + AT_VHI + (uint32_t)(wk * 16 + vrow) * 144
                              + dp * 32 + vdb;
                LDMX4T(vh4[0], vh4[1], vh4[2], vh4[3], ad);
                MMA16816(o[2 * dp], ahi, vh4[0], vh4[1]);
                MMA16816(o[2 * dp + 1], ahi, vh4[2], vh4[3]);
            }
        }

        // ---- rel-V contribution ----
        if (qt == 0) {
#pragma unroll 1
            for (int r = 0; r < NR_; r++) {
                float w0 = pS[r0l * 33 + r];
                float w1 = pS[(r0l + 8) * 33 + r];
                const float* rv = relv + r * 64 + 2 * (lane & 3);
#pragma unroll
                for (int dt = 0; dt < 8; dt++) {
                    float rv0 = rv[dt * 8], rv1 = rv[dt * 8 + 1];
                    o[dt][0] += w0 * rv0; o[dt][1] += w0 * rv1;
                    o[dt][2] += w1 * rv0; o[dt][3] += w1 * rv1;
                }
            }
        } else {
            const float* rv = relv + 2 * (lane & 3);
#pragma unroll
            for (int dt = 0; dt < 8; dt++) {
                float rv0 = rv[dt * 8], rv1 = rv[dt * 8 + 1];
                o[dt][0] += rv0; o[dt][1] += rv1;
                o[dt][2] += rv0; o[dt][3] += rv1;
            }
        }

        // ---- store fp16 ----
        {
            size_t ob = ((size_t)(b * NQ_ + i0 + r0l)) * 1024 + h * 64
                        + 2 * (lane & 3);
#pragma unroll
            for (int dt = 0; dt < 8; dt++) {
                size_t o0 = ob + dt * 8;
                size_t o1 = o0 + 8 * 1024;
                *(uint32_t*)(atthi + o0) = packh(o[dt][0], o[dt][1]);
                *(uint32_t*)(atthi + o1) = packh(o[dt][2], o[dt][3]);
            }
        }
    }
}

// ---------------------------------------------------------------------------
// Host launcher (5 launches total)
// ---------------------------------------------------------------------------
extern "C" void kernel_launch(void* const* d_in, const int* in_sizes, int n_in,
                              void* d_out, int out_size)
{
    const float* x     = (const float*)d_in[0];
    const float* ctx   = (const float*)d_in[1];
    const float* Wq    = (const float*)d_in[2];
    const float* Wk    = (const float*)d_in[3];
    const float* Wv    = (const float*)d_in[4];
    const float* Wk_ip = (const float*)d_in[5];
    const float* Wv_ip = (const float*)d_in[6];
    const float* Wout  = (const float*)d_in[7];
    const float* bout  = (const float*)d_in[8];
    const float* relk  = (const float*)d_in[9];
    const float* relv  = (const float*)d_in[10];
    float* out = (float*)d_out;

    __half *pahi, *pqhi, *pchi, *pwhi;
    __half *pkt, *pvt, *pki, *pvi;
    cudaGetSymbolAddress((void**)&pahi, g_ahi);
    cudaGetSymbolAddress((void**)&pqhi, g_qhi);
    cudaGetSymbolAddress((void**)&pchi, g_chi);
    cudaGetSymbolAddress((void**)&pwhi, g_whi);
    cudaGetSymbolAddress((void**)&pkt, g_kt);
    cudaGetSymbolAddress((void**)&pvt, g_vt);
    cudaGetSymbolAddress((void**)&pki, g_ki);
    cudaGetSymbolAddress((void**)&pvi, g_vi);

    cudaFuncSetAttribute(gemm_fused,
                         cudaFuncAttributeMaxDynamicSharedMemorySize, GM_SMEM);
    cudaFuncSetAttribute(gemm_out,
                         cudaFuncAttributeMaxDynamicSharedMemorySize, GM_SMEM);
    cudaFuncSetAttribute(attn_mma,
                         cudaFuncAttributeMaxDynamicSharedMemorySize, AT_SMEM);

    const size_t WSZ = (size_t)DM_ * DM_;
    size_t nx = (size_t)B_ * NQ_ * DM_;
    size_t nc = (size_t)B_ * CTXR * DM_;

    // 1) all weight transposes (6-in-1)
    conv_wt6<<<dim3(32, 32, 6), dim3(32, 8)>>>(Wq, Wk, Wv, Wk_ip, Wv_ip, Wout, pwhi);

    // 2) x + ctx fp32->fp16 (fused)
    conv_rows2<<<(unsigned)(((nx + nc) / 4 + 255) / 256), 256>>>(
        x, ctx, pahi, pchi, nx, nx + nc);

    // 3) Q + all KV projections in one launch
    gemm_fused<<<6768, 256, GM_SMEM>>>(
        pahi, pchi, pwhi, pqhi, pkt, pvt, pki, pvi);

    // 4) persistent tensor-core attention (one CTA per (b,h))
    attn_mma<<<B_ * H_, 256, AT_SMEM>>>(
        pqhi, pkt, pvt, pki, pvi, relk, relv, pahi);

    // 5) final projection + bias
    gemm_out<<<dim3(8, 512), 256, GM_SMEM>>>(
        pahi, pwhi + 5 * WSZ, out, bout);
}